// round 10
// baseline (speedup 1.0000x reference)
#include <cuda_runtime.h>
#include <cuda_bf16.h>
#include <math.h>
#include <cstdint>

// ---- problem constants ----
#define NND 8192
#define NF  512
#define NH  64
#define NRel 16
#define NBase 30
#define NE  524288
#define NBc 64
#define NL  128
#define NDm 576
#define NC  7
#define KC  64          // K chunk (bf16) per pipeline stage; 128B rows

typedef __nv_bfloat16 bf16;
typedef unsigned int u32;

// ---- static device scratch ----
__device__ __align__(16) bf16 g_WtTh[1024 * 512];
__device__ __align__(16) bf16 g_WtTl[1024 * 512];
__device__ __align__(16) bf16 g_rootTh[64 * 512];
__device__ __align__(16) bf16 g_rootTl[64 * 512];
__device__ __align__(16) bf16 g_wcatTh[64 * 128];   // [n][k]: k<64 w_root, k>=64 w_nbr
__device__ __align__(16) bf16 g_wcatTl[64 * 128];
__device__ __align__(16) bf16 g_WqTh[640 * 576];    // rows 0..575 WmT, 576..639 WlT
__device__ __align__(16) bf16 g_WqTl[640 * 576];
__device__ __align__(16) bf16 g_emoh[(size_t)NND * NDm];
__device__ __align__(16) bf16 g_emol[(size_t)NND * NDm];
__device__ __align__(16) bf16 g_a2h[NND * 128];     // cols [0,64)=h1, [64,128)=agg(h1)
__device__ __align__(16) bf16 g_a2l[NND * 128];
__device__ __align__(16) u32  g_h1p[NND * NH];      // packed (hi,lo) bf16x2 of h1
__device__ __align__(16) bf16 g_Qh[(size_t)NND * NDm];
__device__ __align__(16) bf16 g_Ql[(size_t)NND * NDm];
__device__ __align__(16) bf16 g_Sh[NND * NL];
__device__ __align__(16) bf16 g_Sl[NND * NL];
__device__ __align__(16) bf16 g_eWTh[NBc * NH * NL];  // [b][n][q]
__device__ __align__(16) bf16 g_eWTl[NBc * NH * NL];

__device__ __align__(16) float g_xw[(size_t)NND * NRel * NH];
__device__ __align__(16) float g_agg[NND * NH];
__device__ __align__(16) float g_hid[NND * NH];
// CSR
__device__ int g_cnt[NND];
__device__ int g_off[NND + 1];
__device__ int g_cur[NND];
__device__ int g_eidx[NE];

__device__ __forceinline__ void split_pair(float v, bf16& h, bf16& l) {
    h = __float2bfloat16(v);
    l = __float2bfloat16(v - __bfloat162float(h));
}

__device__ __forceinline__ u32 smem_u32(const void* p) {
    u32 a;
    asm("{ .reg .u64 t; cvta.to.shared.u64 t, %1; cvt.u32.u64 %0, t; }"
        : "=r"(a) : "l"(p));
    return a;
}

__device__ __forceinline__ void mma16816(float* d, const u32* a, const u32* b) {
    asm volatile(
        "mma.sync.aligned.m16n8k16.row.col.f32.bf16.bf16.f32 "
        "{%0,%1,%2,%3}, {%4,%5,%6,%7}, {%8,%9}, {%0,%1,%2,%3};"
        : "+f"(d[0]), "+f"(d[1]), "+f"(d[2]), "+f"(d[3])
        : "r"(a[0]), "r"(a[1]), "r"(a[2]), "r"(a[3]), "r"(b[0]), "r"(b[1]));
}

#define LDSM4(r, addr) \
    asm volatile("ldmatrix.sync.aligned.m8n8.x4.shared.b16 {%0,%1,%2,%3}, [%4];" \
        : "=r"((r)[0]), "=r"((r)[1]), "=r"((r)[2]), "=r"((r)[3]) : "r"(addr))

#define CPA(d, s) \
    asm volatile("cp.async.cg.shared.global [%0], [%1], 16;" :: "r"(d), "l"(s) : "memory")
#define CPC() asm volatile("cp.async.commit_group;" ::: "memory")
#define CPW0() asm volatile("cp.async.wait_group 0;" ::: "memory")

// ============================================================
// Pipelined warp-MMA 3xBF16 GEMM: C[M,N] = A @ B^T
// OMODE: 0 = fp32 C ; 1 = bf16 pairs (Ch,Cl,ldc) + optional packed Cp(ldp)
//        3 = MIX: n0<576 -> Q pairs (+bias), n0>=576 -> eWT transposed pairs
// ============================================================
template <int BM, int NT, int THREADS,
          bool ADD_D, bool BIAS, bool RELU, int OMODE>
__global__ void __launch_bounds__(THREADS, 2)
mmt(const bf16* __restrict__ Ah, const bf16* __restrict__ Al, int lda, long long sA,
    const bf16* __restrict__ Bh, const bf16* __restrict__ Bl, int ldb, long long sB,
    float* __restrict__ C, bf16* __restrict__ Ch, bf16* __restrict__ Cl,
    u32* __restrict__ Cp, bf16* __restrict__ Th, bf16* __restrict__ Tl,
    int ldc, int ldp, long long sC,
    const float* __restrict__ D, int ldd,
    const float* __restrict__ bias,
    int K)
{
    constexpr int WARPS = THREADS / 32;
    constexpr int WN = NT / 64;
    constexpr int WMC = WARPS / WN;
    constexpr int WM = BM / WMC;
    constexpr int MI = WM / 16;
    constexpr int STAGE_ROWS = 2 * (BM + NT);
    constexpr int STAGE_B = STAGE_ROWS * 128;
    constexpr int CHUNKS = STAGE_ROWS * 8 / THREADS;

    extern __shared__ char smem[];
    const u32 sb0 = smem_u32(smem) + 512;

    const int tid = threadIdx.x;
    const int wid = tid >> 5, lane = tid & 31;
    const int warpM = wid % WMC, warpN = wid / WMC;
    const int bz = blockIdx.z;
    const int m0 = blockIdx.y * BM;
    const int n0 = blockIdx.x * NT;

    const char* pAh = (const char*)(Ah + sA * bz + (size_t)m0 * lda);
    const char* pAl = (const char*)(Al + sA * bz + (size_t)m0 * lda);
    const char* pBh = (const char*)(Bh + sB * bz + (size_t)n0 * ldb);
    const char* pBl = (const char*)(Bl + sB * bz + (size_t)n0 * ldb);
    const size_t ldab = (size_t)lda * 2;
    const size_t ldbb = (size_t)ldb * 2;

    float acc[MI][8][4];
#pragma unroll
    for (int i = 0; i < MI; i++)
#pragma unroll
        for (int j = 0; j < 8; j++)
#pragma unroll
            for (int q = 0; q < 4; q++) acc[i][j][q] = 0.f;

    const int S = K / KC;

    auto load_stage = [&](int s) {
        const size_t kcb = (size_t)s * KC * 2;
        const u32 dst0 = sb0 + (u32)(s & 1) * STAGE_B;
#pragma unroll
        for (int f = 0; f < CHUNKS; f++) {
            int idx = tid + f * THREADS;
            int row = idx >> 3;
            u32 cb = (u32)(idx & 7) << 4;
            u32 sw = cb ^ (((u32)(row & 7)) << 4);
            const char* src;
            if (row < BM)               src = pAh + (size_t)row * ldab + kcb + cb;
            else if (row < 2 * BM)      src = pAl + (size_t)(row - BM) * ldab + kcb + cb;
            else if (row < 2 * BM + NT) src = pBh + (size_t)(row - 2 * BM) * ldbb + kcb + cb;
            else                        src = pBl + (size_t)(row - 2 * BM - NT) * ldbb + kcb + cb;
            CPA(dst0 + (u32)row * 128 + sw, src);
        }
    };

    load_stage(0);
    CPC();

    const u32 xorv = ((u32)(lane & 7)) << 4;
    const u32 aRow = (u32)(warpM * WM + (lane & 15));
    const u32 aCol0 = ((u32)(lane >> 4) & 1) * 16;
    const u32 bRow = (u32)(warpN * 64 + ((lane & 7) | ((lane & 16) >> 1)));
    const u32 bCol0 = ((u32)(lane >> 3) & 1) * 16;

    for (int s = 0; s < S; s++) {
        CPW0();
        __syncthreads();
        if (s + 1 < S) { load_stage(s + 1); CPC(); }

        const u32 base = sb0 + (u32)(s & 1) * STAGE_B;
        const u32 aH = base + aRow * 128;
        const u32 aL = aH + (u32)BM * 128;
        const u32 bH = base + (u32)(2 * BM) * 128 + bRow * 128;
        const u32 bL = bH + (u32)NT * 128;

#pragma unroll
        for (int ks = 0; ks < KC / 16; ks++) {
            const u32 kb = (u32)ks * 32;
            const u32 acol = (aCol0 + kb) ^ xorv;
            const u32 bcol = (bCol0 + kb) ^ xorv;
            u32 ah[MI][4], al[MI][4];
#pragma unroll
            for (int mi = 0; mi < MI; mi++) {
                LDSM4(ah[mi], aH + (u32)mi * (16 * 128) + acol);
                LDSM4(al[mi], aL + (u32)mi * (16 * 128) + acol);
            }
#pragma unroll
            for (int nt = 0; nt < 4; nt++) {
                u32 bh[4], bl[4];
                LDSM4(bh, bH + (u32)nt * (16 * 128) + bcol);
                LDSM4(bl, bL + (u32)nt * (16 * 128) + bcol);
#pragma unroll
                for (int mi = 0; mi < MI; mi++)
#pragma unroll
                    for (int half = 0; half < 2; half++) {
                        float* a4 = acc[mi][nt * 2 + half];
                        mma16816(a4, ah[mi], &bh[half * 2]);
                        mma16816(a4, ah[mi], &bl[half * 2]);
                        mma16816(a4, al[mi], &bh[half * 2]);
                    }
            }
        }
    }

    // ---- epilogue ----
    const bool mixT = (OMODE == 3) && (n0 >= 576);
#pragma unroll
    for (int mi = 0; mi < MI; mi++) {
        const int rm = m0 + warpM * WM + mi * 16 + (lane >> 2);
#pragma unroll
        for (int ni = 0; ni < 8; ni++) {
            const int n = n0 + warpN * 64 + ni * 8 + (lane & 3) * 2;
#pragma unroll
            for (int half = 0; half < 2; half++) {
                const int m = rm + half * 8;
                float v0 = acc[mi][ni][half * 2];
                float v1 = acc[mi][ni][half * 2 + 1];
                if (BIAS && !mixT) { v0 += bias[n]; v1 += bias[n + 1]; }
                if (ADD_D) {
                    v0 += D[(size_t)m * ldd + n];
                    v1 += D[(size_t)m * ldd + n + 1];
                }
                if (RELU) { v0 = fmaxf(v0, 0.f); v1 = fmaxf(v1, 0.f); }
                if (OMODE == 0) {
                    float2 f2; f2.x = v0; f2.y = v1;
                    *(float2*)&C[(size_t)sC * bz + (size_t)m * ldc + n] = f2;
                } else {
                    bf16 h0, l0, h1c, l1c;
                    split_pair(v0, h0, l0);
                    split_pair(v1, h1c, l1c);
                    if (mixT) {
                        // eWT[b][n-576][q]: b=m>>7, q=m&127
                        size_t o = ((size_t)(m >> 7) * 64 + (n - 576)) * 128 + (m & 127);
                        Th[o] = h0; Th[o + 128] = h1c;
                        Tl[o] = l0; Tl[o + 128] = l1c;
                    } else {
                        const size_t o = (size_t)sC * bz + (size_t)m * ldc + n;
                        *(__nv_bfloat162*)&Ch[o] = __nv_bfloat162(h0, h1c);
                        *(__nv_bfloat162*)&Cl[o] = __nv_bfloat162(l0, l1c);
                        if (OMODE == 1 && Cp) {
                            __nv_bfloat162 p0(h0, l0), p1(h1c, l1c);
                            uint2 u; u.x = *(u32*)&p0; u.y = *(u32*)&p1;
                            *(uint2*)&Cp[(size_t)m * ldp + n] = u;
                        }
                    }
                }
            }
        }
    }
}

// ============================================================
// Fused scores kernel: S = tanh((Q.M)*u^2) -> softmax -> *u -> renorm
// ============================================================
__global__ void __launch_bounds__(128, 2)
scores_softmax(const bf16* __restrict__ Qh, const bf16* __restrict__ Ql,
               const bf16* __restrict__ Mh, const bf16* __restrict__ Ml,
               const float* __restrict__ um,
               bf16* __restrict__ Sh, bf16* __restrict__ Sl)
{
    constexpr int BM = 64, NT = 128, THREADS = 128;
    constexpr int STAGE_ROWS = 2 * (BM + NT);
    constexpr int STAGE_B = STAGE_ROWS * 128;
    constexpr int CHUNKS = STAGE_ROWS * 8 / THREADS;

    extern __shared__ char smem[];
    float* ums = (float*)smem;
    float* sbuf = (float*)(smem + 512);
    const u32 sb0 = smem_u32(smem) + 512;

    const int tid = threadIdx.x;
    const int wid = tid >> 5, lane = tid & 31;
    const int warpM = wid & 1, warpN = wid >> 1;
    const int bz = blockIdx.z;
    const int m0 = blockIdx.y * BM;

    const char* pAh = (const char*)(Qh + (size_t)bz * NL * NDm + (size_t)m0 * NDm);
    const char* pAl = (const char*)(Ql + (size_t)bz * NL * NDm + (size_t)m0 * NDm);
    const char* pBh = (const char*)(Mh + (size_t)bz * NL * NDm);
    const char* pBl = (const char*)(Ml + (size_t)bz * NL * NDm);
    const size_t ldab = (size_t)NDm * 2;

    if (tid < NT) ums[tid] = um[bz * NL + tid];

    float acc[2][8][4];
#pragma unroll
    for (int i = 0; i < 2; i++)
#pragma unroll
        for (int j = 0; j < 8; j++)
#pragma unroll
            for (int q = 0; q < 4; q++) acc[i][j][q] = 0.f;

    const int S = NDm / KC;

    auto load_stage = [&](int s) {
        const size_t kcb = (size_t)s * KC * 2;
        const u32 dst0 = sb0 + (u32)(s & 1) * STAGE_B;
#pragma unroll
        for (int f = 0; f < CHUNKS; f++) {
            int idx = tid + f * THREADS;
            int row = idx >> 3;
            u32 cb = (u32)(idx & 7) << 4;
            u32 sw = cb ^ (((u32)(row & 7)) << 4);
            const char* src;
            if (row < BM)               src = pAh + (size_t)row * ldab + kcb + cb;
            else if (row < 2 * BM)      src = pAl + (size_t)(row - BM) * ldab + kcb + cb;
            else if (row < 2 * BM + NT) src = pBh + (size_t)(row - 2 * BM) * ldab + kcb + cb;
            else                        src = pBl + (size_t)(row - 2 * BM - NT) * ldab + kcb + cb;
            CPA(dst0 + (u32)row * 128 + sw, src);
        }
    };

    load_stage(0);
    CPC();

    const u32 xorv = ((u32)(lane & 7)) << 4;
    const u32 aRow = (u32)(warpM * 32 + (lane & 15));
    const u32 aCol0 = ((u32)(lane >> 4) & 1) * 16;
    const u32 bRow = (u32)(warpN * 64 + ((lane & 7) | ((lane & 16) >> 1)));
    const u32 bCol0 = ((u32)(lane >> 3) & 1) * 16;

    for (int s = 0; s < S; s++) {
        CPW0();
        __syncthreads();
        if (s + 1 < S) { load_stage(s + 1); CPC(); }

        const u32 base = sb0 + (u32)(s & 1) * STAGE_B;
        const u32 aH = base + aRow * 128;
        const u32 aL = aH + (u32)BM * 128;
        const u32 bH = base + (u32)(2 * BM) * 128 + bRow * 128;
        const u32 bL = bH + (u32)NT * 128;

#pragma unroll
        for (int ks = 0; ks < KC / 16; ks++) {
            const u32 kb = (u32)ks * 32;
            const u32 acol = (aCol0 + kb) ^ xorv;
            const u32 bcol = (bCol0 + kb) ^ xorv;
            u32 ah[2][4], al[2][4];
#pragma unroll
            for (int mi = 0; mi < 2; mi++) {
                LDSM4(ah[mi], aH + (u32)mi * (16 * 128) + acol);
                LDSM4(al[mi], aL + (u32)mi * (16 * 128) + acol);
            }
#pragma unroll
            for (int nt = 0; nt < 4; nt++) {
                u32 bh[4], bl[4];
                LDSM4(bh, bH + (u32)nt * (16 * 128) + bcol);
                LDSM4(bl, bL + (u32)nt * (16 * 128) + bcol);
#pragma unroll
                for (int mi = 0; mi < 2; mi++)
#pragma unroll
                    for (int half = 0; half < 2; half++) {
                        float* a4 = acc[mi][nt * 2 + half];
                        mma16816(a4, ah[mi], &bh[half * 2]);
                        mma16816(a4, ah[mi], &bl[half * 2]);
                        mma16816(a4, al[mi], &bh[half * 2]);
                    }
            }
        }
    }
    __syncthreads();

    // ---- tanh(score*u^2) into smem (stride 132) ----
#pragma unroll
    for (int mi = 0; mi < 2; mi++) {
#pragma unroll
        for (int ni = 0; ni < 8; ni++) {
            const int col = warpN * 64 + ni * 8 + (lane & 3) * 2;
            const float u0 = ums[col], u1 = ums[col + 1];
#pragma unroll
            for (int half = 0; half < 2; half++) {
                const int row = warpM * 32 + mi * 16 + (lane >> 2) + half * 8;
                float v0 = tanhf(acc[mi][ni][half * 2] * u0 * u0);
                float v1 = tanhf(acc[mi][ni][half * 2 + 1] * u1 * u1);
                float2 f2; f2.x = v0; f2.y = v1;
                *(float2*)&sbuf[row * 132 + col] = f2;
            }
        }
    }
    __syncthreads();

    // ---- per-row softmax ----
    for (int r8 = 0; r8 < 16; r8++) {
        const int row = wid * 16 + r8;
        float4 v = *(const float4*)&sbuf[row * 132 + lane * 4];
        float mx = fmaxf(fmaxf(v.x, v.y), fmaxf(v.z, v.w));
#pragma unroll
        for (int o = 16; o > 0; o >>= 1)
            mx = fmaxf(mx, __shfl_xor_sync(0xffffffffu, mx, o));
        float e0 = expf(v.x - mx), e1 = expf(v.y - mx);
        float e2 = expf(v.z - mx), e3 = expf(v.w - mx);
        float sum1 = e0 + e1 + e2 + e3;
#pragma unroll
        for (int o = 16; o > 0; o >>= 1)
            sum1 += __shfl_xor_sync(0xffffffffu, sum1, o);
        const int col = lane * 4;
        float a0 = (e0 / sum1) * ums[col];
        float a1 = (e1 / sum1) * ums[col + 1];
        float a2 = (e2 / sum1) * ums[col + 2];
        float a3 = (e3 / sum1) * ums[col + 3];
        float sum2 = a0 + a1 + a2 + a3;
#pragma unroll
        for (int o = 16; o > 0; o >>= 1)
            sum2 += __shfl_xor_sync(0xffffffffu, sum2, o);
        float inv = 1.f / sum2;
        bf16 h0, l0, h1, l1, h2, l2, h3, l3;
        split_pair(a0 * inv, h0, l0);
        split_pair(a1 * inv, h1, l1);
        split_pair(a2 * inv, h2, l2);
        split_pair(a3 * inv, h3, l3);
        const size_t o0 = (size_t)(bz * NL + m0 + row) * NL + col;
        *(__nv_bfloat162*)&Sh[o0]     = __nv_bfloat162(h0, h1);
        *(__nv_bfloat162*)&Sh[o0 + 2] = __nv_bfloat162(h2, h3);
        *(__nv_bfloat162*)&Sl[o0]     = __nv_bfloat162(l0, l1);
        *(__nv_bfloat162*)&Sl[o0 + 2] = __nv_bfloat162(l2, l3);
    }
}

// ============================================================
// conversion kernels
// ============================================================
__global__ void cvtx_kernel(const float* __restrict__ x,
                            bf16* __restrict__ eh, bf16* __restrict__ el)
{
    int i = blockIdx.x * 256 + threadIdx.x;     // 8192*512
    bf16 h, l; split_pair(x[i], h, l);
    int row = i >> 9, c = i & 511;
    size_t eo = (size_t)row * NDm + c;
    eh[eo] = h; el[eo] = l;
}

// batched transpose+split: root, w_root/w_nbr stacked, [Wm;Wl] stacked
__global__ void tcvt_all_kernel(
    const float* __restrict__ root, bf16* __restrict__ rTh, bf16* __restrict__ rTl,
    const float* __restrict__ wr, const float* __restrict__ wn,
    bf16* __restrict__ wcTh, bf16* __restrict__ wcTl,
    const float* __restrict__ Wm, const float* __restrict__ Wl,
    bf16* __restrict__ WqTh, bf16* __restrict__ WqTl)
{
    int i = blockIdx.x * 256 + threadIdx.x;
    if (i < 32768) {
        int rr = i / 64, cc = i % 64;
        bf16 h, l; split_pair(root[i], h, l);
        rTh[(size_t)cc * 512 + rr] = h; rTl[(size_t)cc * 512 + rr] = l;
    } else if (i < 36864) {
        int j = i - 32768, rr = j / 64, cc = j % 64;
        bf16 h, l; split_pair(wr[j], h, l);
        wcTh[cc * 128 + rr] = h; wcTl[cc * 128 + rr] = l;
    } else if (i < 40960) {
        int j = i - 36864, rr = j / 64, cc = j % 64;
        bf16 h, l; split_pair(wn[j], h, l);
        wcTh[cc * 128 + 64 + rr] = h; wcTl[cc * 128 + 64 + rr] = l;
    } else if (i < 372736) {
        int j = i - 40960, rr = j / 576, cc = j % 576;
        bf16 h, l; split_pair(Wm[j], h, l);
        WqTh[(size_t)cc * 576 + rr] = h; WqTl[(size_t)cc * 576 + rr] = l;
    } else if (i < 409600) {
        int j = i - 372736, rr = j / 64, cc = j % 64;
        bf16 h, l; split_pair(Wl[j], h, l);
        WqTh[(size_t)(576 + cc) * 576 + rr] = h;
        WqTl[(size_t)(576 + cc) * 576 + rr] = l;
    }
}

// Wt: one thread per (k,h), loops relations; basis read exactly once.
__global__ void wt_kernel(const float* __restrict__ comp,
                          const float* __restrict__ basis,
                          bf16* __restrict__ Wh, bf16* __restrict__ Wl)
{
    int i = blockIdx.x * 256 + threadIdx.x;   // 32768
    int k = i >> 6, h = i & 63;
    float acc[NRel];
#pragma unroll
    for (int r = 0; r < NRel; r++) acc[r] = 0.f;
    for (int b = 0; b < NBase; b++) {
        float bv = basis[((size_t)b * NF + k) * NH + h];
#pragma unroll
        for (int r = 0; r < NRel; r++)
            acc[r] = fmaf(comp[r * NBase + b], bv, acc[r]);
    }
#pragma unroll
    for (int r = 0; r < NRel; r++) {
        bf16 hh, ll; split_pair(acc[r], hh, ll);
        size_t o = (size_t)(r * 64 + h) * 512 + k;
        Wh[o] = hh; Wl[o] = ll;
    }
}

// ---- CSR build ----
__global__ void hist_kernel(const int* __restrict__ ei, int* __restrict__ cnt)
{
    int i = blockIdx.x * 256 + threadIdx.x;
    if (i < NE) atomicAdd(&cnt[ei[NE + i]], 1);
}
__global__ void __launch_bounds__(1024)
scan_kernel(const int* __restrict__ cnt, int* __restrict__ off, int* __restrict__ cur)
{
    __shared__ int wsum[32];
    int t = threadIdx.x;
    int c[8], pre[8], p = 0;
#pragma unroll
    for (int j = 0; j < 8; j++) { c[j] = cnt[t * 8 + j]; pre[j] = p; p += c[j]; }
    const int tot = p;
    const int lane = t & 31, w = t >> 5;
    int sc = tot;
#pragma unroll
    for (int o = 1; o < 32; o <<= 1) {
        int v = __shfl_up_sync(0xffffffffu, sc, o);
        if (lane >= o) sc += v;
    }
    if (lane == 31) wsum[w] = sc;
    __syncthreads();
    if (w == 0) {
        int v = wsum[lane];
#pragma unroll
        for (int o = 1; o < 32; o <<= 1) {
            int x = __shfl_up_sync(0xffffffffu, v, o);
            if (lane >= o) v += x;
        }
        wsum[lane] = v;
    }
    __syncthreads();
    const int base = (w ? wsum[w - 1] : 0) + (sc - tot);
#pragma unroll
    for (int j = 0; j < 8; j++) {
        off[t * 8 + j + 1] = base + pre[j] + c[j];
        cur[t * 8 + j] = base + pre[j];
    }
    if (t == 0) off[0] = 0;
}
__global__ void fill_kernel(const int* __restrict__ ei, const int* __restrict__ et,
                            int* __restrict__ cur, int* __restrict__ eidx)
{
    int i = blockIdx.x * 256 + threadIdx.x;
    if (i >= NE) return;
    int dst = ei[NE + i];
    int pos = atomicAdd(&cur[dst], 1);
    eidx[pos] = ei[i] * 16 + et[i];
}

// ---- CSR gathers ----
__global__ void __launch_bounds__(64)
rgcn_gather(const int* __restrict__ off, const int* __restrict__ eidx,
            const float* __restrict__ xw, float* __restrict__ agg)
{
    const int n = blockIdx.x, h = threadIdx.x;
    const int beg = off[n], end = off[n + 1];
    float acc = 0.f;
    int e = beg;
    for (; e + 4 <= end; e += 4) {
        int p0 = eidx[e], p1 = eidx[e + 1], p2 = eidx[e + 2], p3 = eidx[e + 3];
        acc += xw[(size_t)(p0 >> 4) * 1024 + (p0 & 15) * 64 + h]
             + xw[(size_t)(p1 >> 4) * 1024 + (p1 & 15) * 64 + h]
             + xw[(size_t)(p2 >> 4) * 1024 + (p2 & 15) * 64 + h]
             + xw[(size_t)(p3 >> 4) * 1024 + (p3 & 15) * 64 + h];
    }
    for (; e < end; e++) {
        int p = eidx[e];
        acc += xw[(size_t)(p >> 4) * 1024 + (p & 15) * 64 + h];
    }
    agg[n * NH + h] = acc / fmaxf((float)(end - beg), 1.f);
}

// gather sum of h1 (packed pairs) -> a2 pair cols [64,128)
__global__ void __launch_bounds__(64)
gc_gather(const int* __restrict__ off, const int* __restrict__ eidx,
          const u32* __restrict__ h1p, bf16* __restrict__ a2h, bf16* __restrict__ a2l)
{
    const int n = blockIdx.x, h = threadIdx.x;
    const int beg = off[n], end = off[n + 1];
    float acc = 0.f;
    int e = beg;
    for (; e + 4 <= end; e += 4) {
        u32 q0 = h1p[(eidx[e] >> 4) * 64 + h];
        u32 q1 = h1p[(eidx[e + 1] >> 4) * 64 + h];
        u32 q2 = h1p[(eidx[e + 2] >> 4) * 64 + h];
        u32 q3 = h1p[(eidx[e + 3] >> 4) * 64 + h];
        __nv_bfloat162 t0 = *(__nv_bfloat162*)&q0, t1 = *(__nv_bfloat162*)&q1;
        __nv_bfloat162 t2 = *(__nv_bfloat162*)&q2, t3 = *(__nv_bfloat162*)&q3;
        acc += __bfloat162float(t0.x) + __bfloat162float(t0.y)
             + __bfloat162float(t1.x) + __bfloat162float(t1.y)
             + __bfloat162float(t2.x) + __bfloat162float(t2.y)
             + __bfloat162float(t3.x) + __bfloat162float(t3.y);
    }
    for (; e < end; e++) {
        u32 q = h1p[(eidx[e] >> 4) * 64 + h];
        __nv_bfloat162 t = *(__nv_bfloat162*)&q;
        acc += __bfloat162float(t.x) + __bfloat162float(t.y);
    }
    bf16 hh, ll; split_pair(acc, hh, ll);
    a2h[n * 128 + 64 + h] = hh;
    a2l[n * 128 + 64 + h] = ll;
}

// head: logits = hid @ Ws + bs ; log_softmax
__global__ void head_kernel(const float* __restrict__ hid, const float* __restrict__ Ws,
                            const float* __restrict__ bsv, float* __restrict__ out)
{
    int n = blockIdx.x * blockDim.x + threadIdx.x;
    if (n >= NND) return;
    float lg[NC];
#pragma unroll
    for (int c = 0; c < NC; c++) lg[c] = bsv[c];
    const float* h = hid + (size_t)n * NH;
#pragma unroll 8
    for (int k = 0; k < NH; k++) {
        float hv = h[k];
#pragma unroll
        for (int c = 0; c < NC; c++) lg[c] = fmaf(hv, Ws[k * NC + c], lg[c]);
    }
    float mx = lg[0];
#pragma unroll
    for (int c = 1; c < NC; c++) mx = fmaxf(mx, lg[c]);
    float ssum = 0.f;
#pragma unroll
    for (int c = 0; c < NC; c++) ssum += expf(lg[c] - mx);
    float lse = mx + logf(ssum);
#pragma unroll
    for (int c = 0; c < NC; c++) out[(size_t)n * NC + c] = lg[c] - lse;
}

// ============================================================
extern "C" void kernel_launch(void* const* d_in, const int* in_sizes, int n_in,
                              void* d_out, int out_size)
{
    const float* x      = (const float*)d_in[0];
    const int*   ei     = (const int*)d_in[1];
    const int*   et     = (const int*)d_in[3];
    const float* umask  = (const float*)d_in[5];
    const float* basis  = (const float*)d_in[8];
    const float* comp   = (const float*)d_in[9];
    const float* root   = (const float*)d_in[10];
    const float* bias1  = (const float*)d_in[11];
    const float* w_nbr  = (const float*)d_in[12];
    const float* w_root = (const float*)d_in[13];
    const float* bias2  = (const float*)d_in[14];
    const float* Wm     = (const float*)d_in[15];
    const float* bm     = (const float*)d_in[16];
    const float* Wl     = (const float*)d_in[17];
    const float* bl     = (const float*)d_in[18];
    const float* Ws     = (const float*)d_in[19];
    const float* bs     = (const float*)d_in[20];
    float* out = (float*)d_out;

#define SYM(T, v, s) T* v; cudaGetSymbolAddress((void**)&v, s)
    SYM(bf16, WtTh, g_WtTh); SYM(bf16, WtTl, g_WtTl);
    SYM(bf16, rootTh, g_rootTh); SYM(bf16, rootTl, g_rootTl);
    SYM(bf16, wcatTh, g_wcatTh); SYM(bf16, wcatTl, g_wcatTl);
    SYM(bf16, WqTh, g_WqTh); SYM(bf16, WqTl, g_WqTl);
    SYM(bf16, emoh, g_emoh); SYM(bf16, emol, g_emol);
    SYM(bf16, a2h, g_a2h); SYM(bf16, a2l, g_a2l);
    SYM(u32, h1p, g_h1p);
    SYM(bf16, Qh, g_Qh); SYM(bf16, Ql, g_Ql);
    SYM(bf16, Sh, g_Sh); SYM(bf16, Sl, g_Sl);
    SYM(bf16, eWTh, g_eWTh); SYM(bf16, eWTl, g_eWTl);
    SYM(float, xw, g_xw); SYM(float, agg, g_agg); SYM(float, hid, g_hid);
    SYM(int, cnt, g_cnt); SYM(int, off, g_off); SYM(int, cur, g_cur);
    SYM(int, eidx, g_eidx);
#undef SYM

    const int SZ_128_64 = 512 + 2 * 2 * (128 + 64) * 128;   // 98816
    const int SZ_64_128 = 512 + 2 * 2 * (64 + 128) * 128;   // 98816
    const int SZ_64_64  = 512 + 2 * 2 * (64 + 64) * 128;    // 66048

#define SETSM(KERN, SZ) cudaFuncSetAttribute((const void*)(KERN), \
    cudaFuncAttributeMaxDynamicSharedMemorySize, SZ)
    SETSM((mmt<128, 64, 128, false, false, false, 0>), SZ_128_64);
    SETSM((mmt<64, 64, 128, true,  true,  false, 1>),  SZ_64_64);
    SETSM((mmt<64, 64, 128, false, true,  false, 1>),  SZ_64_64);
    SETSM((mmt<128, 64, 128, false, true,  false, 3>), SZ_128_64);
    SETSM((mmt<128, 64, 128, false, true,  true,  0>), SZ_128_64);
    SETSM(scores_softmax, SZ_64_128);
#undef SETSM

    // ---- operand prep (xw GEMM stays the 4th launch for ncu) ----
    cvtx_kernel<<<(NND * NF) / 256, 256>>>(x, emoh, emol);
    wt_kernel<<<(NF * NH) / 256, 256>>>(comp, basis, WtTh, WtTl);
    tcvt_all_kernel<<<409600 / 256, 256>>>(
        root, rootTh, rootTl, w_root, w_nbr, wcatTh, wcatTl,
        Wm, Wl, WqTh, WqTl);

    // xw = x @ Wt  (A = emo cols [0,512), lda=576) -> fp32
    mmt<128, 64, 128, false, false, false, 0>
        <<<dim3(16, 64, 1), 128, SZ_128_64>>>(
        emoh, emol, NDm, 0, WtTh, WtTl, 512, 0,
        xw, nullptr, nullptr, nullptr, nullptr, nullptr,
        1024, 0, 0, nullptr, 0, nullptr, 512);

    // ---- CSR build ----
    cudaMemsetAsync(cnt, 0, NND * sizeof(int));
    hist_kernel<<<NE / 256, 256>>>(ei, cnt);
    scan_kernel<<<1, 1024>>>(cnt, off, cur);
    fill_kernel<<<NE / 256, 256>>>(ei, et, cur, eidx);

    rgcn_gather<<<NND, 64>>>(off, eidx, xw, agg);

    // h1 = agg + x@root + bias1 -> a2 cols [0,64) pairs + packed h1p
    mmt<64, 64, 128, true, true, false, 1>
        <<<dim3(1, 128, 1), 128, SZ_64_64>>>(
        emoh, emol, NDm, 0, rootTh, rootTl, 512, 0,
        nullptr, a2h, a2l, h1p, nullptr, nullptr,
        128, 64, 0, agg, 64, bias1, 512);

    // gather(h1) -> a2 cols [64,128) pairs
    gc_gather<<<NND, 64>>>(off, eidx, h1p, a2h, a2l);

    // h2 = [h1 | aggH1] @ [w_root; w_nbr] + bias2 -> emo cols [512,576)
    mmt<64, 64, 128, false, true, false, 1>
        <<<dim3(1, 128, 1), 128, SZ_64_64>>>(
        a2h, a2l, 128, 0, wcatTh, wcatTl, 128, 0,
        nullptr, emoh + NF, emol + NF, nullptr, nullptr, nullptr,
        NDm, 0, 0, nullptr, 0, bias2, 128);

    // MERGED: Q = emo@Wm + bm -> pairs ; eW = emo@Wl -> transposed pairs
    mmt<128, 64, 128, false, true, false, 3>
        <<<dim3(10, 64, 1), 128, SZ_128_64>>>(
        emoh, emol, NDm, 0, WqTh, WqTl, NDm, 0,
        nullptr, Qh, Ql, nullptr, eWTh, eWTl,
        NDm, 0, 0, nullptr, 0, bm, NDm);

    // fused scores + softmax -> bf16 pairs
    scores_softmax<<<dim3(1, 2, NBc), 128, SZ_64_128>>>(
        Qh, Ql, emoh, emol, umask, Sh, Sl);

    // hidden = relu(alpha @ eWT + bl)   (batched, K=128, N=64)
    mmt<128, 64, 128, false, true, true, 0>
        <<<dim3(1, 1, NBc), 128, SZ_128_64>>>(
        Sh, Sl, NL, (long long)NL * NL, eWTh, eWTl, NL, (long long)NH * NL,
        hid, nullptr, nullptr, nullptr, nullptr, nullptr,
        NH, 0, (long long)NL * NH, nullptr, 0, bl, NL);

    head_kernel<<<NND / 128, 128>>>(hid, Ws, bs, out);

    (void)in_sizes; (void)n_in; (void)out_size;
}

// round 11
// speedup vs baseline: 1.0570x; 1.0570x over previous
#include <cuda_runtime.h>
#include <cuda_bf16.h>
#include <math.h>
#include <cstdint>

// ---- problem constants ----
#define NND 8192
#define NF  512
#define NH  64
#define NRel 16
#define NBase 30
#define NE  524288
#define NBc 64
#define NL  128
#define NDm 576
#define NC  7
#define KC  64          // K chunk (bf16) per pipeline stage; 128B rows

typedef __nv_bfloat16 bf16;
typedef unsigned int u32;

// ---- static device scratch ----
__device__ __align__(16) bf16 g_WtTh[1024 * 512];
__device__ __align__(16) bf16 g_WtTl[1024 * 512];
__device__ __align__(16) bf16 g_rootTh[64 * 512];
__device__ __align__(16) bf16 g_rootTl[64 * 512];
__device__ __align__(16) bf16 g_wcatTh[64 * 128];   // [n][k]: k<64 w_root, k>=64 w_nbr
__device__ __align__(16) bf16 g_wcatTl[64 * 128];
__device__ __align__(16) bf16 g_WmTh[576 * 576];
__device__ __align__(16) bf16 g_WmTl[576 * 576];
__device__ __align__(16) bf16 g_WlTh[64 * 576];
__device__ __align__(16) bf16 g_WlTl[64 * 576];
__device__ __align__(16) bf16 g_emoh[(size_t)NND * NDm];
__device__ __align__(16) bf16 g_emol[(size_t)NND * NDm];
__device__ __align__(16) bf16 g_a2h[NND * 128];     // cols [0,64)=h1, [64,128)=agg(h1)
__device__ __align__(16) bf16 g_a2l[NND * 128];
__device__ __align__(16) u32  g_h1p[NND * NH];      // packed (hi,lo) bf16x2 of h1
__device__ __align__(16) bf16 g_Qh[(size_t)NND * NDm];
__device__ __align__(16) bf16 g_Ql[(size_t)NND * NDm];
__device__ __align__(16) bf16 g_Sh[NND * NL];
__device__ __align__(16) bf16 g_Sl[NND * NL];
__device__ __align__(16) bf16 g_eWTh[NBc * NH * NL];  // [b][n][q]
__device__ __align__(16) bf16 g_eWTl[NBc * NH * NL];

__device__ __align__(16) float g_xw[(size_t)NND * NRel * NH];
__device__ __align__(16) float g_agg[NND * NH];
__device__ __align__(16) float g_hid[NND * NH];
// CSR
__device__ int g_cnt[NND];
__device__ int g_off[NND + 1];
__device__ int g_cur[NND];
__device__ int g_eidx[NE];

__device__ __forceinline__ void split_pair(float v, bf16& h, bf16& l) {
    h = __float2bfloat16(v);
    l = __float2bfloat16(v - __bfloat162float(h));
}

__device__ __forceinline__ u32 smem_u32(const void* p) {
    u32 a;
    asm("{ .reg .u64 t; cvta.to.shared.u64 t, %1; cvt.u32.u64 %0, t; }"
        : "=r"(a) : "l"(p));
    return a;
}

__device__ __forceinline__ void mma16816(float* d, const u32* a, const u32* b) {
    asm volatile(
        "mma.sync.aligned.m16n8k16.row.col.f32.bf16.bf16.f32 "
        "{%0,%1,%2,%3}, {%4,%5,%6,%7}, {%8,%9}, {%0,%1,%2,%3};"
        : "+f"(d[0]), "+f"(d[1]), "+f"(d[2]), "+f"(d[3])
        : "r"(a[0]), "r"(a[1]), "r"(a[2]), "r"(a[3]), "r"(b[0]), "r"(b[1]));
}

#define LDSM4(r, addr) \
    asm volatile("ldmatrix.sync.aligned.m8n8.x4.shared.b16 {%0,%1,%2,%3}, [%4];" \
        : "=r"((r)[0]), "=r"((r)[1]), "=r"((r)[2]), "=r"((r)[3]) : "r"(addr))

#define CPA(d, s) \
    asm volatile("cp.async.cg.shared.global [%0], [%1], 16;" :: "r"(d), "l"(s) : "memory")
#define CPC() asm volatile("cp.async.commit_group;" ::: "memory")
#define CPW0() asm volatile("cp.async.wait_group 0;" ::: "memory")

// ============================================================
// Pipelined warp-MMA 3xBF16 GEMM: C[M,N] = A @ B^T
// OUT_T: write pair output transposed per conversation: [m/128][n][m%128].
// Cp (if non-null, with OUT_PAIR): also write packed (hi,lo) u32 at [m*64+n].
// ============================================================
template <int BM, int NT, int THREADS,
          bool ADD_D, bool BIAS, bool RELU, bool OUT_PAIR, bool OUT_T>
__global__ void __launch_bounds__(THREADS, 2)
mmt(const bf16* __restrict__ Ah, const bf16* __restrict__ Al, int lda, long long sA,
    const bf16* __restrict__ Bh, const bf16* __restrict__ Bl, int ldb, long long sB,
    float* __restrict__ C, bf16* __restrict__ Ch, bf16* __restrict__ Cl,
    u32* __restrict__ Cp,
    int ldc, long long sC,
    const float* __restrict__ D, int ldd,
    const float* __restrict__ bias,
    int K)
{
    constexpr int WARPS = THREADS / 32;
    constexpr int WN = NT / 64;
    constexpr int WMC = WARPS / WN;
    constexpr int WM = BM / WMC;
    constexpr int MI = WM / 16;
    constexpr int STAGE_ROWS = 2 * (BM + NT);
    constexpr int STAGE_B = STAGE_ROWS * 128;
    constexpr int CHUNKS = STAGE_ROWS * 8 / THREADS;

    extern __shared__ char smem[];
    const u32 sb0 = smem_u32(smem) + 512;

    const int tid = threadIdx.x;
    const int wid = tid >> 5, lane = tid & 31;
    const int warpM = wid % WMC, warpN = wid / WMC;
    const int bz = blockIdx.z;
    const int m0 = blockIdx.y * BM;
    const int n0 = blockIdx.x * NT;

    const char* pAh = (const char*)(Ah + sA * bz + (size_t)m0 * lda);
    const char* pAl = (const char*)(Al + sA * bz + (size_t)m0 * lda);
    const char* pBh = (const char*)(Bh + sB * bz + (size_t)n0 * ldb);
    const char* pBl = (const char*)(Bl + sB * bz + (size_t)n0 * ldb);
    const size_t ldab = (size_t)lda * 2;
    const size_t ldbb = (size_t)ldb * 2;

    float acc[MI][8][4];
#pragma unroll
    for (int i = 0; i < MI; i++)
#pragma unroll
        for (int j = 0; j < 8; j++)
#pragma unroll
            for (int q = 0; q < 4; q++) acc[i][j][q] = 0.f;

    const int S = K / KC;

    auto load_stage = [&](int s) {
        const size_t kcb = (size_t)s * KC * 2;
        const u32 dst0 = sb0 + (u32)(s & 1) * STAGE_B;
#pragma unroll
        for (int f = 0; f < CHUNKS; f++) {
            int idx = tid + f * THREADS;
            int row = idx >> 3;
            u32 cb = (u32)(idx & 7) << 4;
            u32 sw = cb ^ (((u32)(row & 7)) << 4);
            const char* src;
            if (row < BM)               src = pAh + (size_t)row * ldab + kcb + cb;
            else if (row < 2 * BM)      src = pAl + (size_t)(row - BM) * ldab + kcb + cb;
            else if (row < 2 * BM + NT) src = pBh + (size_t)(row - 2 * BM) * ldbb + kcb + cb;
            else                        src = pBl + (size_t)(row - 2 * BM - NT) * ldbb + kcb + cb;
            CPA(dst0 + (u32)row * 128 + sw, src);
        }
    };

    load_stage(0);
    CPC();

    const u32 xorv = ((u32)(lane & 7)) << 4;
    const u32 aRow = (u32)(warpM * WM + (lane & 15));
    const u32 aCol0 = ((u32)(lane >> 4) & 1) * 16;
    const u32 bRow = (u32)(warpN * 64 + ((lane & 7) | ((lane & 16) >> 1)));
    const u32 bCol0 = ((u32)(lane >> 3) & 1) * 16;

    for (int s = 0; s < S; s++) {
        CPW0();
        __syncthreads();
        if (s + 1 < S) { load_stage(s + 1); CPC(); }

        const u32 base = sb0 + (u32)(s & 1) * STAGE_B;
        const u32 aH = base + aRow * 128;
        const u32 aL = aH + (u32)BM * 128;
        const u32 bH = base + (u32)(2 * BM) * 128 + bRow * 128;
        const u32 bL = bH + (u32)NT * 128;

#pragma unroll
        for (int ks = 0; ks < KC / 16; ks++) {
            const u32 kb = (u32)ks * 32;
            const u32 acol = (aCol0 + kb) ^ xorv;
            const u32 bcol = (bCol0 + kb) ^ xorv;
            u32 ah[MI][4], al[MI][4];
#pragma unroll
            for (int mi = 0; mi < MI; mi++) {
                LDSM4(ah[mi], aH + (u32)mi * (16 * 128) + acol);
                LDSM4(al[mi], aL + (u32)mi * (16 * 128) + acol);
            }
#pragma unroll
            for (int nt = 0; nt < 4; nt++) {
                u32 bh[4], bl[4];
                LDSM4(bh, bH + (u32)nt * (16 * 128) + bcol);
                LDSM4(bl, bL + (u32)nt * (16 * 128) + bcol);
#pragma unroll
                for (int mi = 0; mi < MI; mi++)
#pragma unroll
                    for (int half = 0; half < 2; half++) {
                        float* a4 = acc[mi][nt * 2 + half];
                        mma16816(a4, ah[mi], &bh[half * 2]);
                        mma16816(a4, ah[mi], &bl[half * 2]);
                        mma16816(a4, al[mi], &bh[half * 2]);
                    }
            }
        }
    }

    // ---- epilogue ----
#pragma unroll
    for (int mi = 0; mi < MI; mi++) {
        const int rm = m0 + warpM * WM + mi * 16 + (lane >> 2);
#pragma unroll
        for (int ni = 0; ni < 8; ni++) {
            const int n = n0 + warpN * 64 + ni * 8 + (lane & 3) * 2;
#pragma unroll
            for (int half = 0; half < 2; half++) {
                const int m = rm + half * 8;
                float v0 = acc[mi][ni][half * 2];
                float v1 = acc[mi][ni][half * 2 + 1];
                if (BIAS) { v0 += bias[n]; v1 += bias[n + 1]; }
                if (ADD_D) {
                    v0 += D[(size_t)m * ldd + n];
                    v1 += D[(size_t)m * ldd + n + 1];
                }
                if (RELU) { v0 = fmaxf(v0, 0.f); v1 = fmaxf(v1, 0.f); }
                if (OUT_PAIR) {
                    bf16 h0, l0, h1c, l1c;
                    split_pair(v0, h0, l0);
                    split_pair(v1, h1c, l1c);
                    if (OUT_T) {
                        size_t o = ((size_t)(m >> 7) * 64 + n) * 128 + (m & 127);
                        Ch[o] = h0; Ch[o + 128] = h1c;
                        Cl[o] = l0; Cl[o + 128] = l1c;
                    } else {
                        const size_t o = (size_t)sC * bz + (size_t)m * ldc + n;
                        *(__nv_bfloat162*)&Ch[o] = __nv_bfloat162(h0, h1c);
                        *(__nv_bfloat162*)&Cl[o] = __nv_bfloat162(l0, l1c);
                        if (Cp) {
                            __nv_bfloat162 p0(h0, l0), p1(h1c, l1c);
                            uint2 u; u.x = *(u32*)&p0; u.y = *(u32*)&p1;
                            *(uint2*)&Cp[(size_t)m * 64 + n] = u;
                        }
                    }
                } else {
                    float2 f2; f2.x = v0; f2.y = v1;
                    *(float2*)&C[(size_t)sC * bz + (size_t)m * ldc + n] = f2;
                }
            }
        }
    }
}

// ============================================================
// Fused scores kernel: S = tanh((Q.M)*u^2) -> softmax -> *u -> renorm
// ============================================================
__global__ void __launch_bounds__(128, 2)
scores_softmax(const bf16* __restrict__ Qh, const bf16* __restrict__ Ql,
               const bf16* __restrict__ Mh, const bf16* __restrict__ Ml,
               const float* __restrict__ um,
               bf16* __restrict__ Sh, bf16* __restrict__ Sl)
{
    constexpr int BM = 64, NT = 128, THREADS = 128;
    constexpr int STAGE_ROWS = 2 * (BM + NT);
    constexpr int STAGE_B = STAGE_ROWS * 128;
    constexpr int CHUNKS = STAGE_ROWS * 8 / THREADS;

    extern __shared__ char smem[];
    float* ums = (float*)smem;
    float* sbuf = (float*)(smem + 512);
    const u32 sb0 = smem_u32(smem) + 512;

    const int tid = threadIdx.x;
    const int wid = tid >> 5, lane = tid & 31;
    const int warpM = wid & 1, warpN = wid >> 1;
    const int bz = blockIdx.z;
    const int m0 = blockIdx.y * BM;

    const char* pAh = (const char*)(Qh + (size_t)bz * NL * NDm + (size_t)m0 * NDm);
    const char* pAl = (const char*)(Ql + (size_t)bz * NL * NDm + (size_t)m0 * NDm);
    const char* pBh = (const char*)(Mh + (size_t)bz * NL * NDm);
    const char* pBl = (const char*)(Ml + (size_t)bz * NL * NDm);
    const size_t ldab = (size_t)NDm * 2;

    if (tid < NT) ums[tid] = um[bz * NL + tid];

    float acc[2][8][4];
#pragma unroll
    for (int i = 0; i < 2; i++)
#pragma unroll
        for (int j = 0; j < 8; j++)
#pragma unroll
            for (int q = 0; q < 4; q++) acc[i][j][q] = 0.f;

    const int S = NDm / KC;

    auto load_stage = [&](int s) {
        const size_t kcb = (size_t)s * KC * 2;
        const u32 dst0 = sb0 + (u32)(s & 1) * STAGE_B;
#pragma unroll
        for (int f = 0; f < CHUNKS; f++) {
            int idx = tid + f * THREADS;
            int row = idx >> 3;
            u32 cb = (u32)(idx & 7) << 4;
            u32 sw = cb ^ (((u32)(row & 7)) << 4);
            const char* src;
            if (row < BM)               src = pAh + (size_t)row * ldab + kcb + cb;
            else if (row < 2 * BM)      src = pAl + (size_t)(row - BM) * ldab + kcb + cb;
            else if (row < 2 * BM + NT) src = pBh + (size_t)(row - 2 * BM) * ldab + kcb + cb;
            else                        src = pBl + (size_t)(row - 2 * BM - NT) * ldab + kcb + cb;
            CPA(dst0 + (u32)row * 128 + sw, src);
        }
    };

    load_stage(0);
    CPC();

    const u32 xorv = ((u32)(lane & 7)) << 4;
    const u32 aRow = (u32)(warpM * 32 + (lane & 15));
    const u32 aCol0 = ((u32)(lane >> 4) & 1) * 16;
    const u32 bRow = (u32)(warpN * 64 + ((lane & 7) | ((lane & 16) >> 1)));
    const u32 bCol0 = ((u32)(lane >> 3) & 1) * 16;

    for (int s = 0; s < S; s++) {
        CPW0();
        __syncthreads();
        if (s + 1 < S) { load_stage(s + 1); CPC(); }

        const u32 base = sb0 + (u32)(s & 1) * STAGE_B;
        const u32 aH = base + aRow * 128;
        const u32 aL = aH + (u32)BM * 128;
        const u32 bH = base + (u32)(2 * BM) * 128 + bRow * 128;
        const u32 bL = bH + (u32)NT * 128;

#pragma unroll
        for (int ks = 0; ks < KC / 16; ks++) {
            const u32 kb = (u32)ks * 32;
            const u32 acol = (aCol0 + kb) ^ xorv;
            const u32 bcol = (bCol0 + kb) ^ xorv;
            u32 ah[2][4], al[2][4];
#pragma unroll
            for (int mi = 0; mi < 2; mi++) {
                LDSM4(ah[mi], aH + (u32)mi * (16 * 128) + acol);
                LDSM4(al[mi], aL + (u32)mi * (16 * 128) + acol);
            }
#pragma unroll
            for (int nt = 0; nt < 4; nt++) {
                u32 bh[4], bl[4];
                LDSM4(bh, bH + (u32)nt * (16 * 128) + bcol);
                LDSM4(bl, bL + (u32)nt * (16 * 128) + bcol);
#pragma unroll
                for (int mi = 0; mi < 2; mi++)
#pragma unroll
                    for (int half = 0; half < 2; half++) {
                        float* a4 = acc[mi][nt * 2 + half];
                        mma16816(a4, ah[mi], &bh[half * 2]);
                        mma16816(a4, ah[mi], &bl[half * 2]);
                        mma16816(a4, al[mi], &bh[half * 2]);
                    }
            }
        }
    }
    __syncthreads();

    // ---- tanh(score*u^2) into smem (stride 132) ----
#pragma unroll
    for (int mi = 0; mi < 2; mi++) {
#pragma unroll
        for (int ni = 0; ni < 8; ni++) {
            const int col = warpN * 64 + ni * 8 + (lane & 3) * 2;
            const float u0 = ums[col], u1 = ums[col + 1];
#pragma unroll
            for (int half = 0; half < 2; half++) {
                const int row = warpM * 32 + mi * 16 + (lane >> 2) + half * 8;
                float v0 = tanhf(acc[mi][ni][half * 2] * u0 * u0);
                float v1 = tanhf(acc[mi][ni][half * 2 + 1] * u1 * u1);
                float2 f2; f2.x = v0; f2.y = v1;
                *(float2*)&sbuf[row * 132 + col] = f2;
            }
        }
    }
    __syncthreads();

    // ---- per-row softmax ----
    for (int r8 = 0; r8 < 16; r8++) {
        const int row = wid * 16 + r8;
        float4 v = *(const float4*)&sbuf[row * 132 + lane * 4];
        float mx = fmaxf(fmaxf(v.x, v.y), fmaxf(v.z, v.w));
#pragma unroll
        for (int o = 16; o > 0; o >>= 1)
            mx = fmaxf(mx, __shfl_xor_sync(0xffffffffu, mx, o));
        float e0 = expf(v.x - mx), e1 = expf(v.y - mx);
        float e2 = expf(v.z - mx), e3 = expf(v.w - mx);
        float sum1 = e0 + e1 + e2 + e3;
#pragma unroll
        for (int o = 16; o > 0; o >>= 1)
            sum1 += __shfl_xor_sync(0xffffffffu, sum1, o);
        const int col = lane * 4;
        float a0 = (e0 / sum1) * ums[col];
        float a1 = (e1 / sum1) * ums[col + 1];
        float a2 = (e2 / sum1) * ums[col + 2];
        float a3 = (e3 / sum1) * ums[col + 3];
        float sum2 = a0 + a1 + a2 + a3;
#pragma unroll
        for (int o = 16; o > 0; o >>= 1)
            sum2 += __shfl_xor_sync(0xffffffffu, sum2, o);
        float inv = 1.f / sum2;
        bf16 h0, l0, h1, l1, h2, l2, h3, l3;
        split_pair(a0 * inv, h0, l0);
        split_pair(a1 * inv, h1, l1);
        split_pair(a2 * inv, h2, l2);
        split_pair(a3 * inv, h3, l3);
        const size_t o0 = (size_t)(bz * NL + m0 + row) * NL + col;
        *(__nv_bfloat162*)&Sh[o0]     = __nv_bfloat162(h0, h1);
        *(__nv_bfloat162*)&Sh[o0 + 2] = __nv_bfloat162(h2, h3);
        *(__nv_bfloat162*)&Sl[o0]     = __nv_bfloat162(l0, l1);
        *(__nv_bfloat162*)&Sl[o0 + 2] = __nv_bfloat162(l2, l3);
    }
}

// ============================================================
// conversion kernels
// ============================================================
__global__ void cvtx_kernel(const float* __restrict__ x,
                            bf16* __restrict__ eh, bf16* __restrict__ el)
{
    int i = blockIdx.x * 256 + threadIdx.x;     // 8192*512
    bf16 h, l; split_pair(x[i], h, l);
    int row = i >> 9, c = i & 511;
    size_t eo = (size_t)row * NDm + c;
    eh[eo] = h; el[eo] = l;
}

// batched transpose+split: root, w_root/w_nbr (stacked), Wm, Wl
__global__ void tcvt_all_kernel(
    const float* __restrict__ root, bf16* __restrict__ rTh, bf16* __restrict__ rTl,
    const float* __restrict__ wr, const float* __restrict__ wn,
    bf16* __restrict__ wcTh, bf16* __restrict__ wcTl,
    const float* __restrict__ Wm, bf16* __restrict__ WmTh, bf16* __restrict__ WmTl,
    const float* __restrict__ Wl, bf16* __restrict__ WlTh, bf16* __restrict__ WlTl)
{
    int i = blockIdx.x * 256 + threadIdx.x;
    if (i < 32768) {
        int rr = i / 64, cc = i % 64;
        bf16 h, l; split_pair(root[i], h, l);
        rTh[(size_t)cc * 512 + rr] = h; rTl[(size_t)cc * 512 + rr] = l;
    } else if (i < 36864) {
        int j = i - 32768, rr = j / 64, cc = j % 64;
        bf16 h, l; split_pair(wr[j], h, l);
        wcTh[cc * 128 + rr] = h; wcTl[cc * 128 + rr] = l;
    } else if (i < 40960) {
        int j = i - 36864, rr = j / 64, cc = j % 64;
        bf16 h, l; split_pair(wn[j], h, l);
        wcTh[cc * 128 + 64 + rr] = h; wcTl[cc * 128 + 64 + rr] = l;
    } else if (i < 372736) {
        int j = i - 40960, rr = j / 576, cc = j % 576;
        bf16 h, l; split_pair(Wm[j], h, l);
        WmTh[(size_t)cc * 576 + rr] = h; WmTl[(size_t)cc * 576 + rr] = l;
    } else if (i < 409600) {
        int j = i - 372736, rr = j / 64, cc = j % 64;
        bf16 h, l; split_pair(Wl[j], h, l);
        WlTh[(size_t)cc * 576 + rr] = h; WlTl[(size_t)cc * 576 + rr] = l;
    }
}

// Wt: one thread per (k,h,relation-group-of-4); relation group in HIGH bits
// so warps stay contiguous over (k,h) -> coalesced basis reads, 4x reuse.
__global__ void wt_kernel(const float* __restrict__ comp,
                          const float* __restrict__ basis,
                          bf16* __restrict__ Wh, bf16* __restrict__ Wl)
{
    int i = blockIdx.x * 256 + threadIdx.x;   // 131072
    int rg = i >> 15;                          // 0..3
    int kh = i & 32767;
    int k = kh >> 6, h = kh & 63;
    float acc[4] = {0.f, 0.f, 0.f, 0.f};
    for (int b = 0; b < NBase; b++) {
        float bv = basis[((size_t)b * NF + k) * NH + h];
#pragma unroll
        for (int j = 0; j < 4; j++)
            acc[j] = fmaf(comp[(rg * 4 + j) * NBase + b], bv, acc[j]);
    }
#pragma unroll
    for (int j = 0; j < 4; j++) {
        bf16 hh, ll; split_pair(acc[j], hh, ll);
        size_t o = (size_t)((rg * 4 + j) * 64 + h) * 512 + k;
        Wh[o] = hh; Wl[o] = ll;
    }
}

// ---- CSR build ----
__global__ void hist_kernel(const int* __restrict__ ei, int* __restrict__ cnt)
{
    int i = blockIdx.x * 256 + threadIdx.x;
    if (i < NE) atomicAdd(&cnt[ei[NE + i]], 1);
}
__global__ void __launch_bounds__(1024)
scan_kernel(const int* __restrict__ cnt, int* __restrict__ off, int* __restrict__ cur)
{
    __shared__ int wsum[32];
    int t = threadIdx.x;
    int c[8], pre[8], p = 0;
#pragma unroll
    for (int j = 0; j < 8; j++) { c[j] = cnt[t * 8 + j]; pre[j] = p; p += c[j]; }
    const int tot = p;
    const int lane = t & 31, w = t >> 5;
    int sc = tot;
#pragma unroll
    for (int o = 1; o < 32; o <<= 1) {
        int v = __shfl_up_sync(0xffffffffu, sc, o);
        if (lane >= o) sc += v;
    }
    if (lane == 31) wsum[w] = sc;
    __syncthreads();
    if (w == 0) {
        int v = wsum[lane];
#pragma unroll
        for (int o = 1; o < 32; o <<= 1) {
            int x = __shfl_up_sync(0xffffffffu, v, o);
            if (lane >= o) v += x;
        }
        wsum[lane] = v;
    }
    __syncthreads();
    const int base = (w ? wsum[w - 1] : 0) + (sc - tot);
#pragma unroll
    for (int j = 0; j < 8; j++) {
        off[t * 8 + j + 1] = base + pre[j] + c[j];
        cur[t * 8 + j] = base + pre[j];
    }
    if (t == 0) off[0] = 0;
}
__global__ void fill_kernel(const int* __restrict__ ei, const int* __restrict__ et,
                            int* __restrict__ cur, int* __restrict__ eidx)
{
    int i = blockIdx.x * 256 + threadIdx.x;
    if (i >= NE) return;
    int dst = ei[NE + i];
    int pos = atomicAdd(&cur[dst], 1);
    eidx[pos] = ei[i] * 16 + et[i];
}

// ---- CSR gathers ----
__global__ void __launch_bounds__(64)
rgcn_gather(const int* __restrict__ off, const int* __restrict__ eidx,
            const float* __restrict__ xw, float* __restrict__ agg)
{
    const int n = blockIdx.x, h = threadIdx.x;
    const int beg = off[n], end = off[n + 1];
    float acc = 0.f;
    int e = beg;
    for (; e + 4 <= end; e += 4) {
        int p0 = eidx[e], p1 = eidx[e + 1], p2 = eidx[e + 2], p3 = eidx[e + 3];
        acc += xw[(size_t)(p0 >> 4) * 1024 + (p0 & 15) * 64 + h]
             + xw[(size_t)(p1 >> 4) * 1024 + (p1 & 15) * 64 + h]
             + xw[(size_t)(p2 >> 4) * 1024 + (p2 & 15) * 64 + h]
             + xw[(size_t)(p3 >> 4) * 1024 + (p3 & 15) * 64 + h];
    }
    for (; e < end; e++) {
        int p = eidx[e];
        acc += xw[(size_t)(p >> 4) * 1024 + (p & 15) * 64 + h];
    }
    agg[n * NH + h] = acc / fmaxf((float)(end - beg), 1.f);
}

// gather sum of h1 (packed pairs) -> a2 pair cols [64,128)
__global__ void __launch_bounds__(64)
gc_gather(const int* __restrict__ off, const int* __restrict__ eidx,
          const u32* __restrict__ h1p, bf16* __restrict__ a2h, bf16* __restrict__ a2l)
{
    const int n = blockIdx.x, h = threadIdx.x;
    const int beg = off[n], end = off[n + 1];
    float acc = 0.f;
    int e = beg;
    for (; e + 4 <= end; e += 4) {
        u32 q0 = h1p[(eidx[e] >> 4) * 64 + h];
        u32 q1 = h1p[(eidx[e + 1] >> 4) * 64 + h];
        u32 q2 = h1p[(eidx[e + 2] >> 4) * 64 + h];
        u32 q3 = h1p[(eidx[e + 3] >> 4) * 64 + h];
        __nv_bfloat162 t0 = *(__nv_bfloat162*)&q0, t1 = *(__nv_bfloat162*)&q1;
        __nv_bfloat162 t2 = *(__nv_bfloat162*)&q2, t3 = *(__nv_bfloat162*)&q3;
        acc += __bfloat162float(t0.x) + __bfloat162float(t0.y)
             + __bfloat162float(t1.x) + __bfloat162float(t1.y)
             + __bfloat162float(t2.x) + __bfloat162float(t2.y)
             + __bfloat162float(t3.x) + __bfloat162float(t3.y);
    }
    for (; e < end; e++) {
        u32 q = h1p[(eidx[e] >> 4) * 64 + h];
        __nv_bfloat162 t = *(__nv_bfloat162*)&q;
        acc += __bfloat162float(t.x) + __bfloat162float(t.y);
    }
    bf16 hh, ll; split_pair(acc, hh, ll);
    a2h[n * 128 + 64 + h] = hh;
    a2l[n * 128 + 64 + h] = ll;
}

// head: logits = hid @ Ws + bs ; log_softmax
__global__ void head_kernel(const float* __restrict__ hid, const float* __restrict__ Ws,
                            const float* __restrict__ bsv, float* __restrict__ out)
{
    int n = blockIdx.x * blockDim.x + threadIdx.x;
    if (n >= NND) return;
    float lg[NC];
#pragma unroll
    for (int c = 0; c < NC; c++) lg[c] = bsv[c];
    const float* h = hid + (size_t)n * NH;
#pragma unroll 8
    for (int k = 0; k < NH; k++) {
        float hv = h[k];
#pragma unroll
        for (int c = 0; c < NC; c++) lg[c] = fmaf(hv, Ws[k * NC + c], lg[c]);
    }
    float mx = lg[0];
#pragma unroll
    for (int c = 1; c < NC; c++) mx = fmaxf(mx, lg[c]);
    float ssum = 0.f;
#pragma unroll
    for (int c = 0; c < NC; c++) ssum += expf(lg[c] - mx);
    float lse = mx + logf(ssum);
#pragma unroll
    for (int c = 0; c < NC; c++) out[(size_t)n * NC + c] = lg[c] - lse;
}

// ============================================================
extern "C" void kernel_launch(void* const* d_in, const int* in_sizes, int n_in,
                              void* d_out, int out_size)
{
    const float* x      = (const float*)d_in[0];
    const int*   ei     = (const int*)d_in[1];
    const int*   et     = (const int*)d_in[3];
    const float* umask  = (const float*)d_in[5];
    const float* basis  = (const float*)d_in[8];
    const float* comp   = (const float*)d_in[9];
    const float* root   = (const float*)d_in[10];
    const float* bias1  = (const float*)d_in[11];
    const float* w_nbr  = (const float*)d_in[12];
    const float* w_root = (const float*)d_in[13];
    const float* bias2  = (const float*)d_in[14];
    const float* Wm     = (const float*)d_in[15];
    const float* bm     = (const float*)d_in[16];
    const float* Wl     = (const float*)d_in[17];
    const float* bl     = (const float*)d_in[18];
    const float* Ws     = (const float*)d_in[19];
    const float* bs     = (const float*)d_in[20];
    float* out = (float*)d_out;

#define SYM(T, v, s) T* v; cudaGetSymbolAddress((void**)&v, s)
    SYM(bf16, WtTh, g_WtTh); SYM(bf16, WtTl, g_WtTl);
    SYM(bf16, rootTh, g_rootTh); SYM(bf16, rootTl, g_rootTl);
    SYM(bf16, wcatTh, g_wcatTh); SYM(bf16, wcatTl, g_wcatTl);
    SYM(bf16, WmTh, g_WmTh); SYM(bf16, WmTl, g_WmTl);
    SYM(bf16, WlTh, g_WlTh); SYM(bf16, WlTl, g_WlTl);
    SYM(bf16, emoh, g_emoh); SYM(bf16, emol, g_emol);
    SYM(bf16, a2h, g_a2h); SYM(bf16, a2l, g_a2l);
    SYM(u32, h1p, g_h1p);
    SYM(bf16, Qh, g_Qh); SYM(bf16, Ql, g_Ql);
    SYM(bf16, Sh, g_Sh); SYM(bf16, Sl, g_Sl);
    SYM(bf16, eWTh, g_eWTh); SYM(bf16, eWTl, g_eWTl);
    SYM(float, xw, g_xw); SYM(float, agg, g_agg); SYM(float, hid, g_hid);
    SYM(int, cnt, g_cnt); SYM(int, off, g_off); SYM(int, cur, g_cur);
    SYM(int, eidx, g_eidx);
#undef SYM

    const int SZ_128_64 = 512 + 2 * 2 * (128 + 64) * 128;   // 98816
    const int SZ_64_128 = 512 + 2 * 2 * (64 + 128) * 128;   // 98816
    const int SZ_64_64  = 512 + 2 * 2 * (64 + 64) * 128;    // 66048

#define SETSM(KERN, SZ) cudaFuncSetAttribute((const void*)(KERN), \
    cudaFuncAttributeMaxDynamicSharedMemorySize, SZ)
    SETSM((mmt<128, 64, 128, false, false, false, false, false>), SZ_128_64);
    SETSM((mmt<64, 64, 128, true,  true,  false, true,  false>),  SZ_64_64);
    SETSM((mmt<64, 64, 128, false, true,  false, true,  false>),  SZ_64_64);
    SETSM((mmt<128, 64, 128, false, true,  false, true,  false>), SZ_128_64);
    SETSM((mmt<64, 64, 128, false, false, false, true,  true>),   SZ_64_64);
    SETSM((mmt<64, 64, 128, false, true,  true,  false, false>),  SZ_64_64);
    SETSM(scores_softmax, SZ_64_128);
#undef SETSM

    // ---- operand prep (xw GEMM stays the 4th launch for ncu) ----
    cvtx_kernel<<<(NND * NF) / 256, 256>>>(x, emoh, emol);
    wt_kernel<<<(4 * NF * NH) / 256, 256>>>(comp, basis, WtTh, WtTl);
    tcvt_all_kernel<<<409600 / 256, 256>>>(
        root, rootTh, rootTl, w_root, w_nbr, wcatTh, wcatTl,
        Wm, WmTh, WmTl, Wl, WlTh, WlTl);

    // xw = x @ Wt  (A = emo cols [0,512), lda=576)
    mmt<128, 64, 128, false, false, false, false, false>
        <<<dim3(16, 64, 1), 128, SZ_128_64>>>(
        emoh, emol, NDm, 0, WtTh, WtTl, 512, 0,
        xw, nullptr, nullptr, nullptr, 1024, 0, nullptr, 0, nullptr, 512);

    // ---- CSR build ----
    cudaMemsetAsync(cnt, 0, NND * sizeof(int));
    hist_kernel<<<NE / 256, 256>>>(ei, cnt);
    scan_kernel<<<1, 1024>>>(cnt, off, cur);
    fill_kernel<<<NE / 256, 256>>>(ei, et, cur, eidx);

    rgcn_gather<<<NND, 64>>>(off, eidx, xw, agg);

    // h1 = agg + x@root + bias1 -> a2 cols [0,64) pairs + packed h1p
    mmt<64, 64, 128, true, true, false, true, false>
        <<<dim3(1, 128, 1), 128, SZ_64_64>>>(
        emoh, emol, NDm, 0, rootTh, rootTl, 512, 0,
        nullptr, a2h, a2l, h1p, 128, 0, agg, 64, bias1, 512);

    // gather(h1) -> a2 cols [64,128) pairs
    gc_gather<<<NND, 64>>>(off, eidx, h1p, a2h, a2l);

    // h2 = [h1 | aggH1] @ [w_root; w_nbr] + bias2 -> emo cols [512,576)
    mmt<64, 64, 128, false, true, false, true, false>
        <<<dim3(1, 128, 1), 128, SZ_64_64>>>(
        a2h, a2l, 128, 0, wcatTh, wcatTl, 128, 0,
        nullptr, emoh + NF, emol + NF, nullptr, NDm, 0, nullptr, 0, bias2, 128);

    // Q = emo @ Wm + bm -> pairs
    mmt<128, 64, 128, false, true, false, true, false>
        <<<dim3(9, 64, 1), 128, SZ_128_64>>>(
        emoh, emol, NDm, 0, WmTh, WmTl, NDm, 0,
        nullptr, Qh, Ql, nullptr, NDm, 0, nullptr, 0, bm, NDm);

    // eW = emo @ Wl -> per-conversation TRANSPOSED pairs eWT[b][n][q]
    mmt<64, 64, 128, false, false, false, true, true>
        <<<dim3(1, 128, 1), 128, SZ_64_64>>>(
        emoh, emol, NDm, 0, WlTh, WlTl, NDm, 0,
        nullptr, eWTh, eWTl, nullptr, 0, 0, nullptr, 0, nullptr, NDm);

    // fused scores + softmax -> bf16 pairs
    scores_softmax<<<dim3(1, 2, NBc), 128, SZ_64_128>>>(
        Qh, Ql, emoh, emol, umask, Sh, Sl);

    // hidden = relu(alpha @ eWT + bl)   (batched, BM=64 -> 128 CTAs)
    mmt<64, 64, 128, false, true, true, false, false>
        <<<dim3(1, 2, NBc), 128, SZ_64_64>>>(
        Sh, Sl, NL, (long long)NL * NL, eWTh, eWTl, NL, (long long)NH * NL,
        hid, nullptr, nullptr, nullptr, NH, (long long)NL * NH, nullptr, 0, bl, NL);

    head_kernel<<<NND / 128, 128>>>(hid, Ws, bs, out);

    (void)in_sizes; (void)n_in; (void)out_size;
}

// round 12
// speedup vs baseline: 1.1093x; 1.0495x over previous
#include <cuda_runtime.h>
#include <cuda_bf16.h>
#include <math.h>
#include <cstdint>

// ---- problem constants ----
#define NND 8192
#define NF  512
#define NH  64
#define NRel 16
#define NBase 30
#define NE  524288
#define NBc 64
#define NL  128
#define NDm 576
#define NC  7
#define KC  64          // K chunk (bf16) per pipeline stage; 128B rows

typedef __nv_bfloat16 bf16;
typedef unsigned int u32;

// ---- static device scratch ----
__device__ __align__(16) bf16 g_WtTh[1024 * 512];
__device__ __align__(16) bf16 g_WtTl[1024 * 512];
__device__ __align__(16) bf16 g_rootTh[64 * 512];
__device__ __align__(16) bf16 g_rootTl[64 * 512];
__device__ __align__(16) bf16 g_wcatTh[64 * 128];   // [n][k]: k<64 w_root, k>=64 w_nbr
__device__ __align__(16) bf16 g_wcatTl[64 * 128];
__device__ __align__(16) bf16 g_WmTh[576 * 576];
__device__ __align__(16) bf16 g_WmTl[576 * 576];
__device__ __align__(16) bf16 g_WlTh[64 * 576];
__device__ __align__(16) bf16 g_WlTl[64 * 576];
__device__ __align__(16) bf16 g_emoh[(size_t)NND * NDm];
__device__ __align__(16) bf16 g_emol[(size_t)NND * NDm];
__device__ __align__(16) bf16 g_a2h[NND * 128];     // cols [0,64)=h1, [64,128)=agg(h1)
__device__ __align__(16) bf16 g_a2l[NND * 128];
__device__ __align__(16) u32  g_h1p[NND * NH];      // packed (hi,lo) bf16x2 of h1
__device__ __align__(16) bf16 g_Qh[(size_t)NND * NDm];
__device__ __align__(16) bf16 g_Ql[(size_t)NND * NDm];
__device__ __align__(16) bf16 g_Sh[NND * NL];
__device__ __align__(16) bf16 g_Sl[NND * NL];
__device__ __align__(16) bf16 g_eWTh[NBc * NH * NL];  // [b][n][q]
__device__ __align__(16) bf16 g_eWTl[NBc * NH * NL];

__device__ __align__(16) float g_xw[(size_t)NND * NRel * NH];
__device__ __align__(16) float g_agg[NND * NH];
// CSR
__device__ int g_cnt[NND];
__device__ int g_off[NND + 1];
__device__ int g_cur[NND];
__device__ int g_eidx[NE];

__device__ __forceinline__ void split_pair(float v, bf16& h, bf16& l) {
    h = __float2bfloat16(v);
    l = __float2bfloat16(v - __bfloat162float(h));
}

__device__ __forceinline__ u32 smem_u32(const void* p) {
    u32 a;
    asm("{ .reg .u64 t; cvta.to.shared.u64 t, %1; cvt.u32.u64 %0, t; }"
        : "=r"(a) : "l"(p));
    return a;
}

__device__ __forceinline__ void mma16816(float* d, const u32* a, const u32* b) {
    asm volatile(
        "mma.sync.aligned.m16n8k16.row.col.f32.bf16.bf16.f32 "
        "{%0,%1,%2,%3}, {%4,%5,%6,%7}, {%8,%9}, {%0,%1,%2,%3};"
        : "+f"(d[0]), "+f"(d[1]), "+f"(d[2]), "+f"(d[3])
        : "r"(a[0]), "r"(a[1]), "r"(a[2]), "r"(a[3]), "r"(b[0]), "r"(b[1]));
}

#define LDSM4(r, addr) \
    asm volatile("ldmatrix.sync.aligned.m8n8.x4.shared.b16 {%0,%1,%2,%3}, [%4];" \
        : "=r"((r)[0]), "=r"((r)[1]), "=r"((r)[2]), "=r"((r)[3]) : "r"(addr))

#define CPA(d, s) \
    asm volatile("cp.async.cg.shared.global [%0], [%1], 16;" :: "r"(d), "l"(s) : "memory")
#define CPC() asm volatile("cp.async.commit_group;" ::: "memory")
#define CPW0() asm volatile("cp.async.wait_group 0;" ::: "memory")

// ============================================================
// Pipelined warp-MMA 3xBF16 GEMM: C[M,N] = A @ B^T
// OUT_T: write pair output transposed per conversation: [m/128][n][m%128].
// Cp (if non-null, with OUT_PAIR): also write packed (hi,lo) u32 at [m*64+n].
// HEAD: fused classifier head — logits = hid@Ws+bs, log_softmax -> C (7/row).
// ============================================================
template <int BM, int NT, int THREADS,
          bool ADD_D, bool BIAS, bool RELU, bool OUT_PAIR, bool OUT_T, bool HEAD>
__global__ void __launch_bounds__(THREADS, 2)
mmt(const bf16* __restrict__ Ah, const bf16* __restrict__ Al, int lda, long long sA,
    const bf16* __restrict__ Bh, const bf16* __restrict__ Bl, int ldb, long long sB,
    float* __restrict__ C, bf16* __restrict__ Ch, bf16* __restrict__ Cl,
    u32* __restrict__ Cp,
    int ldc, long long sC,
    const float* __restrict__ D, int ldd,
    const float* __restrict__ bias,
    const float* __restrict__ Ws, const float* __restrict__ bsv,
    int K)
{
    constexpr int WARPS = THREADS / 32;
    constexpr int WN = NT / 64;
    constexpr int WMC = WARPS / WN;
    constexpr int WM = BM / WMC;
    constexpr int MI = WM / 16;
    constexpr int STAGE_ROWS = 2 * (BM + NT);
    constexpr int STAGE_B = STAGE_ROWS * 128;
    constexpr int CHUNKS = STAGE_ROWS * 8 / THREADS;

    extern __shared__ char smem[];
    const u32 sb0 = smem_u32(smem) + 512;

    const int tid = threadIdx.x;
    const int wid = tid >> 5, lane = tid & 31;
    const int warpM = wid % WMC, warpN = wid / WMC;
    const int bz = blockIdx.z;
    const int m0 = blockIdx.y * BM;
    const int n0 = blockIdx.x * NT;

    const char* pAh = (const char*)(Ah + sA * bz + (size_t)m0 * lda);
    const char* pAl = (const char*)(Al + sA * bz + (size_t)m0 * lda);
    const char* pBh = (const char*)(Bh + sB * bz + (size_t)n0 * ldb);
    const char* pBl = (const char*)(Bl + sB * bz + (size_t)n0 * ldb);
    const size_t ldab = (size_t)lda * 2;
    const size_t ldbb = (size_t)ldb * 2;

    float acc[MI][8][4];
#pragma unroll
    for (int i = 0; i < MI; i++)
#pragma unroll
        for (int j = 0; j < 8; j++)
#pragma unroll
            for (int q = 0; q < 4; q++) acc[i][j][q] = 0.f;

    const int S = K / KC;

    auto load_stage = [&](int s) {
        const size_t kcb = (size_t)s * KC * 2;
        const u32 dst0 = sb0 + (u32)(s & 1) * STAGE_B;
#pragma unroll
        for (int f = 0; f < CHUNKS; f++) {
            int idx = tid + f * THREADS;
            int row = idx >> 3;
            u32 cb = (u32)(idx & 7) << 4;
            u32 sw = cb ^ (((u32)(row & 7)) << 4);
            const char* src;
            if (row < BM)               src = pAh + (size_t)row * ldab + kcb + cb;
            else if (row < 2 * BM)      src = pAl + (size_t)(row - BM) * ldab + kcb + cb;
            else if (row < 2 * BM + NT) src = pBh + (size_t)(row - 2 * BM) * ldbb + kcb + cb;
            else                        src = pBl + (size_t)(row - 2 * BM - NT) * ldbb + kcb + cb;
            CPA(dst0 + (u32)row * 128 + sw, src);
        }
    };

    load_stage(0);
    CPC();

    const u32 xorv = ((u32)(lane & 7)) << 4;
    const u32 aRow = (u32)(warpM * WM + (lane & 15));
    const u32 aCol0 = ((u32)(lane >> 4) & 1) * 16;
    const u32 bRow = (u32)(warpN * 64 + ((lane & 7) | ((lane & 16) >> 1)));
    const u32 bCol0 = ((u32)(lane >> 3) & 1) * 16;

    for (int s = 0; s < S; s++) {
        CPW0();
        __syncthreads();
        if (s + 1 < S) { load_stage(s + 1); CPC(); }

        const u32 base = sb0 + (u32)(s & 1) * STAGE_B;
        const u32 aH = base + aRow * 128;
        const u32 aL = aH + (u32)BM * 128;
        const u32 bH = base + (u32)(2 * BM) * 128 + bRow * 128;
        const u32 bL = bH + (u32)NT * 128;

#pragma unroll
        for (int ks = 0; ks < KC / 16; ks++) {
            const u32 kb = (u32)ks * 32;
            const u32 acol = (aCol0 + kb) ^ xorv;
            const u32 bcol = (bCol0 + kb) ^ xorv;
            u32 ah[MI][4], al[MI][4];
#pragma unroll
            for (int mi = 0; mi < MI; mi++) {
                LDSM4(ah[mi], aH + (u32)mi * (16 * 128) + acol);
                LDSM4(al[mi], aL + (u32)mi * (16 * 128) + acol);
            }
#pragma unroll
            for (int nt = 0; nt < 4; nt++) {
                u32 bh[4], bl[4];
                LDSM4(bh, bH + (u32)nt * (16 * 128) + bcol);
                LDSM4(bl, bL + (u32)nt * (16 * 128) + bcol);
#pragma unroll
                for (int mi = 0; mi < MI; mi++)
#pragma unroll
                    for (int half = 0; half < 2; half++) {
                        float* a4 = acc[mi][nt * 2 + half];
                        mma16816(a4, ah[mi], &bh[half * 2]);
                        mma16816(a4, ah[mi], &bl[half * 2]);
                        mma16816(a4, al[mi], &bh[half * 2]);
                    }
            }
        }
    }

    if (HEAD) {
        // ---- fused classifier head ----
        // stage Ws[64][7] + bs[7] in smem (stage buffers are dead now)
        __syncthreads();
        float* wss = (float*)smem;            // 448 + 7 floats
        for (int i = tid; i < NH * NC + NC; i += THREADS)
            wss[i] = (i < NH * NC) ? Ws[i] : bsv[i - NH * NC];
        __syncthreads();
        const int tg = lane & 3;
#pragma unroll
        for (int mi = 0; mi < MI; mi++) {
#pragma unroll
            for (int half = 0; half < 2; half++) {
                const int m = m0 + warpM * WM + mi * 16 + (lane >> 2) + half * 8;
                float lg[NC];
#pragma unroll
                for (int c = 0; c < NC; c++) lg[c] = 0.f;
#pragma unroll
                for (int ni = 0; ni < 8; ni++) {
                    const int n = ni * 8 + tg * 2;
                    float v0 = acc[mi][ni][half * 2];
                    float v1 = acc[mi][ni][half * 2 + 1];
                    if (BIAS) { v0 += bias[n]; v1 += bias[n + 1]; }
                    if (RELU) { v0 = fmaxf(v0, 0.f); v1 = fmaxf(v1, 0.f); }
#pragma unroll
                    for (int c = 0; c < NC; c++)
                        lg[c] = fmaf(v0, wss[n * NC + c],
                                     fmaf(v1, wss[(n + 1) * NC + c], lg[c]));
                }
#pragma unroll
                for (int o = 1; o < 4; o <<= 1)
#pragma unroll
                    for (int c = 0; c < NC; c++)
                        lg[c] += __shfl_xor_sync(0xffffffffu, lg[c], o);
                if (tg == 0) {
#pragma unroll
                    for (int c = 0; c < NC; c++) lg[c] += wss[NH * NC + c];
                    float mx = lg[0];
#pragma unroll
                    for (int c = 1; c < NC; c++) mx = fmaxf(mx, lg[c]);
                    float ssum = 0.f;
#pragma unroll
                    for (int c = 0; c < NC; c++) ssum += expf(lg[c] - mx);
                    float lse = mx + logf(ssum);
                    const size_t o0 = (size_t)(bz * NL + m) * NC;
#pragma unroll
                    for (int c = 0; c < NC; c++) C[o0 + c] = lg[c] - lse;
                }
            }
        }
        return;
    }

    // ---- standard epilogue ----
#pragma unroll
    for (int mi = 0; mi < MI; mi++) {
        const int rm = m0 + warpM * WM + mi * 16 + (lane >> 2);
#pragma unroll
        for (int ni = 0; ni < 8; ni++) {
            const int n = n0 + warpN * 64 + ni * 8 + (lane & 3) * 2;
#pragma unroll
            for (int half = 0; half < 2; half++) {
                const int m = rm + half * 8;
                float v0 = acc[mi][ni][half * 2];
                float v1 = acc[mi][ni][half * 2 + 1];
                if (BIAS) { v0 += bias[n]; v1 += bias[n + 1]; }
                if (ADD_D) {
                    v0 += D[(size_t)m * ldd + n];
                    v1 += D[(size_t)m * ldd + n + 1];
                }
                if (RELU) { v0 = fmaxf(v0, 0.f); v1 = fmaxf(v1, 0.f); }
                if (OUT_PAIR) {
                    bf16 h0, l0, h1c, l1c;
                    split_pair(v0, h0, l0);
                    split_pair(v1, h1c, l1c);
                    if (OUT_T) {
                        size_t o = ((size_t)(m >> 7) * 64 + n) * 128 + (m & 127);
                        Ch[o] = h0; Ch[o + 128] = h1c;
                        Cl[o] = l0; Cl[o + 128] = l1c;
                    } else {
                        const size_t o = (size_t)sC * bz + (size_t)m * ldc + n;
                        *(__nv_bfloat162*)&Ch[o] = __nv_bfloat162(h0, h1c);
                        *(__nv_bfloat162*)&Cl[o] = __nv_bfloat162(l0, l1c);
                        if (Cp) {
                            __nv_bfloat162 p0(h0, l0), p1(h1c, l1c);
                            uint2 u; u.x = *(u32*)&p0; u.y = *(u32*)&p1;
                            *(uint2*)&Cp[(size_t)m * 64 + n] = u;
                        }
                    }
                } else {
                    float2 f2; f2.x = v0; f2.y = v1;
                    *(float2*)&C[(size_t)sC * bz + (size_t)m * ldc + n] = f2;
                }
            }
        }
    }
}

// ============================================================
// Fused scores kernel: S = tanh((Q.M)*u^2) -> softmax -> *u -> renorm
// ============================================================
__global__ void __launch_bounds__(128, 2)
scores_softmax(const bf16* __restrict__ Qh, const bf16* __restrict__ Ql,
               const bf16* __restrict__ Mh, const bf16* __restrict__ Ml,
               const float* __restrict__ um,
               bf16* __restrict__ Sh, bf16* __restrict__ Sl)
{
    constexpr int BM = 64, NT = 128, THREADS = 128;
    constexpr int STAGE_ROWS = 2 * (BM + NT);
    constexpr int STAGE_B = STAGE_ROWS * 128;
    constexpr int CHUNKS = STAGE_ROWS * 8 / THREADS;

    extern __shared__ char smem[];
    float* ums = (float*)smem;
    float* sbuf = (float*)(smem + 512);
    const u32 sb0 = smem_u32(smem) + 512;

    const int tid = threadIdx.x;
    const int wid = tid >> 5, lane = tid & 31;
    const int warpM = wid & 1, warpN = wid >> 1;
    const int bz = blockIdx.z;
    const int m0 = blockIdx.y * BM;

    const char* pAh = (const char*)(Qh + (size_t)bz * NL * NDm + (size_t)m0 * NDm);
    const char* pAl = (const char*)(Ql + (size_t)bz * NL * NDm + (size_t)m0 * NDm);
    const char* pBh = (const char*)(Mh + (size_t)bz * NL * NDm);
    const char* pBl = (const char*)(Ml + (size_t)bz * NL * NDm);
    const size_t ldab = (size_t)NDm * 2;

    if (tid < NT) ums[tid] = um[bz * NL + tid];

    float acc[2][8][4];
#pragma unroll
    for (int i = 0; i < 2; i++)
#pragma unroll
        for (int j = 0; j < 8; j++)
#pragma unroll
            for (int q = 0; q < 4; q++) acc[i][j][q] = 0.f;

    const int S = NDm / KC;

    auto load_stage = [&](int s) {
        const size_t kcb = (size_t)s * KC * 2;
        const u32 dst0 = sb0 + (u32)(s & 1) * STAGE_B;
#pragma unroll
        for (int f = 0; f < CHUNKS; f++) {
            int idx = tid + f * THREADS;
            int row = idx >> 3;
            u32 cb = (u32)(idx & 7) << 4;
            u32 sw = cb ^ (((u32)(row & 7)) << 4);
            const char* src;
            if (row < BM)               src = pAh + (size_t)row * ldab + kcb + cb;
            else if (row < 2 * BM)      src = pAl + (size_t)(row - BM) * ldab + kcb + cb;
            else if (row < 2 * BM + NT) src = pBh + (size_t)(row - 2 * BM) * ldab + kcb + cb;
            else                        src = pBl + (size_t)(row - 2 * BM - NT) * ldab + kcb + cb;
            CPA(dst0 + (u32)row * 128 + sw, src);
        }
    };

    load_stage(0);
    CPC();

    const u32 xorv = ((u32)(lane & 7)) << 4;
    const u32 aRow = (u32)(warpM * 32 + (lane & 15));
    const u32 aCol0 = ((u32)(lane >> 4) & 1) * 16;
    const u32 bRow = (u32)(warpN * 64 + ((lane & 7) | ((lane & 16) >> 1)));
    const u32 bCol0 = ((u32)(lane >> 3) & 1) * 16;

    for (int s = 0; s < S; s++) {
        CPW0();
        __syncthreads();
        if (s + 1 < S) { load_stage(s + 1); CPC(); }

        const u32 base = sb0 + (u32)(s & 1) * STAGE_B;
        const u32 aH = base + aRow * 128;
        const u32 aL = aH + (u32)BM * 128;
        const u32 bH = base + (u32)(2 * BM) * 128 + bRow * 128;
        const u32 bL = bH + (u32)NT * 128;

#pragma unroll
        for (int ks = 0; ks < KC / 16; ks++) {
            const u32 kb = (u32)ks * 32;
            const u32 acol = (aCol0 + kb) ^ xorv;
            const u32 bcol = (bCol0 + kb) ^ xorv;
            u32 ah[2][4], al[2][4];
#pragma unroll
            for (int mi = 0; mi < 2; mi++) {
                LDSM4(ah[mi], aH + (u32)mi * (16 * 128) + acol);
                LDSM4(al[mi], aL + (u32)mi * (16 * 128) + acol);
            }
#pragma unroll
            for (int nt = 0; nt < 4; nt++) {
                u32 bh[4], bl[4];
                LDSM4(bh, bH + (u32)nt * (16 * 128) + bcol);
                LDSM4(bl, bL + (u32)nt * (16 * 128) + bcol);
#pragma unroll
                for (int mi = 0; mi < 2; mi++)
#pragma unroll
                    for (int half = 0; half < 2; half++) {
                        float* a4 = acc[mi][nt * 2 + half];
                        mma16816(a4, ah[mi], &bh[half * 2]);
                        mma16816(a4, ah[mi], &bl[half * 2]);
                        mma16816(a4, al[mi], &bh[half * 2]);
                    }
            }
        }
    }
    __syncthreads();

    // ---- tanh(score*u^2) into smem (stride 132) ----
#pragma unroll
    for (int mi = 0; mi < 2; mi++) {
#pragma unroll
        for (int ni = 0; ni < 8; ni++) {
            const int col = warpN * 64 + ni * 8 + (lane & 3) * 2;
            const float u0 = ums[col], u1 = ums[col + 1];
#pragma unroll
            for (int half = 0; half < 2; half++) {
                const int row = warpM * 32 + mi * 16 + (lane >> 2) + half * 8;
                float v0 = tanhf(acc[mi][ni][half * 2] * u0 * u0);
                float v1 = tanhf(acc[mi][ni][half * 2 + 1] * u1 * u1);
                float2 f2; f2.x = v0; f2.y = v1;
                *(float2*)&sbuf[row * 132 + col] = f2;
            }
        }
    }
    __syncthreads();

    // ---- per-row softmax ----
    for (int r8 = 0; r8 < 16; r8++) {
        const int row = wid * 16 + r8;
        float4 v = *(const float4*)&sbuf[row * 132 + lane * 4];
        float mx = fmaxf(fmaxf(v.x, v.y), fmaxf(v.z, v.w));
#pragma unroll
        for (int o = 16; o > 0; o >>= 1)
            mx = fmaxf(mx, __shfl_xor_sync(0xffffffffu, mx, o));
        float e0 = expf(v.x - mx), e1 = expf(v.y - mx);
        float e2 = expf(v.z - mx), e3 = expf(v.w - mx);
        float sum1 = e0 + e1 + e2 + e3;
#pragma unroll
        for (int o = 16; o > 0; o >>= 1)
            sum1 += __shfl_xor_sync(0xffffffffu, sum1, o);
        const int col = lane * 4;
        float a0 = (e0 / sum1) * ums[col];
        float a1 = (e1 / sum1) * ums[col + 1];
        float a2 = (e2 / sum1) * ums[col + 2];
        float a3 = (e3 / sum1) * ums[col + 3];
        float sum2 = a0 + a1 + a2 + a3;
#pragma unroll
        for (int o = 16; o > 0; o >>= 1)
            sum2 += __shfl_xor_sync(0xffffffffu, sum2, o);
        float inv = 1.f / sum2;
        bf16 h0, l0, h1, l1, h2, l2, h3, l3;
        split_pair(a0 * inv, h0, l0);
        split_pair(a1 * inv, h1, l1);
        split_pair(a2 * inv, h2, l2);
        split_pair(a3 * inv, h3, l3);
        const size_t o0 = (size_t)(bz * NL + m0 + row) * NL + col;
        *(__nv_bfloat162*)&Sh[o0]     = __nv_bfloat162(h0, h1);
        *(__nv_bfloat162*)&Sh[o0 + 2] = __nv_bfloat162(h2, h3);
        *(__nv_bfloat162*)&Sl[o0]     = __nv_bfloat162(l0, l1);
        *(__nv_bfloat162*)&Sl[o0 + 2] = __nv_bfloat162(l2, l3);
    }
}

// ============================================================
// conversion kernels
// ============================================================
__global__ void cvtx_kernel(const float* __restrict__ x,
                            bf16* __restrict__ eh, bf16* __restrict__ el)
{
    int i = blockIdx.x * 256 + threadIdx.x;     // 8192*512
    bf16 h, l; split_pair(x[i], h, l);
    int row = i >> 9, c = i & 511;
    size_t eo = (size_t)row * NDm + c;
    eh[eo] = h; el[eo] = l;
}

// batched transpose+split: root, w_root/w_nbr (stacked), Wm, Wl
__global__ void tcvt_all_kernel(
    const float* __restrict__ root, bf16* __restrict__ rTh, bf16* __restrict__ rTl,
    const float* __restrict__ wr, const float* __restrict__ wn,
    bf16* __restrict__ wcTh, bf16* __restrict__ wcTl,
    const float* __restrict__ Wm, bf16* __restrict__ WmTh, bf16* __restrict__ WmTl,
    const float* __restrict__ Wl, bf16* __restrict__ WlTh, bf16* __restrict__ WlTl)
{
    int i = blockIdx.x * 256 + threadIdx.x;
    if (i < 32768) {
        int rr = i / 64, cc = i % 64;
        bf16 h, l; split_pair(root[i], h, l);
        rTh[(size_t)cc * 512 + rr] = h; rTl[(size_t)cc * 512 + rr] = l;
    } else if (i < 36864) {
        int j = i - 32768, rr = j / 64, cc = j % 64;
        bf16 h, l; split_pair(wr[j], h, l);
        wcTh[cc * 128 + rr] = h; wcTl[cc * 128 + rr] = l;
    } else if (i < 40960) {
        int j = i - 36864, rr = j / 64, cc = j % 64;
        bf16 h, l; split_pair(wn[j], h, l);
        wcTh[cc * 128 + 64 + rr] = h; wcTl[cc * 128 + 64 + rr] = l;
    } else if (i < 372736) {
        int j = i - 40960, rr = j / 576, cc = j % 576;
        bf16 h, l; split_pair(Wm[j], h, l);
        WmTh[(size_t)cc * 576 + rr] = h; WmTl[(size_t)cc * 576 + rr] = l;
    } else if (i < 409600) {
        int j = i - 372736, rr = j / 64, cc = j % 64;
        bf16 h, l; split_pair(Wl[j], h, l);
        WlTh[(size_t)cc * 576 + rr] = h; WlTl[(size_t)cc * 576 + rr] = l;
    }
}

// WtT pairs: WtT[n=r*64+h][k] = sum_b comp[r][b]*basis[b][k][h]   (R9 version)
__global__ void wt_kernel(const float* __restrict__ comp,
                          const float* __restrict__ basis,
                          bf16* __restrict__ Wh, bf16* __restrict__ Wl)
{
    int idx = blockIdx.x * 256 + threadIdx.x;   // 524288
    int h = idx & 63, rr = (idx >> 6) & 15, k = idx >> 10;
    float acc = 0.f;
#pragma unroll
    for (int b = 0; b < NBase; b++)
        acc = fmaf(comp[rr * NBase + b], basis[((size_t)b * NF + k) * NH + h], acc);
    bf16 hh, ll; split_pair(acc, hh, ll);
    size_t o = (size_t)(rr * 64 + h) * 512 + k;
    Wh[o] = hh; Wl[o] = ll;
}

// ---- CSR build ----
__global__ void hist_kernel(const int* __restrict__ ei, int* __restrict__ cnt)
{
    int i = blockIdx.x * 256 + threadIdx.x;
    if (i < NE) atomicAdd(&cnt[ei[NE + i]], 1);
}
__global__ void __launch_bounds__(1024)
scan_kernel(const int* __restrict__ cnt, int* __restrict__ off, int* __restrict__ cur)
{
    __shared__ int wsum[32];
    int t = threadIdx.x;
    int c[8], pre[8], p = 0;
#pragma unroll
    for (int j = 0; j < 8; j++) { c[j] = cnt[t * 8 + j]; pre[j] = p; p += c[j]; }
    const int tot = p;
    const int lane = t & 31, w = t >> 5;
    int sc = tot;
#pragma unroll
    for (int o = 1; o < 32; o <<= 1) {
        int v = __shfl_up_sync(0xffffffffu, sc, o);
        if (lane >= o) sc += v;
    }
    if (lane == 31) wsum[w] = sc;
    __syncthreads();
    if (w == 0) {
        int v = wsum[lane];
#pragma unroll
        for (int o = 1; o < 32; o <<= 1) {
            int x = __shfl_up_sync(0xffffffffu, v, o);
            if (lane >= o) v += x;
        }
        wsum[lane] = v;
    }
    __syncthreads();
    const int base = (w ? wsum[w - 1] : 0) + (sc - tot);
#pragma unroll
    for (int j = 0; j < 8; j++) {
        off[t * 8 + j + 1] = base + pre[j] + c[j];
        cur[t * 8 + j] = base + pre[j];
    }
    if (t == 0) off[0] = 0;
}
__global__ void fill_kernel(const int* __restrict__ ei, const int* __restrict__ et,
                            int* __restrict__ cur, int* __restrict__ eidx)
{
    int i = blockIdx.x * 256 + threadIdx.x;
    if (i >= NE) return;
    int dst = ei[NE + i];
    int pos = atomicAdd(&cur[dst], 1);
    eidx[pos] = ei[i] * 16 + et[i];
}

// ---- CSR gathers ----
__global__ void __launch_bounds__(64)
rgcn_gather(const int* __restrict__ off, const int* __restrict__ eidx,
            const float* __restrict__ xw, float* __restrict__ agg)
{
    const int n = blockIdx.x, h = threadIdx.x;
    const int beg = off[n], end = off[n + 1];
    float acc = 0.f;
    int e = beg;
    for (; e + 4 <= end; e += 4) {
        int p0 = eidx[e], p1 = eidx[e + 1], p2 = eidx[e + 2], p3 = eidx[e + 3];
        acc += xw[(size_t)(p0 >> 4) * 1024 + (p0 & 15) * 64 + h]
             + xw[(size_t)(p1 >> 4) * 1024 + (p1 & 15) * 64 + h]
             + xw[(size_t)(p2 >> 4) * 1024 + (p2 & 15) * 64 + h]
             + xw[(size_t)(p3 >> 4) * 1024 + (p3 & 15) * 64 + h];
    }
    for (; e < end; e++) {
        int p = eidx[e];
        acc += xw[(size_t)(p >> 4) * 1024 + (p & 15) * 64 + h];
    }
    agg[n * NH + h] = acc / fmaxf((float)(end - beg), 1.f);
}

// gather sum of h1 (packed pairs) -> a2 pair cols [64,128)
__global__ void __launch_bounds__(64)
gc_gather(const int* __restrict__ off, const int* __restrict__ eidx,
          const u32* __restrict__ h1p, bf16* __restrict__ a2h, bf16* __restrict__ a2l)
{
    const int n = blockIdx.x, h = threadIdx.x;
    const int beg = off[n], end = off[n + 1];
    float acc = 0.f;
    int e = beg;
    for (; e + 4 <= end; e += 4) {
        u32 q0 = h1p[(eidx[e] >> 4) * 64 + h];
        u32 q1 = h1p[(eidx[e + 1] >> 4) * 64 + h];
        u32 q2 = h1p[(eidx[e + 2] >> 4) * 64 + h];
        u32 q3 = h1p[(eidx[e + 3] >> 4) * 64 + h];
        __nv_bfloat162 t0 = *(__nv_bfloat162*)&q0, t1 = *(__nv_bfloat162*)&q1;
        __nv_bfloat162 t2 = *(__nv_bfloat162*)&q2, t3 = *(__nv_bfloat162*)&q3;
        acc += __bfloat162float(t0.x) + __bfloat162float(t0.y)
             + __bfloat162float(t1.x) + __bfloat162float(t1.y)
             + __bfloat162float(t2.x) + __bfloat162float(t2.y)
             + __bfloat162float(t3.x) + __bfloat162float(t3.y);
    }
    for (; e < end; e++) {
        u32 q = h1p[(eidx[e] >> 4) * 64 + h];
        __nv_bfloat162 t = *(__nv_bfloat162*)&q;
        acc += __bfloat162float(t.x) + __bfloat162float(t.y);
    }
    bf16 hh, ll; split_pair(acc, hh, ll);
    a2h[n * 128 + 64 + h] = hh;
    a2l[n * 128 + 64 + h] = ll;
}

// ============================================================
extern "C" void kernel_launch(void* const* d_in, const int* in_sizes, int n_in,
                              void* d_out, int out_size)
{
    const float* x      = (const float*)d_in[0];
    const int*   ei     = (const int*)d_in[1];
    const int*   et     = (const int*)d_in[3];
    const float* umask  = (const float*)d_in[5];
    const float* basis  = (const float*)d_in[8];
    const float* comp   = (const float*)d_in[9];
    const float* root   = (const float*)d_in[10];
    const float* bias1  = (const float*)d_in[11];
    const float* w_nbr  = (const float*)d_in[12];
    const float* w_root = (const float*)d_in[13];
    const float* bias2  = (const float*)d_in[14];
    const float* Wm     = (const float*)d_in[15];
    const float* bm     = (const float*)d_in[16];
    const float* Wl     = (const float*)d_in[17];
    const float* bl     = (const float*)d_in[18];
    const float* Ws     = (const float*)d_in[19];
    const float* bs     = (const float*)d_in[20];
    float* out = (float*)d_out;

#define SYM(T, v, s) T* v; cudaGetSymbolAddress((void**)&v, s)
    SYM(bf16, WtTh, g_WtTh); SYM(bf16, WtTl, g_WtTl);
    SYM(bf16, rootTh, g_rootTh); SYM(bf16, rootTl, g_rootTl);
    SYM(bf16, wcatTh, g_wcatTh); SYM(bf16, wcatTl, g_wcatTl);
    SYM(bf16, WmTh, g_WmTh); SYM(bf16, WmTl, g_WmTl);
    SYM(bf16, WlTh, g_WlTh); SYM(bf16, WlTl, g_WlTl);
    SYM(bf16, emoh, g_emoh); SYM(bf16, emol, g_emol);
    SYM(bf16, a2h, g_a2h); SYM(bf16, a2l, g_a2l);
    SYM(u32, h1p, g_h1p);
    SYM(bf16, Qh, g_Qh); SYM(bf16, Ql, g_Ql);
    SYM(bf16, Sh, g_Sh); SYM(bf16, Sl, g_Sl);
    SYM(bf16, eWTh, g_eWTh); SYM(bf16, eWTl, g_eWTl);
    SYM(float, xw, g_xw); SYM(float, agg, g_agg);
    SYM(int, cnt, g_cnt); SYM(int, off, g_off); SYM(int, cur, g_cur);
    SYM(int, eidx, g_eidx);
#undef SYM

    const int SZ_128_64 = 512 + 2 * 2 * (128 + 64) * 128;   // 98816
    const int SZ_64_128 = 512 + 2 * 2 * (64 + 128) * 128;   // 98816
    const int SZ_64_64  = 512 + 2 * 2 * (64 + 64) * 128;    // 66048

#define SETSM(KERN, SZ) cudaFuncSetAttribute((const void*)(KERN), \
    cudaFuncAttributeMaxDynamicSharedMemorySize, SZ)
    SETSM((mmt<128, 64, 128, false, false, false, false, false, false>), SZ_128_64);
    SETSM((mmt<64, 64, 128, true,  true,  false, true,  false, false>),  SZ_64_64);
    SETSM((mmt<64, 64, 128, false, true,  false, true,  false, false>),  SZ_64_64);
    SETSM((mmt<128, 64, 128, false, true,  false, true,  false, false>), SZ_128_64);
    SETSM((mmt<64, 64, 128, false, false, false, true,  true,  false>),  SZ_64_64);
    SETSM((mmt<128, 64, 128, false, true,  true,  false, false, true>),  SZ_128_64);
    SETSM(scores_softmax, SZ_64_128);
#undef SETSM

    // ---- operand prep (xw GEMM stays the 4th launch for ncu) ----
    cvtx_kernel<<<(NND * NF) / 256, 256>>>(x, emoh, emol);
    wt_kernel<<<(NF * NRel * NH) / 256, 256>>>(comp, basis, WtTh, WtTl);
    tcvt_all_kernel<<<409600 / 256, 256>>>(
        root, rootTh, rootTl, w_root, w_nbr, wcatTh, wcatTl,
        Wm, WmTh, WmTl, Wl, WlTh, WlTl);

    // xw = x @ Wt  (A = emo cols [0,512), lda=576)
    mmt<128, 64, 128, false, false, false, false, false, false>
        <<<dim3(16, 64, 1), 128, SZ_128_64>>>(
        emoh, emol, NDm, 0, WtTh, WtTl, 512, 0,
        xw, nullptr, nullptr, nullptr, 1024, 0, nullptr, 0, nullptr,
        nullptr, nullptr, 512);

    // ---- CSR build ----
    cudaMemsetAsync(cnt, 0, NND * sizeof(int));
    hist_kernel<<<NE / 256, 256>>>(ei, cnt);
    scan_kernel<<<1, 1024>>>(cnt, off, cur);
    fill_kernel<<<NE / 256, 256>>>(ei, et, cur, eidx);

    rgcn_gather<<<NND, 64>>>(off, eidx, xw, agg);

    // h1 = agg + x@root + bias1 -> a2 cols [0,64) pairs + packed h1p
    mmt<64, 64, 128, true, true, false, true, false, false>
        <<<dim3(1, 128, 1), 128, SZ_64_64>>>(
        emoh, emol, NDm, 0, rootTh, rootTl, 512, 0,
        nullptr, a2h, a2l, h1p, 128, 0, agg, 64, bias1,
        nullptr, nullptr, 512);

    // gather(h1) -> a2 cols [64,128) pairs
    gc_gather<<<NND, 64>>>(off, eidx, h1p, a2h, a2l);

    // h2 = [h1 | aggH1] @ [w_root; w_nbr] + bias2 -> emo cols [512,576)
    mmt<64, 64, 128, false, true, false, true, false, false>
        <<<dim3(1, 128, 1), 128, SZ_64_64>>>(
        a2h, a2l, 128, 0, wcatTh, wcatTl, 128, 0,
        nullptr, emoh + NF, emol + NF, nullptr, NDm, 0, nullptr, 0, bias2,
        nullptr, nullptr, 128);

    // Q = emo @ Wm + bm -> pairs
    mmt<128, 64, 128, false, true, false, true, false, false>
        <<<dim3(9, 64, 1), 128, SZ_128_64>>>(
        emoh, emol, NDm, 0, WmTh, WmTl, NDm, 0,
        nullptr, Qh, Ql, nullptr, NDm, 0, nullptr, 0, bm,
        nullptr, nullptr, NDm);

    // eW = emo @ Wl -> per-conversation TRANSPOSED pairs eWT[b][n][q]
    mmt<64, 64, 128, false, false, false, true, true, false>
        <<<dim3(1, 128, 1), 128, SZ_64_64>>>(
        emoh, emol, NDm, 0, WlTh, WlTl, NDm, 0,
        nullptr, eWTh, eWTl, nullptr, 0, 0, nullptr, 0, nullptr,
        nullptr, nullptr, NDm);

    // fused scores + softmax -> bf16 pairs
    scores_softmax<<<dim3(1, 2, NBc), 128, SZ_64_128>>>(
        Qh, Ql, emoh, emol, umask, Sh, Sl);

    // hidden = relu(alpha @ eWT + bl) -> FUSED head: log_softmax logits to out
    mmt<128, 64, 128, false, true, true, false, false, true>
        <<<dim3(1, 1, NBc), 128, SZ_128_64>>>(
        Sh, Sl, NL, (long long)NL * NL, eWTh, eWTl, NL, (long long)NH * NL,
        out, nullptr, nullptr, nullptr, NH, 0, nullptr, 0, bl,
        Ws, bs, NL);

    (void)in_sizes; (void)n_in; (void)out_size;
}

// round 13
// speedup vs baseline: 1.1122x; 1.0026x over previous
#include <cuda_runtime.h>
#include <cuda_bf16.h>
#include <math.h>
#include <cstdint>

// ---- problem constants ----
#define NND 8192
#define NF  512
#define NH  64
#define NRel 16
#define NBase 30
#define NE  524288
#define NBc 64
#define NL  128
#define NDm 576
#define NC  7
#define KC  64          // K chunk (bf16) per pipeline stage; 128B rows

typedef __nv_bfloat16 bf16;
typedef unsigned int u32;

// ---- static device scratch ----
__device__ __align__(16) bf16 g_WtTh[1024 * 512];
__device__ __align__(16) bf16 g_WtTl[1024 * 512];
__device__ __align__(16) bf16 g_rootTh[64 * 512];
__device__ __align__(16) bf16 g_rootTl[64 * 512];
__device__ __align__(16) bf16 g_wcatTh[64 * 128];
__device__ __align__(16) bf16 g_wcatTl[64 * 128];
__device__ __align__(16) bf16 g_WmTh[576 * 576];
__device__ __align__(16) bf16 g_WmTl[576 * 576];
__device__ __align__(16) bf16 g_WlTh[64 * 576];
__device__ __align__(16) bf16 g_WlTl[64 * 576];
__device__ __align__(16) bf16 g_emoh[(size_t)NND * NDm];
__device__ __align__(16) bf16 g_emol[(size_t)NND * NDm];
__device__ __align__(16) bf16 g_a2h[NND * 128];
__device__ __align__(16) bf16 g_a2l[NND * 128];
__device__ __align__(16) u32  g_h1p[NND * NH];
__device__ __align__(16) bf16 g_Qh[(size_t)NND * NDm];
__device__ __align__(16) bf16 g_Ql[(size_t)NND * NDm];
__device__ __align__(16) bf16 g_Sh[NND * NL];
__device__ __align__(16) bf16 g_Sl[NND * NL];
__device__ __align__(16) bf16 g_eWTh[NBc * NH * NL];
__device__ __align__(16) bf16 g_eWTl[NBc * NH * NL];

__device__ __align__(16) float g_xw[(size_t)NND * NRel * NH];
__device__ __align__(16) float g_agg[NND * NH];
// CSR
__device__ int g_cnt[NND];
__device__ int g_off[NND + 1];
__device__ int g_cur[NND];
__device__ int g_eidx[NE];

__device__ __forceinline__ void split_pair(float v, bf16& h, bf16& l) {
    h = __float2bfloat16(v);
    l = __float2bfloat16(v - __bfloat162float(h));
}

__device__ __forceinline__ u32 smem_u32(const void* p) {
    u32 a;
    asm("{ .reg .u64 t; cvta.to.shared.u64 t, %1; cvt.u32.u64 %0, t; }"
        : "=r"(a) : "l"(p));
    return a;
}

__device__ __forceinline__ void mma16816(float* d, const u32* a, const u32* b) {
    asm volatile(
        "mma.sync.aligned.m16n8k16.row.col.f32.bf16.bf16.f32 "
        "{%0,%1,%2,%3}, {%4,%5,%6,%7}, {%8,%9}, {%0,%1,%2,%3};"
        : "+f"(d[0]), "+f"(d[1]), "+f"(d[2]), "+f"(d[3])
        : "r"(a[0]), "r"(a[1]), "r"(a[2]), "r"(a[3]), "r"(b[0]), "r"(b[1]));
}

#define LDSM4(r, addr) \
    asm volatile("ldmatrix.sync.aligned.m8n8.x4.shared.b16 {%0,%1,%2,%3}, [%4];" \
        : "=r"((r)[0]), "=r"((r)[1]), "=r"((r)[2]), "=r"((r)[3]) : "r"(addr))

#define CPA(d, s) \
    asm volatile("cp.async.cg.shared.global [%0], [%1], 16;" :: "r"(d), "l"(s) : "memory")
#define CPC() asm volatile("cp.async.commit_group;" ::: "memory")
#define CPW0() asm volatile("cp.async.wait_group 0;" ::: "memory")

// ============================================================
// Pipelined warp-MMA 3xBF16 GEMM: C[M,N] = A @ B^T
// ============================================================
template <int BM, int NT, int THREADS,
          bool ADD_D, bool BIAS, bool RELU, bool OUT_PAIR, bool OUT_T, bool HEAD>
__global__ void __launch_bounds__(THREADS, 2)
mmt(const bf16* __restrict__ Ah, const bf16* __restrict__ Al, int lda, long long sA,
    const bf16* __restrict__ Bh, const bf16* __restrict__ Bl, int ldb, long long sB,
    float* __restrict__ C, bf16* __restrict__ Ch, bf16* __restrict__ Cl,
    u32* __restrict__ Cp,
    int ldc, long long sC,
    const float* __restrict__ D, int ldd,
    const float* __restrict__ bias,
    const float* __restrict__ Ws, const float* __restrict__ bsv,
    int K)
{
    constexpr int WARPS = THREADS / 32;
    constexpr int WN = NT / 64;
    constexpr int WMC = WARPS / WN;
    constexpr int WM = BM / WMC;
    constexpr int MI = WM / 16;
    constexpr int STAGE_ROWS = 2 * (BM + NT);
    constexpr int STAGE_B = STAGE_ROWS * 128;
    constexpr int CHUNKS = STAGE_ROWS * 8 / THREADS;

    extern __shared__ char smem[];
    const u32 sb0 = smem_u32(smem) + 512;

    const int tid = threadIdx.x;
    const int wid = tid >> 5, lane = tid & 31;
    const int warpM = wid % WMC, warpN = wid / WMC;
    const int bz = blockIdx.z;
    const int m0 = blockIdx.y * BM;
    const int n0 = blockIdx.x * NT;

    const char* pAh = (const char*)(Ah + sA * bz + (size_t)m0 * lda);
    const char* pAl = (const char*)(Al + sA * bz + (size_t)m0 * lda);
    const char* pBh = (const char*)(Bh + sB * bz + (size_t)n0 * ldb);
    const char* pBl = (const char*)(Bl + sB * bz + (size_t)n0 * ldb);
    const size_t ldab = (size_t)lda * 2;
    const size_t ldbb = (size_t)ldb * 2;

    float acc[MI][8][4];
#pragma unroll
    for (int i = 0; i < MI; i++)
#pragma unroll
        for (int j = 0; j < 8; j++)
#pragma unroll
            for (int q = 0; q < 4; q++) acc[i][j][q] = 0.f;

    const int S = K / KC;

    auto load_stage = [&](int s) {
        const size_t kcb = (size_t)s * KC * 2;
        const u32 dst0 = sb0 + (u32)(s & 1) * STAGE_B;
#pragma unroll
        for (int f = 0; f < CHUNKS; f++) {
            int idx = tid + f * THREADS;
            int row = idx >> 3;
            u32 cb = (u32)(idx & 7) << 4;
            u32 sw = cb ^ (((u32)(row & 7)) << 4);
            const char* src;
            if (row < BM)               src = pAh + (size_t)row * ldab + kcb + cb;
            else if (row < 2 * BM)      src = pAl + (size_t)(row - BM) * ldab + kcb + cb;
            else if (row < 2 * BM + NT) src = pBh + (size_t)(row - 2 * BM) * ldbb + kcb + cb;
            else                        src = pBl + (size_t)(row - 2 * BM - NT) * ldbb + kcb + cb;
            CPA(dst0 + (u32)row * 128 + sw, src);
        }
    };

    load_stage(0);
    CPC();

    const u32 xorv = ((u32)(lane & 7)) << 4;
    const u32 aRow = (u32)(warpM * WM + (lane & 15));
    const u32 aCol0 = ((u32)(lane >> 4) & 1) * 16;
    const u32 bRow = (u32)(warpN * 64 + ((lane & 7) | ((lane & 16) >> 1)));
    const u32 bCol0 = ((u32)(lane >> 3) & 1) * 16;

    for (int s = 0; s < S; s++) {
        CPW0();
        __syncthreads();
        if (s + 1 < S) { load_stage(s + 1); CPC(); }

        const u32 base = sb0 + (u32)(s & 1) * STAGE_B;
        const u32 aH = base + aRow * 128;
        const u32 aL = aH + (u32)BM * 128;
        const u32 bH = base + (u32)(2 * BM) * 128 + bRow * 128;
        const u32 bL = bH + (u32)NT * 128;

#pragma unroll
        for (int ks = 0; ks < KC / 16; ks++) {
            const u32 kb = (u32)ks * 32;
            const u32 acol = (aCol0 + kb) ^ xorv;
            const u32 bcol = (bCol0 + kb) ^ xorv;
            u32 ah[MI][4], al[MI][4];
#pragma unroll
            for (int mi = 0; mi < MI; mi++) {
                LDSM4(ah[mi], aH + (u32)mi * (16 * 128) + acol);
                LDSM4(al[mi], aL + (u32)mi * (16 * 128) + acol);
            }
#pragma unroll
            for (int nt = 0; nt < 4; nt++) {
                u32 bh[4], bl[4];
                LDSM4(bh, bH + (u32)nt * (16 * 128) + bcol);
                LDSM4(bl, bL + (u32)nt * (16 * 128) + bcol);
#pragma unroll
                for (int mi = 0; mi < MI; mi++)
#pragma unroll
                    for (int half = 0; half < 2; half++) {
                        float* a4 = acc[mi][nt * 2 + half];
                        mma16816(a4, ah[mi], &bh[half * 2]);
                        mma16816(a4, ah[mi], &bl[half * 2]);
                        mma16816(a4, al[mi], &bh[half * 2]);
                    }
            }
        }
    }

    if (HEAD) {
        __syncthreads();
        float* wss = (float*)smem;
        for (int i = tid; i < NH * NC + NC; i += THREADS)
            wss[i] = (i < NH * NC) ? Ws[i] : bsv[i - NH * NC];
        __syncthreads();
        const int tg = lane & 3;
#pragma unroll
        for (int mi = 0; mi < MI; mi++) {
#pragma unroll
            for (int half = 0; half < 2; half++) {
                const int m = m0 + warpM * WM + mi * 16 + (lane >> 2) + half * 8;
                float lg[NC];
#pragma unroll
                for (int c = 0; c < NC; c++) lg[c] = 0.f;
#pragma unroll
                for (int ni = 0; ni < 8; ni++) {
                    const int n = ni * 8 + tg * 2;
                    float v0 = acc[mi][ni][half * 2];
                    float v1 = acc[mi][ni][half * 2 + 1];
                    if (BIAS) { v0 += bias[n]; v1 += bias[n + 1]; }
                    if (RELU) { v0 = fmaxf(v0, 0.f); v1 = fmaxf(v1, 0.f); }
#pragma unroll
                    for (int c = 0; c < NC; c++)
                        lg[c] = fmaf(v0, wss[n * NC + c],
                                     fmaf(v1, wss[(n + 1) * NC + c], lg[c]));
                }
#pragma unroll
                for (int o = 1; o < 4; o <<= 1)
#pragma unroll
                    for (int c = 0; c < NC; c++)
                        lg[c] += __shfl_xor_sync(0xffffffffu, lg[c], o);
                if (tg == 0) {
#pragma unroll
                    for (int c = 0; c < NC; c++) lg[c] += wss[NH * NC + c];
                    float mx = lg[0];
#pragma unroll
                    for (int c = 1; c < NC; c++) mx = fmaxf(mx, lg[c]);
                    float ssum = 0.f;
#pragma unroll
                    for (int c = 0; c < NC; c++) ssum += expf(lg[c] - mx);
                    float lse = mx + logf(ssum);
                    const size_t o0 = (size_t)(bz * NL + m) * NC;
#pragma unroll
                    for (int c = 0; c < NC; c++) C[o0 + c] = lg[c] - lse;
                }
            }
        }
        return;
    }

    // ---- standard epilogue ----
#pragma unroll
    for (int mi = 0; mi < MI; mi++) {
        const int rm = m0 + warpM * WM + mi * 16 + (lane >> 2);
#pragma unroll
        for (int ni = 0; ni < 8; ni++) {
            const int n = n0 + warpN * 64 + ni * 8 + (lane & 3) * 2;
#pragma unroll
            for (int half = 0; half < 2; half++) {
                const int m = rm + half * 8;
                float v0 = acc[mi][ni][half * 2];
                float v1 = acc[mi][ni][half * 2 + 1];
                if (BIAS) { v0 += bias[n]; v1 += bias[n + 1]; }
                if (ADD_D) {
                    v0 += D[(size_t)m * ldd + n];
                    v1 += D[(size_t)m * ldd + n + 1];
                }
                if (RELU) { v0 = fmaxf(v0, 0.f); v1 = fmaxf(v1, 0.f); }
                if (OUT_PAIR) {
                    bf16 h0, l0, h1c, l1c;
                    split_pair(v0, h0, l0);
                    split_pair(v1, h1c, l1c);
                    if (OUT_T) {
                        size_t o = ((size_t)(m >> 7) * 64 + n) * 128 + (m & 127);
                        Ch[o] = h0; Ch[o + 128] = h1c;
                        Cl[o] = l0; Cl[o + 128] = l1c;
                    } else {
                        const size_t o = (size_t)sC * bz + (size_t)m * ldc + n;
                        *(__nv_bfloat162*)&Ch[o] = __nv_bfloat162(h0, h1c);
                        *(__nv_bfloat162*)&Cl[o] = __nv_bfloat162(l0, l1c);
                        if (Cp) {
                            __nv_bfloat162 p0(h0, l0), p1(h1c, l1c);
                            uint2 u; u.x = *(u32*)&p0; u.y = *(u32*)&p1;
                            *(uint2*)&Cp[(size_t)m * 64 + n] = u;
                        }
                    }
                } else {
                    float2 f2; f2.x = v0; f2.y = v1;
                    *(float2*)&C[(size_t)sC * bz + (size_t)m * ldc + n] = f2;
                }
            }
        }
    }
}

// ============================================================
// Fused scores kernel: S = tanh((Q.M)*u^2) -> softmax -> *u -> renorm
// ============================================================
__global__ void __launch_bounds__(128, 2)
scores_softmax(const bf16* __restrict__ Qh, const bf16* __restrict__ Ql,
               const bf16* __restrict__ Mh, const bf16* __restrict__ Ml,
               const float* __restrict__ um,
               bf16* __restrict__ Sh, bf16* __restrict__ Sl)
{
    constexpr int BM = 64, NT = 128, THREADS = 128;
    constexpr int STAGE_ROWS = 2 * (BM + NT);
    constexpr int STAGE_B = STAGE_ROWS * 128;
    constexpr int CHUNKS = STAGE_ROWS * 8 / THREADS;

    extern __shared__ char smem[];
    float* ums = (float*)smem;
    float* sbuf = (float*)(smem + 512);
    const u32 sb0 = smem_u32(smem) + 512;

    const int tid = threadIdx.x;
    const int wid = tid >> 5, lane = tid & 31;
    const int warpM = wid & 1, warpN = wid >> 1;
    const int bz = blockIdx.z;
    const int m0 = blockIdx.y * BM;

    const char* pAh = (const char*)(Qh + (size_t)bz * NL * NDm + (size_t)m0 * NDm);
    const char* pAl = (const char*)(Ql + (size_t)bz * NL * NDm + (size_t)m0 * NDm);
    const char* pBh = (const char*)(Mh + (size_t)bz * NL * NDm);
    const char* pBl = (const char*)(Ml + (size_t)bz * NL * NDm);
    const size_t ldab = (size_t)NDm * 2;

    if (tid < NT) ums[tid] = um[bz * NL + tid];

    float acc[2][8][4];
#pragma unroll
    for (int i = 0; i < 2; i++)
#pragma unroll
        for (int j = 0; j < 8; j++)
#pragma unroll
            for (int q = 0; q < 4; q++) acc[i][j][q] = 0.f;

    const int S = NDm / KC;

    auto load_stage = [&](int s) {
        const size_t kcb = (size_t)s * KC * 2;
        const u32 dst0 = sb0 + (u32)(s & 1) * STAGE_B;
#pragma unroll
        for (int f = 0; f < CHUNKS; f++) {
            int idx = tid + f * THREADS;
            int row = idx >> 3;
            u32 cb = (u32)(idx & 7) << 4;
            u32 sw = cb ^ (((u32)(row & 7)) << 4);
            const char* src;
            if (row < BM)               src = pAh + (size_t)row * ldab + kcb + cb;
            else if (row < 2 * BM)      src = pAl + (size_t)(row - BM) * ldab + kcb + cb;
            else if (row < 2 * BM + NT) src = pBh + (size_t)(row - 2 * BM) * ldab + kcb + cb;
            else                        src = pBl + (size_t)(row - 2 * BM - NT) * ldab + kcb + cb;
            CPA(dst0 + (u32)row * 128 + sw, src);
        }
    };

    load_stage(0);
    CPC();

    const u32 xorv = ((u32)(lane & 7)) << 4;
    const u32 aRow = (u32)(warpM * 32 + (lane & 15));
    const u32 aCol0 = ((u32)(lane >> 4) & 1) * 16;
    const u32 bRow = (u32)(warpN * 64 + ((lane & 7) | ((lane & 16) >> 1)));
    const u32 bCol0 = ((u32)(lane >> 3) & 1) * 16;

    for (int s = 0; s < S; s++) {
        CPW0();
        __syncthreads();
        if (s + 1 < S) { load_stage(s + 1); CPC(); }

        const u32 base = sb0 + (u32)(s & 1) * STAGE_B;
        const u32 aH = base + aRow * 128;
        const u32 aL = aH + (u32)BM * 128;
        const u32 bH = base + (u32)(2 * BM) * 128 + bRow * 128;
        const u32 bL = bH + (u32)NT * 128;

#pragma unroll
        for (int ks = 0; ks < KC / 16; ks++) {
            const u32 kb = (u32)ks * 32;
            const u32 acol = (aCol0 + kb) ^ xorv;
            const u32 bcol = (bCol0 + kb) ^ xorv;
            u32 ah[2][4], al[2][4];
#pragma unroll
            for (int mi = 0; mi < 2; mi++) {
                LDSM4(ah[mi], aH + (u32)mi * (16 * 128) + acol);
                LDSM4(al[mi], aL + (u32)mi * (16 * 128) + acol);
            }
#pragma unroll
            for (int nt = 0; nt < 4; nt++) {
                u32 bh[4], bl[4];
                LDSM4(bh, bH + (u32)nt * (16 * 128) + bcol);
                LDSM4(bl, bL + (u32)nt * (16 * 128) + bcol);
#pragma unroll
                for (int mi = 0; mi < 2; mi++)
#pragma unroll
                    for (int half = 0; half < 2; half++) {
                        float* a4 = acc[mi][nt * 2 + half];
                        mma16816(a4, ah[mi], &bh[half * 2]);
                        mma16816(a4, ah[mi], &bl[half * 2]);
                        mma16816(a4, al[mi], &bh[half * 2]);
                    }
            }
        }
    }
    __syncthreads();

#pragma unroll
    for (int mi = 0; mi < 2; mi++) {
#pragma unroll
        for (int ni = 0; ni < 8; ni++) {
            const int col = warpN * 64 + ni * 8 + (lane & 3) * 2;
            const float u0 = ums[col], u1 = ums[col + 1];
#pragma unroll
            for (int half = 0; half < 2; half++) {
                const int row = warpM * 32 + mi * 16 + (lane >> 2) + half * 8;
                float v0 = tanhf(acc[mi][ni][half * 2] * u0 * u0);
                float v1 = tanhf(acc[mi][ni][half * 2 + 1] * u1 * u1);
                float2 f2; f2.x = v0; f2.y = v1;
                *(float2*)&sbuf[row * 132 + col] = f2;
            }
        }
    }
    __syncthreads();

    for (int r8 = 0; r8 < 16; r8++) {
        const int row = wid * 16 + r8;
        float4 v = *(const float4*)&sbuf[row * 132 + lane * 4];
        float mx = fmaxf(fmaxf(v.x, v.y), fmaxf(v.z, v.w));
#pragma unroll
        for (int o = 16; o > 0; o >>= 1)
            mx = fmaxf(mx, __shfl_xor_sync(0xffffffffu, mx, o));
        float e0 = expf(v.x - mx), e1 = expf(v.y - mx);
        float e2 = expf(v.z - mx), e3 = expf(v.w - mx);
        float sum1 = e0 + e1 + e2 + e3;
#pragma unroll
        for (int o = 16; o > 0; o >>= 1)
            sum1 += __shfl_xor_sync(0xffffffffu, sum1, o);
        const int col = lane * 4;
        float a0 = (e0 / sum1) * ums[col];
        float a1 = (e1 / sum1) * ums[col + 1];
        float a2 = (e2 / sum1) * ums[col + 2];
        float a3 = (e3 / sum1) * ums[col + 3];
        float sum2 = a0 + a1 + a2 + a3;
#pragma unroll
        for (int o = 16; o > 0; o >>= 1)
            sum2 += __shfl_xor_sync(0xffffffffu, sum2, o);
        float inv = 1.f / sum2;
        bf16 h0, l0, h1, l1, h2, l2, h3, l3;
        split_pair(a0 * inv, h0, l0);
        split_pair(a1 * inv, h1, l1);
        split_pair(a2 * inv, h2, l2);
        split_pair(a3 * inv, h3, l3);
        const size_t o0 = (size_t)(bz * NL + m0 + row) * NL + col;
        *(__nv_bfloat162*)&Sh[o0]     = __nv_bfloat162(h0, h1);
        *(__nv_bfloat162*)&Sh[o0 + 2] = __nv_bfloat162(h2, h3);
        *(__nv_bfloat162*)&Sl[o0]     = __nv_bfloat162(l0, l1);
        *(__nv_bfloat162*)&Sl[o0 + 2] = __nv_bfloat162(l2, l3);
    }
}

// ============================================================
// merged prep kernel: cvtx + wt + tcvt in one launch
// region 0: [0, 4194304)      cvtx
// region 1: [4194304, 4718592) wt (524288)
// region 2: [4718592, 5128192) tcvt (409600)
// ============================================================
__global__ void prep_kernel(
    const float* __restrict__ x, bf16* __restrict__ eh, bf16* __restrict__ el,
    const float* __restrict__ comp, const float* __restrict__ basis,
    bf16* __restrict__ Wh, bf16* __restrict__ Wl,
    const float* __restrict__ root, bf16* __restrict__ rTh, bf16* __restrict__ rTl,
    const float* __restrict__ wr, const float* __restrict__ wn,
    bf16* __restrict__ wcTh, bf16* __restrict__ wcTl,
    const float* __restrict__ Wm, bf16* __restrict__ WmTh, bf16* __restrict__ WmTl,
    const float* __restrict__ Wl2, bf16* __restrict__ WlTh, bf16* __restrict__ WlTl)
{
    int i = blockIdx.x * 256 + threadIdx.x;
    if (i < 4194304) {
        // cvtx
        bf16 h, l; split_pair(x[i], h, l);
        int row = i >> 9, c = i & 511;
        size_t eo = (size_t)row * NDm + c;
        eh[eo] = h; el[eo] = l;
    } else if (i < 4718592) {
        // wt
        int idx = i - 4194304;
        int h = idx & 63, rr = (idx >> 6) & 15, k = idx >> 10;
        float acc = 0.f;
#pragma unroll
        for (int b = 0; b < NBase; b++)
            acc = fmaf(comp[rr * NBase + b], basis[((size_t)b * NF + k) * NH + h], acc);
        bf16 hh, ll; split_pair(acc, hh, ll);
        size_t o = (size_t)(rr * 64 + h) * 512 + k;
        Wh[o] = hh; Wl[o] = ll;
    } else {
        int j = i - 4718592;
        if (j < 32768) {
            int rr = j / 64, cc = j % 64;
            bf16 h, l; split_pair(root[j], h, l);
            rTh[(size_t)cc * 512 + rr] = h; rTl[(size_t)cc * 512 + rr] = l;
        } else if (j < 36864) {
            int q = j - 32768, rr = q / 64, cc = q % 64;
            bf16 h, l; split_pair(wr[q], h, l);
            wcTh[cc * 128 + rr] = h; wcTl[cc * 128 + rr] = l;
        } else if (j < 40960) {
            int q = j - 36864, rr = q / 64, cc = q % 64;
            bf16 h, l; split_pair(wn[q], h, l);
            wcTh[cc * 128 + 64 + rr] = h; wcTl[cc * 128 + 64 + rr] = l;
        } else if (j < 372736) {
            int q = j - 40960, rr = q / 576, cc = q % 576;
            bf16 h, l; split_pair(Wm[q], h, l);
            WmTh[(size_t)cc * 576 + rr] = h; WmTl[(size_t)cc * 576 + rr] = l;
        } else if (j < 409600) {
            int q = j - 372736, rr = q / 64, cc = q % 64;
            bf16 h, l; split_pair(Wl2[q], h, l);
            WlTh[(size_t)cc * 576 + rr] = h; WlTl[(size_t)cc * 576 + rr] = l;
        }
    }
}

// ---- CSR build ----
__global__ void hist_kernel(const int* __restrict__ ei, int* __restrict__ cnt)
{
    int i = blockIdx.x * 256 + threadIdx.x;
    if (i < NE) atomicAdd(&cnt[ei[NE + i]], 1);
}
__global__ void __launch_bounds__(1024)
scan_kernel(const int* __restrict__ cnt, int* __restrict__ off, int* __restrict__ cur)
{
    __shared__ int wsum[32];
    int t = threadIdx.x;
    int c[8], pre[8], p = 0;
#pragma unroll
    for (int j = 0; j < 8; j++) { c[j] = cnt[t * 8 + j]; pre[j] = p; p += c[j]; }
    const int tot = p;
    const int lane = t & 31, w = t >> 5;
    int sc = tot;
#pragma unroll
    for (int o = 1; o < 32; o <<= 1) {
        int v = __shfl_up_sync(0xffffffffu, sc, o);
        if (lane >= o) sc += v;
    }
    if (lane == 31) wsum[w] = sc;
    __syncthreads();
    if (w == 0) {
        int v = wsum[lane];
#pragma unroll
        for (int o = 1; o < 32; o <<= 1) {
            int x2 = __shfl_up_sync(0xffffffffu, v, o);
            if (lane >= o) v += x2;
        }
        wsum[lane] = v;
    }
    __syncthreads();
    const int base = (w ? wsum[w - 1] : 0) + (sc - tot);
#pragma unroll
    for (int j = 0; j < 8; j++) {
        off[t * 8 + j + 1] = base + pre[j] + c[j];
        cur[t * 8 + j] = base + pre[j];
    }
    if (t == 0) off[0] = 0;
}
__global__ void fill_kernel(const int* __restrict__ ei, const int* __restrict__ et,
                            int* __restrict__ cur, int* __restrict__ eidx)
{
    int i = blockIdx.x * 256 + threadIdx.x;
    if (i >= NE) return;
    int dst = ei[NE + i];
    int pos = atomicAdd(&cur[dst], 1);
    eidx[pos] = ei[i] * 16 + et[i];
}

// ---- CSR gathers (4 nodes per 256-thread block) ----
__global__ void __launch_bounds__(256)
rgcn_gather(const int* __restrict__ off, const int* __restrict__ eidx,
            const float* __restrict__ xw, float* __restrict__ agg)
{
    const int n = blockIdx.x * 4 + (threadIdx.x >> 6);
    const int h = threadIdx.x & 63;
    const int beg = off[n], end = off[n + 1];
    float acc = 0.f;
    int e = beg;
    for (; e + 4 <= end; e += 4) {
        int p0 = eidx[e], p1 = eidx[e + 1], p2 = eidx[e + 2], p3 = eidx[e + 3];
        acc += xw[(size_t)(p0 >> 4) * 1024 + (p0 & 15) * 64 + h]
             + xw[(size_t)(p1 >> 4) * 1024 + (p1 & 15) * 64 + h]
             + xw[(size_t)(p2 >> 4) * 1024 + (p2 & 15) * 64 + h]
             + xw[(size_t)(p3 >> 4) * 1024 + (p3 & 15) * 64 + h];
    }
    for (; e < end; e++) {
        int p = eidx[e];
        acc += xw[(size_t)(p >> 4) * 1024 + (p & 15) * 64 + h];
    }
    agg[n * NH + h] = acc / fmaxf((float)(end - beg), 1.f);
}

__global__ void __launch_bounds__(256)
gc_gather(const int* __restrict__ off, const int* __restrict__ eidx,
          const u32* __restrict__ h1p, bf16* __restrict__ a2h, bf16* __restrict__ a2l)
{
    const int n = blockIdx.x * 4 + (threadIdx.x >> 6);
    const int h = threadIdx.x & 63;
    const int beg = off[n], end = off[n + 1];
    float acc = 0.f;
    int e = beg;
    for (; e + 4 <= end; e += 4) {
        u32 q0 = h1p[(eidx[e] >> 4) * 64 + h];
        u32 q1 = h1p[(eidx[e + 1] >> 4) * 64 + h];
        u32 q2 = h1p[(eidx[e + 2] >> 4) * 64 + h];
        u32 q3 = h1p[(eidx[e + 3] >> 4) * 64 + h];
        __nv_bfloat162 t0 = *(__nv_bfloat162*)&q0, t1 = *(__nv_bfloat162*)&q1;
        __nv_bfloat162 t2 = *(__nv_bfloat162*)&q2, t3 = *(__nv_bfloat162*)&q3;
        acc += __bfloat162float(t0.x) + __bfloat162float(t0.y)
             + __bfloat162float(t1.x) + __bfloat162float(t1.y)
             + __bfloat162float(t2.x) + __bfloat162float(t2.y)
             + __bfloat162float(t3.x) + __bfloat162float(t3.y);
    }
    for (; e < end; e++) {
        u32 q = h1p[(eidx[e] >> 4) * 64 + h];
        __nv_bfloat162 t = *(__nv_bfloat162*)&q;
        acc += __bfloat162float(t.x) + __bfloat162float(t.y);
    }
    bf16 hh, ll; split_pair(acc, hh, ll);
    a2h[n * 128 + 64 + h] = hh;
    a2l[n * 128 + 64 + h] = ll;
}

// ============================================================
extern "C" void kernel_launch(void* const* d_in, const int* in_sizes, int n_in,
                              void* d_out, int out_size)
{
    const float* x      = (const float*)d_in[0];
    const int*   ei     = (const int*)d_in[1];
    const int*   et     = (const int*)d_in[3];
    const float* umask  = (const float*)d_in[5];
    const float* basis  = (const float*)d_in[8];
    const float* comp   = (const float*)d_in[9];
    const float* root   = (const float*)d_in[10];
    const float* bias1  = (const float*)d_in[11];
    const float* w_nbr  = (const float*)d_in[12];
    const float* w_root = (const float*)d_in[13];
    const float* bias2  = (const float*)d_in[14];
    const float* Wm     = (const float*)d_in[15];
    const float* bm     = (const float*)d_in[16];
    const float* Wl     = (const float*)d_in[17];
    const float* bl     = (const float*)d_in[18];
    const float* Ws     = (const float*)d_in[19];
    const float* bs     = (const float*)d_in[20];
    float* out = (float*)d_out;

#define SYM(T, v, s) T* v; cudaGetSymbolAddress((void**)&v, s)
    SYM(bf16, WtTh, g_WtTh); SYM(bf16, WtTl, g_WtTl);
    SYM(bf16, rootTh, g_rootTh); SYM(bf16, rootTl, g_rootTl);
    SYM(bf16, wcatTh, g_wcatTh); SYM(bf16, wcatTl, g_wcatTl);
    SYM(bf16, WmTh, g_WmTh); SYM(bf16, WmTl, g_WmTl);
    SYM(bf16, WlTh, g_WlTh); SYM(bf16, WlTl, g_WlTl);
    SYM(bf16, emoh, g_emoh); SYM(bf16, emol, g_emol);
    SYM(bf16, a2h, g_a2h); SYM(bf16, a2l, g_a2l);
    SYM(u32, h1p, g_h1p);
    SYM(bf16, Qh, g_Qh); SYM(bf16, Ql, g_Ql);
    SYM(bf16, Sh, g_Sh); SYM(bf16, Sl, g_Sl);
    SYM(bf16, eWTh, g_eWTh); SYM(bf16, eWTl, g_eWTl);
    SYM(float, xw, g_xw); SYM(float, agg, g_agg);
    SYM(int, cnt, g_cnt); SYM(int, off, g_off); SYM(int, cur, g_cur);
    SYM(int, eidx, g_eidx);
#undef SYM

    const int SZ_128_64 = 512 + 2 * 2 * (128 + 64) * 128;   // 98816
    const int SZ_64_128 = 512 + 2 * 2 * (64 + 128) * 128;   // 98816
    const int SZ_64_64  = 512 + 2 * 2 * (64 + 64) * 128;    // 66048

#define SETSM(KERN, SZ) cudaFuncSetAttribute((const void*)(KERN), \
    cudaFuncAttributeMaxDynamicSharedMemorySize, SZ)
    SETSM((mmt<128, 64, 128, false, false, false, false, false, false>), SZ_128_64);
    SETSM((mmt<64, 64, 128, true,  true,  false, true,  false, false>),  SZ_64_64);
    SETSM((mmt<64, 64, 128, false, true,  false, true,  false, false>),  SZ_64_64);
    SETSM((mmt<128, 64, 128, false, true,  false, true,  false, false>), SZ_128_64);
    SETSM((mmt<64, 64, 128, false, false, false, true,  true,  false>),  SZ_64_64);
    SETSM((mmt<128, 64, 128, false, true,  true,  false, false, true>),  SZ_128_64);
    SETSM(scores_softmax, SZ_64_128);
#undef SETSM

    // ---- merged prep (1 launch) ----
    prep_kernel<<<(4194304 + 524288 + 409600) / 256, 256>>>(
        x, emoh, emol, comp, basis, WtTh, WtTl,
        root, rootTh, rootTl, w_root, w_nbr, wcatTh, wcatTl,
        Wm, WmTh, WmTl, Wl, WlTh, WlTl);

    cudaMemsetAsync(cnt, 0, NND * sizeof(int));
    hist_kernel<<<NE / 256, 256>>>(ei, cnt);

    // xw = x @ Wt  (A = emo cols [0,512), lda=576)
    mmt<128, 64, 128, false, false, false, false, false, false>
        <<<dim3(16, 64, 1), 128, SZ_128_64>>>(
        emoh, emol, NDm, 0, WtTh, WtTl, 512, 0,
        xw, nullptr, nullptr, nullptr, 1024, 0, nullptr, 0, nullptr,
        nullptr, nullptr, 512);

    scan_kernel<<<1, 1024>>>(cnt, off, cur);
    fill_kernel<<<NE / 256, 256>>>(ei, et, cur, eidx);

    rgcn_gather<<<NND / 4, 256>>>(off, eidx, xw, agg);

    // h1 = agg + x@root + bias1 -> a2 cols [0,64) pairs + packed h1p
    mmt<64, 64, 128, true, true, false, true, false, false>
        <<<dim3(1, 128, 1), 128, SZ_64_64>>>(
        emoh, emol, NDm, 0, rootTh, rootTl, 512, 0,
        nullptr, a2h, a2l, h1p, 128, 0, agg, 64, bias1,
        nullptr, nullptr, 512);

    gc_gather<<<NND / 4, 256>>>(off, eidx, h1p, a2h, a2l);

    // h2 = [h1 | aggH1] @ [w_root; w_nbr] + bias2 -> emo cols [512,576)
    mmt<64, 64, 128, false, true, false, true, false, false>
        <<<dim3(1, 128, 1), 128, SZ_64_64>>>(
        a2h, a2l, 128, 0, wcatTh, wcatTl, 128, 0,
        nullptr, emoh + NF, emol + NF, nullptr, NDm, 0, nullptr, 0, bias2,
        nullptr, nullptr, 128);

    // Q = emo @ Wm + bm -> pairs
    mmt<128, 64, 128, false, true, false, true, false, false>
        <<<dim3(9, 64, 1), 128, SZ_128_64>>>(
        emoh, emol, NDm, 0, WmTh, WmTl, NDm, 0,
        nullptr, Qh, Ql, nullptr, NDm, 0, nullptr, 0, bm,
        nullptr, nullptr, NDm);

    // eW = emo @ Wl -> per-conversation TRANSPOSED pairs eWT[b][n][q]
    mmt<64, 64, 128, false, false, false, true, true, false>
        <<<dim3(1, 128, 1), 128, SZ_64_64>>>(
        emoh, emol, NDm, 0, WlTh, WlTl, NDm, 0,
        nullptr, eWTh, eWTl, nullptr, 0, 0, nullptr, 0, nullptr,
        nullptr, nullptr, NDm);

    // fused scores + softmax -> bf16 pairs
    scores_softmax<<<dim3(1, 2, NBc), 128, SZ_64_128>>>(
        Qh, Ql, emoh, emol, umask, Sh, Sl);

    // hidden = relu(alpha @ eWT + bl) -> FUSED head -> out
    mmt<128, 64, 128, false, true, true, false, false, true>
        <<<dim3(1, 1, NBc), 128, SZ_128_64>>>(
        Sh, Sl, NL, (long long)NL * NL, eWTh, eWTl, NL, (long long)NH * NL,
        out, nullptr, nullptr, nullptr, NH, 0, nullptr, 0, bl,
        Ws, bs, NL);

    (void)in_sizes; (void)n_in; (void)out_size;
}

// round 14
// speedup vs baseline: 1.2128x; 1.0905x over previous
#include <cuda_runtime.h>
#include <cuda_bf16.h>
#include <math.h>
#include <cstdint>

// ---- problem constants ----
#define NND 8192
#define NF  512
#define NH  64
#define NRel 16
#define NBase 30
#define NE  524288
#define NBc 64
#define NL  128
#define NDm 576
#define NC  7
#define KC  64          // K chunk (bf16) per pipeline stage; 128B rows
#define MAXD 192        // padded slots per node (mean deg 64, sigma 8)

typedef __nv_bfloat16 bf16;
typedef unsigned int u32;

// ---- static device scratch ----
__device__ __align__(16) bf16 g_WtTh[1024 * 512];
__device__ __align__(16) bf16 g_WtTl[1024 * 512];
__device__ __align__(16) bf16 g_rootTh[64 * 512];
__device__ __align__(16) bf16 g_rootTl[64 * 512];
__device__ __align__(16) bf16 g_wcatTh[64 * 128];
__device__ __align__(16) bf16 g_wcatTl[64 * 128];
__device__ __align__(16) bf16 g_WmTh[576 * 576];
__device__ __align__(16) bf16 g_WmTl[576 * 576];
__device__ __align__(16) bf16 g_WlTh[64 * 576];
__device__ __align__(16) bf16 g_WlTl[64 * 576];
__device__ __align__(16) bf16 g_emoh[(size_t)NND * NDm];
__device__ __align__(16) bf16 g_emol[(size_t)NND * NDm];
__device__ __align__(16) bf16 g_a2h[NND * 128];
__device__ __align__(16) bf16 g_a2l[NND * 128];
__device__ __align__(16) u32  g_h1p[NND * NH];
__device__ __align__(16) bf16 g_Qh[(size_t)NND * NDm];
__device__ __align__(16) bf16 g_Ql[(size_t)NND * NDm];
__device__ __align__(16) bf16 g_Sh[NND * NL];
__device__ __align__(16) bf16 g_Sl[NND * NL];
__device__ __align__(16) bf16 g_eWTh[NBc * NH * NL];
__device__ __align__(16) bf16 g_eWTl[NBc * NH * NL];

__device__ __align__(16) float g_xw[(size_t)NND * NRel * NH];
__device__ __align__(16) float g_agg[NND * NH];
// padded edge slots
__device__ int g_cur[NND];
__device__ int g_eidx[(size_t)NND * MAXD];

__device__ __forceinline__ void split_pair(float v, bf16& h, bf16& l) {
    h = __float2bfloat16(v);
    l = __float2bfloat16(v - __bfloat162float(h));
}

__device__ __forceinline__ u32 smem_u32(const void* p) {
    u32 a;
    asm("{ .reg .u64 t; cvta.to.shared.u64 t, %1; cvt.u32.u64 %0, t; }"
        : "=r"(a) : "l"(p));
    return a;
}

__device__ __forceinline__ void mma16816(float* d, const u32* a, const u32* b) {
    asm volatile(
        "mma.sync.aligned.m16n8k16.row.col.f32.bf16.bf16.f32 "
        "{%0,%1,%2,%3}, {%4,%5,%6,%7}, {%8,%9}, {%0,%1,%2,%3};"
        : "+f"(d[0]), "+f"(d[1]), "+f"(d[2]), "+f"(d[3])
        : "r"(a[0]), "r"(a[1]), "r"(a[2]), "r"(a[3]), "r"(b[0]), "r"(b[1]));
}

#define LDSM4(r, addr) \
    asm volatile("ldmatrix.sync.aligned.m8n8.x4.shared.b16 {%0,%1,%2,%3}, [%4];" \
        : "=r"((r)[0]), "=r"((r)[1]), "=r"((r)[2]), "=r"((r)[3]) : "r"(addr))

#define CPA(d, s) \
    asm volatile("cp.async.cg.shared.global [%0], [%1], 16;" :: "r"(d), "l"(s) : "memory")
#define CPC() asm volatile("cp.async.commit_group;" ::: "memory")
#define CPW0() asm volatile("cp.async.wait_group 0;" ::: "memory")

// ============================================================
// Pipelined warp-MMA 3xBF16 GEMM: C[M,N] = A @ B^T
// ============================================================
template <int BM, int NT, int THREADS,
          bool ADD_D, bool BIAS, bool RELU, bool OUT_PAIR, bool OUT_T, bool HEAD>
__global__ void __launch_bounds__(THREADS, 2)
mmt(const bf16* __restrict__ Ah, const bf16* __restrict__ Al, int lda, long long sA,
    const bf16* __restrict__ Bh, const bf16* __restrict__ Bl, int ldb, long long sB,
    float* __restrict__ C, bf16* __restrict__ Ch, bf16* __restrict__ Cl,
    u32* __restrict__ Cp,
    int ldc, long long sC,
    const float* __restrict__ D, int ldd,
    const float* __restrict__ bias,
    const float* __restrict__ Ws, const float* __restrict__ bsv,
    int K)
{
    constexpr int WARPS = THREADS / 32;
    constexpr int WN = NT / 64;
    constexpr int WMC = WARPS / WN;
    constexpr int WM = BM / WMC;
    constexpr int MI = WM / 16;
    constexpr int STAGE_ROWS = 2 * (BM + NT);
    constexpr int STAGE_B = STAGE_ROWS * 128;
    constexpr int CHUNKS = STAGE_ROWS * 8 / THREADS;

    extern __shared__ char smem[];
    const u32 sb0 = smem_u32(smem) + 512;

    const int tid = threadIdx.x;
    const int wid = tid >> 5, lane = tid & 31;
    const int warpM = wid % WMC, warpN = wid / WMC;
    const int bz = blockIdx.z;
    const int m0 = blockIdx.y * BM;
    const int n0 = blockIdx.x * NT;

    const char* pAh = (const char*)(Ah + sA * bz + (size_t)m0 * lda);
    const char* pAl = (const char*)(Al + sA * bz + (size_t)m0 * lda);
    const char* pBh = (const char*)(Bh + sB * bz + (size_t)n0 * ldb);
    const char* pBl = (const char*)(Bl + sB * bz + (size_t)n0 * ldb);
    const size_t ldab = (size_t)lda * 2;
    const size_t ldbb = (size_t)ldb * 2;

    float acc[MI][8][4];
#pragma unroll
    for (int i = 0; i < MI; i++)
#pragma unroll
        for (int j = 0; j < 8; j++)
#pragma unroll
            for (int q = 0; q < 4; q++) acc[i][j][q] = 0.f;

    const int S = K / KC;

    auto load_stage = [&](int s) {
        const size_t kcb = (size_t)s * KC * 2;
        const u32 dst0 = sb0 + (u32)(s & 1) * STAGE_B;
#pragma unroll
        for (int f = 0; f < CHUNKS; f++) {
            int idx = tid + f * THREADS;
            int row = idx >> 3;
            u32 cb = (u32)(idx & 7) << 4;
            u32 sw = cb ^ (((u32)(row & 7)) << 4);
            const char* src;
            if (row < BM)               src = pAh + (size_t)row * ldab + kcb + cb;
            else if (row < 2 * BM)      src = pAl + (size_t)(row - BM) * ldab + kcb + cb;
            else if (row < 2 * BM + NT) src = pBh + (size_t)(row - 2 * BM) * ldbb + kcb + cb;
            else                        src = pBl + (size_t)(row - 2 * BM - NT) * ldbb + kcb + cb;
            CPA(dst0 + (u32)row * 128 + sw, src);
        }
    };

    load_stage(0);
    CPC();

    const u32 xorv = ((u32)(lane & 7)) << 4;
    const u32 aRow = (u32)(warpM * WM + (lane & 15));
    const u32 aCol0 = ((u32)(lane >> 4) & 1) * 16;
    const u32 bRow = (u32)(warpN * 64 + ((lane & 7) | ((lane & 16) >> 1)));
    const u32 bCol0 = ((u32)(lane >> 3) & 1) * 16;

    for (int s = 0; s < S; s++) {
        CPW0();
        __syncthreads();
        if (s + 1 < S) { load_stage(s + 1); CPC(); }

        const u32 base = sb0 + (u32)(s & 1) * STAGE_B;
        const u32 aH = base + aRow * 128;
        const u32 aL = aH + (u32)BM * 128;
        const u32 bH = base + (u32)(2 * BM) * 128 + bRow * 128;
        const u32 bL = bH + (u32)NT * 128;

#pragma unroll
        for (int ks = 0; ks < KC / 16; ks++) {
            const u32 kb = (u32)ks * 32;
            const u32 acol = (aCol0 + kb) ^ xorv;
            const u32 bcol = (bCol0 + kb) ^ xorv;
            u32 ah[MI][4], al[MI][4];
#pragma unroll
            for (int mi = 0; mi < MI; mi++) {
                LDSM4(ah[mi], aH + (u32)mi * (16 * 128) + acol);
                LDSM4(al[mi], aL + (u32)mi * (16 * 128) + acol);
            }
#pragma unroll
            for (int nt = 0; nt < 4; nt++) {
                u32 bh[4], bl[4];
                LDSM4(bh, bH + (u32)nt * (16 * 128) + bcol);
                LDSM4(bl, bL + (u32)nt * (16 * 128) + bcol);
#pragma unroll
                for (int mi = 0; mi < MI; mi++)
#pragma unroll
                    for (int half = 0; half < 2; half++) {
                        float* a4 = acc[mi][nt * 2 + half];
                        mma16816(a4, ah[mi], &bh[half * 2]);
                        mma16816(a4, ah[mi], &bl[half * 2]);
                        mma16816(a4, al[mi], &bh[half * 2]);
                    }
            }
        }
    }

    if (HEAD) {
        __syncthreads();
        float* wss = (float*)smem;
        for (int i = tid; i < NH * NC + NC; i += THREADS)
            wss[i] = (i < NH * NC) ? Ws[i] : bsv[i - NH * NC];
        __syncthreads();
        const int tg = lane & 3;
#pragma unroll
        for (int mi = 0; mi < MI; mi++) {
#pragma unroll
            for (int half = 0; half < 2; half++) {
                const int m = m0 + warpM * WM + mi * 16 + (lane >> 2) + half * 8;
                float lg[NC];
#pragma unroll
                for (int c = 0; c < NC; c++) lg[c] = 0.f;
#pragma unroll
                for (int ni = 0; ni < 8; ni++) {
                    const int n = ni * 8 + tg * 2;
                    float v0 = acc[mi][ni][half * 2];
                    float v1 = acc[mi][ni][half * 2 + 1];
                    if (BIAS) { v0 += bias[n]; v1 += bias[n + 1]; }
                    if (RELU) { v0 = fmaxf(v0, 0.f); v1 = fmaxf(v1, 0.f); }
#pragma unroll
                    for (int c = 0; c < NC; c++)
                        lg[c] = fmaf(v0, wss[n * NC + c],
                                     fmaf(v1, wss[(n + 1) * NC + c], lg[c]));
                }
#pragma unroll
                for (int o = 1; o < 4; o <<= 1)
#pragma unroll
                    for (int c = 0; c < NC; c++)
                        lg[c] += __shfl_xor_sync(0xffffffffu, lg[c], o);
                if (tg == 0) {
#pragma unroll
                    for (int c = 0; c < NC; c++) lg[c] += wss[NH * NC + c];
                    float mx = lg[0];
#pragma unroll
                    for (int c = 1; c < NC; c++) mx = fmaxf(mx, lg[c]);
                    float ssum = 0.f;
#pragma unroll
                    for (int c = 0; c < NC; c++) ssum += expf(lg[c] - mx);
                    float lse = mx + logf(ssum);
                    const size_t o0 = (size_t)(bz * NL + m) * NC;
#pragma unroll
                    for (int c = 0; c < NC; c++) C[o0 + c] = lg[c] - lse;
                }
            }
        }
        return;
    }

    // ---- standard epilogue ----
#pragma unroll
    for (int mi = 0; mi < MI; mi++) {
        const int rm = m0 + warpM * WM + mi * 16 + (lane >> 2);
#pragma unroll
        for (int ni = 0; ni < 8; ni++) {
            const int n = n0 + warpN * 64 + ni * 8 + (lane & 3) * 2;
#pragma unroll
            for (int half = 0; half < 2; half++) {
                const int m = rm + half * 8;
                float v0 = acc[mi][ni][half * 2];
                float v1 = acc[mi][ni][half * 2 + 1];
                if (BIAS) { v0 += bias[n]; v1 += bias[n + 1]; }
                if (ADD_D) {
                    v0 += D[(size_t)m * ldd + n];
                    v1 += D[(size_t)m * ldd + n + 1];
                }
                if (RELU) { v0 = fmaxf(v0, 0.f); v1 = fmaxf(v1, 0.f); }
                if (OUT_PAIR) {
                    bf16 h0, l0, h1c, l1c;
                    split_pair(v0, h0, l0);
                    split_pair(v1, h1c, l1c);
                    if (OUT_T) {
                        size_t o = ((size_t)(m >> 7) * 64 + n) * 128 + (m & 127);
                        Ch[o] = h0; Ch[o + 128] = h1c;
                        Cl[o] = l0; Cl[o + 128] = l1c;
                    } else {
                        const size_t o = (size_t)sC * bz + (size_t)m * ldc + n;
                        *(__nv_bfloat162*)&Ch[o] = __nv_bfloat162(h0, h1c);
                        *(__nv_bfloat162*)&Cl[o] = __nv_bfloat162(l0, l1c);
                        if (Cp) {
                            __nv_bfloat162 p0(h0, l0), p1(h1c, l1c);
                            uint2 u; u.x = *(u32*)&p0; u.y = *(u32*)&p1;
                            *(uint2*)&Cp[(size_t)m * 64 + n] = u;
                        }
                    }
                } else {
                    float2 f2; f2.x = v0; f2.y = v1;
                    *(float2*)&C[(size_t)sC * bz + (size_t)m * ldc + n] = f2;
                }
            }
        }
    }
}

// ============================================================
// Fused scores kernel: S = tanh((Q.M)*u^2) -> softmax -> *u -> renorm
// ============================================================
__global__ void __launch_bounds__(128, 2)
scores_softmax(const bf16* __restrict__ Qh, const bf16* __restrict__ Ql,
               const bf16* __restrict__ Mh, const bf16* __restrict__ Ml,
               const float* __restrict__ um,
               bf16* __restrict__ Sh, bf16* __restrict__ Sl)
{
    constexpr int BM = 64, NT = 128, THREADS = 128;
    constexpr int STAGE_ROWS = 2 * (BM + NT);
    constexpr int STAGE_B = STAGE_ROWS * 128;
    constexpr int CHUNKS = STAGE_ROWS * 8 / THREADS;

    extern __shared__ char smem[];
    float* ums = (float*)smem;
    float* sbuf = (float*)(smem + 512);
    const u32 sb0 = smem_u32(smem) + 512;

    const int tid = threadIdx.x;
    const int wid = tid >> 5, lane = tid & 31;
    const int warpM = wid & 1, warpN = wid >> 1;
    const int bz = blockIdx.z;
    const int m0 = blockIdx.y * BM;

    const char* pAh = (const char*)(Qh + (size_t)bz * NL * NDm + (size_t)m0 * NDm);
    const char* pAl = (const char*)(Ql + (size_t)bz * NL * NDm + (size_t)m0 * NDm);
    const char* pBh = (const char*)(Mh + (size_t)bz * NL * NDm);
    const char* pBl = (const char*)(Ml + (size_t)bz * NL * NDm);
    const size_t ldab = (size_t)NDm * 2;

    if (tid < NT) ums[tid] = um[bz * NL + tid];

    float acc[2][8][4];
#pragma unroll
    for (int i = 0; i < 2; i++)
#pragma unroll
        for (int j = 0; j < 8; j++)
#pragma unroll
            for (int q = 0; q < 4; q++) acc[i][j][q] = 0.f;

    const int S = NDm / KC;

    auto load_stage = [&](int s) {
        const size_t kcb = (size_t)s * KC * 2;
        const u32 dst0 = sb0 + (u32)(s & 1) * STAGE_B;
#pragma unroll
        for (int f = 0; f < CHUNKS; f++) {
            int idx = tid + f * THREADS;
            int row = idx >> 3;
            u32 cb = (u32)(idx & 7) << 4;
            u32 sw = cb ^ (((u32)(row & 7)) << 4);
            const char* src;
            if (row < BM)               src = pAh + (size_t)row * ldab + kcb + cb;
            else if (row < 2 * BM)      src = pAl + (size_t)(row - BM) * ldab + kcb + cb;
            else if (row < 2 * BM + NT) src = pBh + (size_t)(row - 2 * BM) * ldab + kcb + cb;
            else                        src = pBl + (size_t)(row - 2 * BM - NT) * ldab + kcb + cb;
            CPA(dst0 + (u32)row * 128 + sw, src);
        }
    };

    load_stage(0);
    CPC();

    const u32 xorv = ((u32)(lane & 7)) << 4;
    const u32 aRow = (u32)(warpM * 32 + (lane & 15));
    const u32 aCol0 = ((u32)(lane >> 4) & 1) * 16;
    const u32 bRow = (u32)(warpN * 64 + ((lane & 7) | ((lane & 16) >> 1)));
    const u32 bCol0 = ((u32)(lane >> 3) & 1) * 16;

    for (int s = 0; s < S; s++) {
        CPW0();
        __syncthreads();
        if (s + 1 < S) { load_stage(s + 1); CPC(); }

        const u32 base = sb0 + (u32)(s & 1) * STAGE_B;
        const u32 aH = base + aRow * 128;
        const u32 aL = aH + (u32)BM * 128;
        const u32 bH = base + (u32)(2 * BM) * 128 + bRow * 128;
        const u32 bL = bH + (u32)NT * 128;

#pragma unroll
        for (int ks = 0; ks < KC / 16; ks++) {
            const u32 kb = (u32)ks * 32;
            const u32 acol = (aCol0 + kb) ^ xorv;
            const u32 bcol = (bCol0 + kb) ^ xorv;
            u32 ah[2][4], al[2][4];
#pragma unroll
            for (int mi = 0; mi < 2; mi++) {
                LDSM4(ah[mi], aH + (u32)mi * (16 * 128) + acol);
                LDSM4(al[mi], aL + (u32)mi * (16 * 128) + acol);
            }
#pragma unroll
            for (int nt = 0; nt < 4; nt++) {
                u32 bh[4], bl[4];
                LDSM4(bh, bH + (u32)nt * (16 * 128) + bcol);
                LDSM4(bl, bL + (u32)nt * (16 * 128) + bcol);
#pragma unroll
                for (int mi = 0; mi < 2; mi++)
#pragma unroll
                    for (int half = 0; half < 2; half++) {
                        float* a4 = acc[mi][nt * 2 + half];
                        mma16816(a4, ah[mi], &bh[half * 2]);
                        mma16816(a4, ah[mi], &bl[half * 2]);
                        mma16816(a4, al[mi], &bh[half * 2]);
                    }
            }
        }
    }
    __syncthreads();

#pragma unroll
    for (int mi = 0; mi < 2; mi++) {
#pragma unroll
        for (int ni = 0; ni < 8; ni++) {
            const int col = warpN * 64 + ni * 8 + (lane & 3) * 2;
            const float u0 = ums[col], u1 = ums[col + 1];
#pragma unroll
            for (int half = 0; half < 2; half++) {
                const int row = warpM * 32 + mi * 16 + (lane >> 2) + half * 8;
                float v0 = tanhf(acc[mi][ni][half * 2] * u0 * u0);
                float v1 = tanhf(acc[mi][ni][half * 2 + 1] * u1 * u1);
                float2 f2; f2.x = v0; f2.y = v1;
                *(float2*)&sbuf[row * 132 + col] = f2;
            }
        }
    }
    __syncthreads();

    for (int r8 = 0; r8 < 16; r8++) {
        const int row = wid * 16 + r8;
        float4 v = *(const float4*)&sbuf[row * 132 + lane * 4];
        float mx = fmaxf(fmaxf(v.x, v.y), fmaxf(v.z, v.w));
#pragma unroll
        for (int o = 16; o > 0; o >>= 1)
            mx = fmaxf(mx, __shfl_xor_sync(0xffffffffu, mx, o));
        float e0 = expf(v.x - mx), e1 = expf(v.y - mx);
        float e2 = expf(v.z - mx), e3 = expf(v.w - mx);
        float sum1 = e0 + e1 + e2 + e3;
#pragma unroll
        for (int o = 16; o > 0; o >>= 1)
            sum1 += __shfl_xor_sync(0xffffffffu, sum1, o);
        const int col = lane * 4;
        float a0 = (e0 / sum1) * ums[col];
        float a1 = (e1 / sum1) * ums[col + 1];
        float a2 = (e2 / sum1) * ums[col + 2];
        float a3 = (e3 / sum1) * ums[col + 3];
        float sum2 = a0 + a1 + a2 + a3;
#pragma unroll
        for (int o = 16; o > 0; o >>= 1)
            sum2 += __shfl_xor_sync(0xffffffffu, sum2, o);
        float inv = 1.f / sum2;
        bf16 h0, l0, h1, l1, h2, l2, h3, l3;
        split_pair(a0 * inv, h0, l0);
        split_pair(a1 * inv, h1, l1);
        split_pair(a2 * inv, h2, l2);
        split_pair(a3 * inv, h3, l3);
        const size_t o0 = (size_t)(bz * NL + m0 + row) * NL + col;
        *(__nv_bfloat162*)&Sh[o0]     = __nv_bfloat162(h0, h1);
        *(__nv_bfloat162*)&Sh[o0 + 2] = __nv_bfloat162(h2, h3);
        *(__nv_bfloat162*)&Sl[o0]     = __nv_bfloat162(l0, l1);
        *(__nv_bfloat162*)&Sl[o0 + 2] = __nv_bfloat162(l2, l3);
    }
}

// ============================================================
// merged prep kernel: cvtx + wt + tcvt in one launch
// ============================================================
__global__ void prep_kernel(
    const float* __restrict__ x, bf16* __restrict__ eh, bf16* __restrict__ el,
    const float* __restrict__ comp, const float* __restrict__ basis,
    bf16* __restrict__ Wh, bf16* __restrict__ Wl,
    const float* __restrict__ root, bf16* __restrict__ rTh, bf16* __restrict__ rTl,
    const float* __restrict__ wr, const float* __restrict__ wn,
    bf16* __restrict__ wcTh, bf16* __restrict__ wcTl,
    const float* __restrict__ Wm, bf16* __restrict__ WmTh, bf16* __restrict__ WmTl,
    const float* __restrict__ Wl2, bf16* __restrict__ WlTh, bf16* __restrict__ WlTl)
{
    int i = blockIdx.x * 256 + threadIdx.x;
    if (i < 4194304) {
        bf16 h, l; split_pair(x[i], h, l);
        int row = i >> 9, c = i & 511;
        size_t eo = (size_t)row * NDm + c;
        eh[eo] = h; el[eo] = l;
    } else if (i < 4718592) {
        int idx = i - 4194304;
        int h = idx & 63, rr = (idx >> 6) & 15, k = idx >> 10;
        float acc = 0.f;
#pragma unroll
        for (int b = 0; b < NBase; b++)
            acc = fmaf(comp[rr * NBase + b], basis[((size_t)b * NF + k) * NH + h], acc);
        bf16 hh, ll; split_pair(acc, hh, ll);
        size_t o = (size_t)(rr * 64 + h) * 512 + k;
        Wh[o] = hh; Wl[o] = ll;
    } else {
        int j = i - 4718592;
        if (j < 32768) {
            int rr = j / 64, cc = j % 64;
            bf16 h, l; split_pair(root[j], h, l);
            rTh[(size_t)cc * 512 + rr] = h; rTl[(size_t)cc * 512 + rr] = l;
        } else if (j < 36864) {
            int q = j - 32768, rr = q / 64, cc = q % 64;
            bf16 h, l; split_pair(wr[q], h, l);
            wcTh[cc * 128 + rr] = h; wcTl[cc * 128 + rr] = l;
        } else if (j < 40960) {
            int q = j - 36864, rr = q / 64, cc = q % 64;
            bf16 h, l; split_pair(wn[q], h, l);
            wcTh[cc * 128 + 64 + rr] = h; wcTl[cc * 128 + 64 + rr] = l;
        } else if (j < 372736) {
            int q = j - 40960, rr = q / 576, cc = q % 576;
            bf16 h, l; split_pair(Wm[q], h, l);
            WmTh[(size_t)cc * 576 + rr] = h; WmTl[(size_t)cc * 576 + rr] = l;
        } else if (j < 409600) {
            int q = j - 372736, rr = q / 64, cc = q % 64;
            bf16 h, l; split_pair(Wl2[q], h, l);
            WlTh[(size_t)cc * 576 + rr] = h; WlTl[(size_t)cc * 576 + rr] = l;
        }
    }
}

// ---- edge fill (padded slots; no scan needed) ----
__global__ void fill_kernel(const int* __restrict__ ei, const int* __restrict__ et,
                            int* __restrict__ cur, int* __restrict__ eidx)
{
    int i = blockIdx.x * 256 + threadIdx.x;
    if (i >= NE) return;
    int dst = ei[NE + i];
    int pos = atomicAdd(&cur[dst], 1);
    eidx[(size_t)dst * MAXD + pos] = ei[i] * 16 + et[i];
}

// ---- gathers (4 nodes per 256-thread block) ----
__global__ void __launch_bounds__(256)
rgcn_gather(const int* __restrict__ cur, const int* __restrict__ eidx,
            const float* __restrict__ xw, float* __restrict__ agg)
{
    const int n = blockIdx.x * 4 + (threadIdx.x >> 6);
    const int h = threadIdx.x & 63;
    const int cntn = cur[n];
    const int beg = n * MAXD, end = beg + cntn;
    float acc = 0.f;
    int e = beg;
    for (; e + 4 <= end; e += 4) {
        int p0 = eidx[e], p1 = eidx[e + 1], p2 = eidx[e + 2], p3 = eidx[e + 3];
        acc += xw[(size_t)(p0 >> 4) * 1024 + (p0 & 15) * 64 + h]
             + xw[(size_t)(p1 >> 4) * 1024 + (p1 & 15) * 64 + h]
             + xw[(size_t)(p2 >> 4) * 1024 + (p2 & 15) * 64 + h]
             + xw[(size_t)(p3 >> 4) * 1024 + (p3 & 15) * 64 + h];
    }
    for (; e < end; e++) {
        int p = eidx[e];
        acc += xw[(size_t)(p >> 4) * 1024 + (p & 15) * 64 + h];
    }
    agg[n * NH + h] = acc / fmaxf((float)cntn, 1.f);
}

__global__ void __launch_bounds__(256)
gc_gather(const int* __restrict__ cur, const int* __restrict__ eidx,
          const u32* __restrict__ h1p, bf16* __restrict__ a2h, bf16* __restrict__ a2l)
{
    const int n = blockIdx.x * 4 + (threadIdx.x >> 6);
    const int h = threadIdx.x & 63;
    const int cntn = cur[n];
    const int beg = n * MAXD, end = beg + cntn;
    float acc = 0.f;
    int e = beg;
    for (; e + 4 <= end; e += 4) {
        u32 q0 = h1p[(eidx[e] >> 4) * 64 + h];
        u32 q1 = h1p[(eidx[e + 1] >> 4) * 64 + h];
        u32 q2 = h1p[(eidx[e + 2] >> 4) * 64 + h];
        u32 q3 = h1p[(eidx[e + 3] >> 4) * 64 + h];
        __nv_bfloat162 t0 = *(__nv_bfloat162*)&q0, t1 = *(__nv_bfloat162*)&q1;
        __nv_bfloat162 t2 = *(__nv_bfloat162*)&q2, t3 = *(__nv_bfloat162*)&q3;
        acc += __bfloat162float(t0.x) + __bfloat162float(t0.y)
             + __bfloat162float(t1.x) + __bfloat162float(t1.y)
             + __bfloat162float(t2.x) + __bfloat162float(t2.y)
             + __bfloat162float(t3.x) + __bfloat162float(t3.y);
    }
    for (; e < end; e++) {
        u32 q = h1p[(eidx[e] >> 4) * 64 + h];
        __nv_bfloat162 t = *(__nv_bfloat162*)&q;
        acc += __bfloat162float(t.x) + __bfloat162float(t.y);
    }
    bf16 hh, ll; split_pair(acc, hh, ll);
    a2h[n * 128 + 64 + h] = hh;
    a2l[n * 128 + 64 + h] = ll;
}

// ============================================================
extern "C" void kernel_launch(void* const* d_in, const int* in_sizes, int n_in,
                              void* d_out, int out_size)
{
    const float* x      = (const float*)d_in[0];
    const int*   ei     = (const int*)d_in[1];
    const int*   et     = (const int*)d_in[3];
    const float* umask  = (const float*)d_in[5];
    const float* basis  = (const float*)d_in[8];
    const float* comp   = (const float*)d_in[9];
    const float* root   = (const float*)d_in[10];
    const float* bias1  = (const float*)d_in[11];
    const float* w_nbr  = (const float*)d_in[12];
    const float* w_root = (const float*)d_in[13];
    const float* bias2  = (const float*)d_in[14];
    const float* Wm     = (const float*)d_in[15];
    const float* bm     = (const float*)d_in[16];
    const float* Wl     = (const float*)d_in[17];
    const float* bl     = (const float*)d_in[18];
    const float* Ws     = (const float*)d_in[19];
    const float* bs     = (const float*)d_in[20];
    float* out = (float*)d_out;

#define SYM(T, v, s) T* v; cudaGetSymbolAddress((void**)&v, s)
    SYM(bf16, WtTh, g_WtTh); SYM(bf16, WtTl, g_WtTl);
    SYM(bf16, rootTh, g_rootTh); SYM(bf16, rootTl, g_rootTl);
    SYM(bf16, wcatTh, g_wcatTh); SYM(bf16, wcatTl, g_wcatTl);
    SYM(bf16, WmTh, g_WmTh); SYM(bf16, WmTl, g_WmTl);
    SYM(bf16, WlTh, g_WlTh); SYM(bf16, WlTl, g_WlTl);
    SYM(bf16, emoh, g_emoh); SYM(bf16, emol, g_emol);
    SYM(bf16, a2h, g_a2h); SYM(bf16, a2l, g_a2l);
    SYM(u32, h1p, g_h1p);
    SYM(bf16, Qh, g_Qh); SYM(bf16, Ql, g_Ql);
    SYM(bf16, Sh, g_Sh); SYM(bf16, Sl, g_Sl);
    SYM(bf16, eWTh, g_eWTh); SYM(bf16, eWTl, g_eWTl);
    SYM(float, xw, g_xw); SYM(float, agg, g_agg);
    SYM(int, cur, g_cur); SYM(int, eidx, g_eidx);
#undef SYM

    const int SZ_128_64 = 512 + 2 * 2 * (128 + 64) * 128;   // 98816
    const int SZ_64_128 = 512 + 2 * 2 * (64 + 128) * 128;   // 98816
    const int SZ_64_64  = 512 + 2 * 2 * (64 + 64) * 128;    // 66048

#define SETSM(KERN, SZ) cudaFuncSetAttribute((const void*)(KERN), \
    cudaFuncAttributeMaxDynamicSharedMemorySize, SZ)
    SETSM((mmt<128, 64, 128, false, false, false, false, false, false>), SZ_128_64);
    SETSM((mmt<64, 64, 128, true,  true,  false, true,  false, false>),  SZ_64_64);
    SETSM((mmt<64, 64, 128, false, true,  false, true,  false, false>),  SZ_64_64);
    SETSM((mmt<128, 64, 128, false, true,  false, true,  false, false>), SZ_128_64);
    SETSM((mmt<64, 64, 128, false, false, false, true,  true,  false>),  SZ_64_64);
    SETSM((mmt<128, 64, 128, false, true,  true,  false, false, true>),  SZ_128_64);
    SETSM(scores_softmax, SZ_64_128);
#undef SETSM

    // ---- merged prep (1 launch) ----
    prep_kernel<<<(4194304 + 524288 + 409600) / 256, 256>>>(
        x, emoh, emol, comp, basis, WtTh, WtTl,
        root, rootTh, rootTl, w_root, w_nbr, wcatTh, wcatTl,
        Wm, WmTh, WmTl, Wl, WlTh, WlTl);

    // ---- edge layout: memset + fill (no hist, no scan) ----
    cudaMemsetAsync(cur, 0, NND * sizeof(int));
    fill_kernel<<<NE / 256, 256>>>(ei, et, cur, eidx);

    // xw = x @ Wt  (A = emo cols [0,512), lda=576)
    mmt<128, 64, 128, false, false, false, false, false, false>
        <<<dim3(16, 64, 1), 128, SZ_128_64>>>(
        emoh, emol, NDm, 0, WtTh, WtTl, 512, 0,
        xw, nullptr, nullptr, nullptr, 1024, 0, nullptr, 0, nullptr,
        nullptr, nullptr, 512);

    rgcn_gather<<<NND / 4, 256>>>(cur, eidx, xw, agg);

    // h1 = agg + x@root + bias1 -> a2 cols [0,64) pairs + packed h1p
    mmt<64, 64, 128, true, true, false, true, false, false>
        <<<dim3(1, 128, 1), 128, SZ_64_64>>>(
        emoh, emol, NDm, 0, rootTh, rootTl, 512, 0,
        nullptr, a2h, a2l, h1p, 128, 0, agg, 64, bias1,
        nullptr, nullptr, 512);

    gc_gather<<<NND / 4, 256>>>(cur, eidx, h1p, a2h, a2l);

    // h2 = [h1 | aggH1] @ [w_root; w_nbr] + bias2 -> emo cols [512,576)
    mmt<64, 64, 128, false, true, false, true, false, false>
        <<<dim3(1, 128, 1), 128, SZ_64_64>>>(
        a2h, a2l, 128, 0, wcatTh, wcatTl, 128, 0,
        nullptr, emoh + NF, emol + NF, nullptr, NDm, 0, nullptr, 0, bias2,
        nullptr, nullptr, 128);

    // Q = emo @ Wm + bm -> pairs
    mmt<128, 64, 128, false, true, false, true, false, false>
        <<<dim3(9, 64, 1), 128, SZ_128_64>>>(
        emoh, emol, NDm, 0, WmTh, WmTl, NDm, 0,
        nullptr, Qh, Ql, nullptr, NDm, 0, nullptr, 0, bm,
        nullptr, nullptr, NDm);

    // eW = emo @ Wl -> per-conversation TRANSPOSED pairs eWT[b][n][q]
    mmt<64, 64, 128, false, false, false, true, true, false>
        <<<dim3(1, 128, 1), 128, SZ_64_64>>>(
        emoh, emol, NDm, 0, WlTh, WlTl, NDm, 0,
        nullptr, eWTh, eWTl, nullptr, 0, 0, nullptr, 0, nullptr,
        nullptr, nullptr, NDm);

    // fused scores + softmax -> bf16 pairs
    scores_softmax<<<dim3(1, 2, NBc), 128, SZ_64_128>>>(
        Qh, Ql, emoh, emol, umask, Sh, Sl);

    // hidden = relu(alpha @ eWT + bl) -> FUSED head -> out
    mmt<128, 64, 128, false, true, true, false, false, true>
        <<<dim3(1, 1, NBc), 128, SZ_128_64>>>(
        Sh, Sl, NL, (long long)NL * NL, eWTh, eWTl, NL, (long long)NH * NL,
        out, nullptr, nullptr, nullptr, NH, 0, nullptr, 0, bl,
        Ws, bs, NL);

    (void)in_sizes; (void)n_in; (void)out_size;
}

// round 15
// speedup vs baseline: 1.2391x; 1.0216x over previous
#include <cuda_runtime.h>
#include <cuda_bf16.h>
#include <math.h>
#include <cstdint>

// ---- problem constants ----
#define NND 8192
#define NF  512
#define NH  64
#define NRel 16
#define NBase 30
#define NE  524288
#define NBc 64
#define NL  128
#define NDm 576
#define NC  7
#define KC  64          // K chunk (bf16) per pipeline stage; 128B rows
#define MAXD 192        // padded slots per node (mean deg 64, sigma 8)

typedef __nv_bfloat16 bf16;
typedef unsigned int u32;

// ---- static device scratch ----
__device__ __align__(16) bf16 g_WtTh[1024 * 512];
__device__ __align__(16) bf16 g_WtTl[1024 * 512];
__device__ __align__(16) bf16 g_rootTh[64 * 512];
__device__ __align__(16) bf16 g_rootTl[64 * 512];
__device__ __align__(16) bf16 g_wcatTh[64 * 128];
__device__ __align__(16) bf16 g_wcatTl[64 * 128];
__device__ __align__(16) bf16 g_WmTh[576 * 576];
__device__ __align__(16) bf16 g_WmTl[576 * 576];
__device__ __align__(16) bf16 g_WlTh[64 * 576];
__device__ __align__(16) bf16 g_WlTl[64 * 576];
__device__ __align__(16) bf16 g_emoh[(size_t)NND * NDm];
__device__ __align__(16) bf16 g_emol[(size_t)NND * NDm];
__device__ __align__(16) bf16 g_a2h[NND * 128];
__device__ __align__(16) bf16 g_a2l[NND * 128];
__device__ __align__(16) u32  g_h1p[NND * NH];
__device__ __align__(16) bf16 g_Qh[(size_t)NND * NDm];
__device__ __align__(16) bf16 g_Ql[(size_t)NND * NDm];
__device__ __align__(16) bf16 g_Sh[NND * NL];
__device__ __align__(16) bf16 g_Sl[NND * NL];
__device__ __align__(16) bf16 g_eWTh[NBc * NH * NL];
__device__ __align__(16) bf16 g_eWTl[NBc * NH * NL];

__device__ __align__(16) float g_xw[(size_t)NND * NRel * NH];
__device__ __align__(16) float g_agg[NND * NH];
// padded edge slots
__device__ int g_cur[NND];
__device__ int g_eidx[(size_t)NND * MAXD];

__device__ __forceinline__ void split_pair(float v, bf16& h, bf16& l) {
    h = __float2bfloat16(v);
    l = __float2bfloat16(v - __bfloat162float(h));
}

__device__ __forceinline__ u32 smem_u32(const void* p) {
    u32 a;
    asm("{ .reg .u64 t; cvta.to.shared.u64 t, %1; cvt.u32.u64 %0, t; }"
        : "=r"(a) : "l"(p));
    return a;
}

__device__ __forceinline__ void mma16816(float* d, const u32* a, const u32* b) {
    asm volatile(
        "mma.sync.aligned.m16n8k16.row.col.f32.bf16.bf16.f32 "
        "{%0,%1,%2,%3}, {%4,%5,%6,%7}, {%8,%9}, {%0,%1,%2,%3};"
        : "+f"(d[0]), "+f"(d[1]), "+f"(d[2]), "+f"(d[3])
        : "r"(a[0]), "r"(a[1]), "r"(a[2]), "r"(a[3]), "r"(b[0]), "r"(b[1]));
}

#define LDSM4(r, addr) \
    asm volatile("ldmatrix.sync.aligned.m8n8.x4.shared.b16 {%0,%1,%2,%3}, [%4];" \
        : "=r"((r)[0]), "=r"((r)[1]), "=r"((r)[2]), "=r"((r)[3]) : "r"(addr))

#define CPA(d, s) \
    asm volatile("cp.async.cg.shared.global [%0], [%1], 16;" :: "r"(d), "l"(s) : "memory")
#define CPC() asm volatile("cp.async.commit_group;" ::: "memory")
#define CPW0() asm volatile("cp.async.wait_group 0;" ::: "memory")

// ============================================================
// Pipelined warp-MMA 3xBF16 GEMM: C[M,N] = A @ B^T
// ============================================================
template <int BM, int NT, int THREADS,
          bool ADD_D, bool BIAS, bool RELU, bool OUT_PAIR, bool OUT_T, bool HEAD>
__global__ void __launch_bounds__(THREADS, 2)
mmt(const bf16* __restrict__ Ah, const bf16* __restrict__ Al, int lda, long long sA,
    const bf16* __restrict__ Bh, const bf16* __restrict__ Bl, int ldb, long long sB,
    float* __restrict__ C, bf16* __restrict__ Ch, bf16* __restrict__ Cl,
    u32* __restrict__ Cp,
    int ldc, long long sC,
    const float* __restrict__ D, int ldd,
    const float* __restrict__ bias,
    const float* __restrict__ Ws, const float* __restrict__ bsv,
    int K)
{
    constexpr int WARPS = THREADS / 32;
    constexpr int WN = NT / 64;
    constexpr int WMC = WARPS / WN;
    constexpr int WM = BM / WMC;
    constexpr int MI = WM / 16;
    constexpr int STAGE_ROWS = 2 * (BM + NT);
    constexpr int STAGE_B = STAGE_ROWS * 128;
    constexpr int CHUNKS = STAGE_ROWS * 8 / THREADS;

    extern __shared__ char smem[];
    const u32 sb0 = smem_u32(smem) + 512;

    const int tid = threadIdx.x;
    const int wid = tid >> 5, lane = tid & 31;
    const int warpM = wid % WMC, warpN = wid / WMC;
    const int bz = blockIdx.z;
    const int m0 = blockIdx.y * BM;
    const int n0 = blockIdx.x * NT;

    const char* pAh = (const char*)(Ah + sA * bz + (size_t)m0 * lda);
    const char* pAl = (const char*)(Al + sA * bz + (size_t)m0 * lda);
    const char* pBh = (const char*)(Bh + sB * bz + (size_t)n0 * ldb);
    const char* pBl = (const char*)(Bl + sB * bz + (size_t)n0 * ldb);
    const size_t ldab = (size_t)lda * 2;
    const size_t ldbb = (size_t)ldb * 2;

    float acc[MI][8][4];
#pragma unroll
    for (int i = 0; i < MI; i++)
#pragma unroll
        for (int j = 0; j < 8; j++)
#pragma unroll
            for (int q = 0; q < 4; q++) acc[i][j][q] = 0.f;

    const int S = K / KC;

    auto load_stage = [&](int s) {
        const size_t kcb = (size_t)s * KC * 2;
        const u32 dst0 = sb0 + (u32)(s & 1) * STAGE_B;
#pragma unroll
        for (int f = 0; f < CHUNKS; f++) {
            int idx = tid + f * THREADS;
            int row = idx >> 3;
            u32 cb = (u32)(idx & 7) << 4;
            u32 sw = cb ^ (((u32)(row & 7)) << 4);
            const char* src;
            if (row < BM)               src = pAh + (size_t)row * ldab + kcb + cb;
            else if (row < 2 * BM)      src = pAl + (size_t)(row - BM) * ldab + kcb + cb;
            else if (row < 2 * BM + NT) src = pBh + (size_t)(row - 2 * BM) * ldbb + kcb + cb;
            else                        src = pBl + (size_t)(row - 2 * BM - NT) * ldbb + kcb + cb;
            CPA(dst0 + (u32)row * 128 + sw, src);
        }
    };

    load_stage(0);
    CPC();

    const u32 xorv = ((u32)(lane & 7)) << 4;
    const u32 aRow = (u32)(warpM * WM + (lane & 15));
    const u32 aCol0 = ((u32)(lane >> 4) & 1) * 16;
    const u32 bRow = (u32)(warpN * 64 + ((lane & 7) | ((lane & 16) >> 1)));
    const u32 bCol0 = ((u32)(lane >> 3) & 1) * 16;

    for (int s = 0; s < S; s++) {
        CPW0();
        __syncthreads();
        if (s + 1 < S) { load_stage(s + 1); CPC(); }

        const u32 base = sb0 + (u32)(s & 1) * STAGE_B;
        const u32 aH = base + aRow * 128;
        const u32 aL = aH + (u32)BM * 128;
        const u32 bH = base + (u32)(2 * BM) * 128 + bRow * 128;
        const u32 bL = bH + (u32)NT * 128;

#pragma unroll
        for (int ks = 0; ks < KC / 16; ks++) {
            const u32 kb = (u32)ks * 32;
            const u32 acol = (aCol0 + kb) ^ xorv;
            const u32 bcol = (bCol0 + kb) ^ xorv;
            u32 ah[MI][4], al[MI][4];
#pragma unroll
            for (int mi = 0; mi < MI; mi++) {
                LDSM4(ah[mi], aH + (u32)mi * (16 * 128) + acol);
                LDSM4(al[mi], aL + (u32)mi * (16 * 128) + acol);
            }
#pragma unroll
            for (int nt = 0; nt < 4; nt++) {
                u32 bh[4], bl[4];
                LDSM4(bh, bH + (u32)nt * (16 * 128) + bcol);
                LDSM4(bl, bL + (u32)nt * (16 * 128) + bcol);
#pragma unroll
                for (int mi = 0; mi < MI; mi++)
#pragma unroll
                    for (int half = 0; half < 2; half++) {
                        float* a4 = acc[mi][nt * 2 + half];
                        mma16816(a4, ah[mi], &bh[half * 2]);
                        mma16816(a4, ah[mi], &bl[half * 2]);
                        mma16816(a4, al[mi], &bh[half * 2]);
                    }
            }
        }
    }

    if (HEAD) {
        __syncthreads();
        float* wss = (float*)smem;
        for (int i = tid; i < NH * NC + NC; i += THREADS)
            wss[i] = (i < NH * NC) ? Ws[i] : bsv[i - NH * NC];
        __syncthreads();
        const int tg = lane & 3;
#pragma unroll
        for (int mi = 0; mi < MI; mi++) {
#pragma unroll
            for (int half = 0; half < 2; half++) {
                const int m = m0 + warpM * WM + mi * 16 + (lane >> 2) + half * 8;
                float lg[NC];
#pragma unroll
                for (int c = 0; c < NC; c++) lg[c] = 0.f;
#pragma unroll
                for (int ni = 0; ni < 8; ni++) {
                    const int n = ni * 8 + tg * 2;
                    float v0 = acc[mi][ni][half * 2];
                    float v1 = acc[mi][ni][half * 2 + 1];
                    if (BIAS) { v0 += bias[n]; v1 += bias[n + 1]; }
                    if (RELU) { v0 = fmaxf(v0, 0.f); v1 = fmaxf(v1, 0.f); }
#pragma unroll
                    for (int c = 0; c < NC; c++)
                        lg[c] = fmaf(v0, wss[n * NC + c],
                                     fmaf(v1, wss[(n + 1) * NC + c], lg[c]));
                }
#pragma unroll
                for (int o = 1; o < 4; o <<= 1)
#pragma unroll
                    for (int c = 0; c < NC; c++)
                        lg[c] += __shfl_xor_sync(0xffffffffu, lg[c], o);
                if (tg == 0) {
#pragma unroll
                    for (int c = 0; c < NC; c++) lg[c] += wss[NH * NC + c];
                    float mx = lg[0];
#pragma unroll
                    for (int c = 1; c < NC; c++) mx = fmaxf(mx, lg[c]);
                    float ssum = 0.f;
#pragma unroll
                    for (int c = 0; c < NC; c++) ssum += expf(lg[c] - mx);
                    float lse = mx + logf(ssum);
                    const size_t o0 = (size_t)(bz * NL + m) * NC;
#pragma unroll
                    for (int c = 0; c < NC; c++) C[o0 + c] = lg[c] - lse;
                }
            }
        }
        return;
    }

    // ---- standard epilogue ----
#pragma unroll
    for (int mi = 0; mi < MI; mi++) {
        const int rm = m0 + warpM * WM + mi * 16 + (lane >> 2);
#pragma unroll
        for (int ni = 0; ni < 8; ni++) {
            const int n = n0 + warpN * 64 + ni * 8 + (lane & 3) * 2;
#pragma unroll
            for (int half = 0; half < 2; half++) {
                const int m = rm + half * 8;
                float v0 = acc[mi][ni][half * 2];
                float v1 = acc[mi][ni][half * 2 + 1];
                if (BIAS) { v0 += bias[n]; v1 += bias[n + 1]; }
                if (ADD_D) {
                    v0 += D[(size_t)m * ldd + n];
                    v1 += D[(size_t)m * ldd + n + 1];
                }
                if (RELU) { v0 = fmaxf(v0, 0.f); v1 = fmaxf(v1, 0.f); }
                if (OUT_PAIR) {
                    bf16 h0, l0, h1c, l1c;
                    split_pair(v0, h0, l0);
                    split_pair(v1, h1c, l1c);
                    if (OUT_T) {
                        size_t o = ((size_t)(m >> 7) * 64 + n) * 128 + (m & 127);
                        Ch[o] = h0; Ch[o + 128] = h1c;
                        Cl[o] = l0; Cl[o + 128] = l1c;
                    } else {
                        const size_t o = (size_t)sC * bz + (size_t)m * ldc + n;
                        *(__nv_bfloat162*)&Ch[o] = __nv_bfloat162(h0, h1c);
                        *(__nv_bfloat162*)&Cl[o] = __nv_bfloat162(l0, l1c);
                        if (Cp) {
                            __nv_bfloat162 p0(h0, l0), p1(h1c, l1c);
                            uint2 u; u.x = *(u32*)&p0; u.y = *(u32*)&p1;
                            *(uint2*)&Cp[(size_t)m * 64 + n] = u;
                        }
                    }
                } else {
                    float2 f2; f2.x = v0; f2.y = v1;
                    *(float2*)&C[(size_t)sC * bz + (size_t)m * ldc + n] = f2;
                }
            }
        }
    }
}

// ============================================================
// Fused scores kernel: S = tanh((Q.M)*u^2) -> softmax -> *u -> renorm
// ============================================================
__global__ void __launch_bounds__(128, 2)
scores_softmax(const bf16* __restrict__ Qh, const bf16* __restrict__ Ql,
               const bf16* __restrict__ Mh, const bf16* __restrict__ Ml,
               const float* __restrict__ um,
               bf16* __restrict__ Sh, bf16* __restrict__ Sl)
{
    constexpr int BM = 64, NT = 128, THREADS = 128;
    constexpr int STAGE_ROWS = 2 * (BM + NT);
    constexpr int STAGE_B = STAGE_ROWS * 128;
    constexpr int CHUNKS = STAGE_ROWS * 8 / THREADS;

    extern __shared__ char smem[];
    float* ums = (float*)smem;
    float* sbuf = (float*)(smem + 512);
    const u32 sb0 = smem_u32(smem) + 512;

    const int tid = threadIdx.x;
    const int wid = tid >> 5, lane = tid & 31;
    const int warpM = wid & 1, warpN = wid >> 1;
    const int bz = blockIdx.z;
    const int m0 = blockIdx.y * BM;

    const char* pAh = (const char*)(Qh + (size_t)bz * NL * NDm + (size_t)m0 * NDm);
    const char* pAl = (const char*)(Ql + (size_t)bz * NL * NDm + (size_t)m0 * NDm);
    const char* pBh = (const char*)(Mh + (size_t)bz * NL * NDm);
    const char* pBl = (const char*)(Ml + (size_t)bz * NL * NDm);
    const size_t ldab = (size_t)NDm * 2;

    if (tid < NT) ums[tid] = um[bz * NL + tid];

    float acc[2][8][4];
#pragma unroll
    for (int i = 0; i < 2; i++)
#pragma unroll
        for (int j = 0; j < 8; j++)
#pragma unroll
            for (int q = 0; q < 4; q++) acc[i][j][q] = 0.f;

    const int S = NDm / KC;

    auto load_stage = [&](int s) {
        const size_t kcb = (size_t)s * KC * 2;
        const u32 dst0 = sb0 + (u32)(s & 1) * STAGE_B;
#pragma unroll
        for (int f = 0; f < CHUNKS; f++) {
            int idx = tid + f * THREADS;
            int row = idx >> 3;
            u32 cb = (u32)(idx & 7) << 4;
            u32 sw = cb ^ (((u32)(row & 7)) << 4);
            const char* src;
            if (row < BM)               src = pAh + (size_t)row * ldab + kcb + cb;
            else if (row < 2 * BM)      src = pAl + (size_t)(row - BM) * ldab + kcb + cb;
            else if (row < 2 * BM + NT) src = pBh + (size_t)(row - 2 * BM) * ldab + kcb + cb;
            else                        src = pBl + (size_t)(row - 2 * BM - NT) * ldab + kcb + cb;
            CPA(dst0 + (u32)row * 128 + sw, src);
        }
    };

    load_stage(0);
    CPC();

    const u32 xorv = ((u32)(lane & 7)) << 4;
    const u32 aRow = (u32)(warpM * 32 + (lane & 15));
    const u32 aCol0 = ((u32)(lane >> 4) & 1) * 16;
    const u32 bRow = (u32)(warpN * 64 + ((lane & 7) | ((lane & 16) >> 1)));
    const u32 bCol0 = ((u32)(lane >> 3) & 1) * 16;

    for (int s = 0; s < S; s++) {
        CPW0();
        __syncthreads();
        if (s + 1 < S) { load_stage(s + 1); CPC(); }

        const u32 base = sb0 + (u32)(s & 1) * STAGE_B;
        const u32 aH = base + aRow * 128;
        const u32 aL = aH + (u32)BM * 128;
        const u32 bH = base + (u32)(2 * BM) * 128 + bRow * 128;
        const u32 bL = bH + (u32)NT * 128;

#pragma unroll
        for (int ks = 0; ks < KC / 16; ks++) {
            const u32 kb = (u32)ks * 32;
            const u32 acol = (aCol0 + kb) ^ xorv;
            const u32 bcol = (bCol0 + kb) ^ xorv;
            u32 ah[2][4], al[2][4];
#pragma unroll
            for (int mi = 0; mi < 2; mi++) {
                LDSM4(ah[mi], aH + (u32)mi * (16 * 128) + acol);
                LDSM4(al[mi], aL + (u32)mi * (16 * 128) + acol);
            }
#pragma unroll
            for (int nt = 0; nt < 4; nt++) {
                u32 bh[4], bl[4];
                LDSM4(bh, bH + (u32)nt * (16 * 128) + bcol);
                LDSM4(bl, bL + (u32)nt * (16 * 128) + bcol);
#pragma unroll
                for (int mi = 0; mi < 2; mi++)
#pragma unroll
                    for (int half = 0; half < 2; half++) {
                        float* a4 = acc[mi][nt * 2 + half];
                        mma16816(a4, ah[mi], &bh[half * 2]);
                        mma16816(a4, ah[mi], &bl[half * 2]);
                        mma16816(a4, al[mi], &bh[half * 2]);
                    }
            }
        }
    }
    __syncthreads();

#pragma unroll
    for (int mi = 0; mi < 2; mi++) {
#pragma unroll
        for (int ni = 0; ni < 8; ni++) {
            const int col = warpN * 64 + ni * 8 + (lane & 3) * 2;
            const float u0 = ums[col], u1 = ums[col + 1];
#pragma unroll
            for (int half = 0; half < 2; half++) {
                const int row = warpM * 32 + mi * 16 + (lane >> 2) + half * 8;
                float v0 = tanhf(acc[mi][ni][half * 2] * u0 * u0);
                float v1 = tanhf(acc[mi][ni][half * 2 + 1] * u1 * u1);
                float2 f2; f2.x = v0; f2.y = v1;
                *(float2*)&sbuf[row * 132 + col] = f2;
            }
        }
    }
    __syncthreads();

    for (int r8 = 0; r8 < 16; r8++) {
        const int row = wid * 16 + r8;
        float4 v = *(const float4*)&sbuf[row * 132 + lane * 4];
        float mx = fmaxf(fmaxf(v.x, v.y), fmaxf(v.z, v.w));
#pragma unroll
        for (int o = 16; o > 0; o >>= 1)
            mx = fmaxf(mx, __shfl_xor_sync(0xffffffffu, mx, o));
        float e0 = expf(v.x - mx), e1 = expf(v.y - mx);
        float e2 = expf(v.z - mx), e3 = expf(v.w - mx);
        float sum1 = e0 + e1 + e2 + e3;
#pragma unroll
        for (int o = 16; o > 0; o >>= 1)
            sum1 += __shfl_xor_sync(0xffffffffu, sum1, o);
        const int col = lane * 4;
        float a0 = (e0 / sum1) * ums[col];
        float a1 = (e1 / sum1) * ums[col + 1];
        float a2 = (e2 / sum1) * ums[col + 2];
        float a3 = (e3 / sum1) * ums[col + 3];
        float sum2 = a0 + a1 + a2 + a3;
#pragma unroll
        for (int o = 16; o > 0; o >>= 1)
            sum2 += __shfl_xor_sync(0xffffffffu, sum2, o);
        float inv = 1.f / sum2;
        bf16 h0, l0, h1, l1, h2, l2, h3, l3;
        split_pair(a0 * inv, h0, l0);
        split_pair(a1 * inv, h1, l1);
        split_pair(a2 * inv, h2, l2);
        split_pair(a3 * inv, h3, l3);
        const size_t o0 = (size_t)(bz * NL + m0 + row) * NL + col;
        *(__nv_bfloat162*)&Sh[o0]     = __nv_bfloat162(h0, h1);
        *(__nv_bfloat162*)&Sh[o0 + 2] = __nv_bfloat162(h2, h3);
        *(__nv_bfloat162*)&Sl[o0]     = __nv_bfloat162(l0, l1);
        *(__nv_bfloat162*)&Sl[o0 + 2] = __nv_bfloat162(l2, l3);
    }
}

// ============================================================
// merged prep kernel: cvtx + wt + tcvt in one launch
// ============================================================
__global__ void prep_kernel(
    const float* __restrict__ x, bf16* __restrict__ eh, bf16* __restrict__ el,
    const float* __restrict__ comp, const float* __restrict__ basis,
    bf16* __restrict__ Wh, bf16* __restrict__ Wl,
    const float* __restrict__ root, bf16* __restrict__ rTh, bf16* __restrict__ rTl,
    const float* __restrict__ wr, const float* __restrict__ wn,
    bf16* __restrict__ wcTh, bf16* __restrict__ wcTl,
    const float* __restrict__ Wm, bf16* __restrict__ WmTh, bf16* __restrict__ WmTl,
    const float* __restrict__ Wl2, bf16* __restrict__ WlTh, bf16* __restrict__ WlTl)
{
    int i = blockIdx.x * 256 + threadIdx.x;
    if (i < 4194304) {
        bf16 h, l; split_pair(x[i], h, l);
        int row = i >> 9, c = i & 511;
        size_t eo = (size_t)row * NDm + c;
        eh[eo] = h; el[eo] = l;
    } else if (i < 4718592) {
        int idx = i - 4194304;
        int h = idx & 63, rr = (idx >> 6) & 15, k = idx >> 10;
        float acc = 0.f;
#pragma unroll
        for (int b = 0; b < NBase; b++)
            acc = fmaf(comp[rr * NBase + b], basis[((size_t)b * NF + k) * NH + h], acc);
        bf16 hh, ll; split_pair(acc, hh, ll);
        size_t o = (size_t)(rr * 64 + h) * 512 + k;
        Wh[o] = hh; Wl[o] = ll;
    } else {
        int j = i - 4718592;
        if (j < 32768) {
            int rr = j / 64, cc = j % 64;
            bf16 h, l; split_pair(root[j], h, l);
            rTh[(size_t)cc * 512 + rr] = h; rTl[(size_t)cc * 512 + rr] = l;
        } else if (j < 36864) {
            int q = j - 32768, rr = q / 64, cc = q % 64;
            bf16 h, l; split_pair(wr[q], h, l);
            wcTh[cc * 128 + rr] = h; wcTl[cc * 128 + rr] = l;
        } else if (j < 40960) {
            int q = j - 36864, rr = q / 64, cc = q % 64;
            bf16 h, l; split_pair(wn[q], h, l);
            wcTh[cc * 128 + 64 + rr] = h; wcTl[cc * 128 + 64 + rr] = l;
        } else if (j < 372736) {
            int q = j - 40960, rr = q / 576, cc = q % 576;
            bf16 h, l; split_pair(Wm[q], h, l);
            WmTh[(size_t)cc * 576 + rr] = h; WmTl[(size_t)cc * 576 + rr] = l;
        } else if (j < 409600) {
            int q = j - 372736, rr = q / 64, cc = q % 64;
            bf16 h, l; split_pair(Wl2[q], h, l);
            WlTh[(size_t)cc * 576 + rr] = h; WlTl[(size_t)cc * 576 + rr] = l;
        }
    }
}

// ---- edge fill: store precomputed element offset src*1024 + rel*64 ----
__global__ void fill_kernel(const int* __restrict__ ei, const int* __restrict__ et,
                            int* __restrict__ cur, int* __restrict__ eidx)
{
    int i = blockIdx.x * 256 + threadIdx.x;
    if (i >= NE) return;
    int dst = ei[NE + i];
    int pos = atomicAdd(&cur[dst], 1);
    eidx[(size_t)dst * MAXD + pos] = (ei[i] << 10) + (et[i] << 6);
}

// ---- gathers: 16 threads/node, float4 per thread ----
__global__ void __launch_bounds__(256)
rgcn_gather(const int* __restrict__ cur, const int* __restrict__ eidx,
            const float* __restrict__ xw, float* __restrict__ agg)
{
    const int n = blockIdx.x * 16 + (threadIdx.x >> 4);
    const int h4 = (threadIdx.x & 15) * 4;
    const int cntn = cur[n];
    const int* ep = eidx + n * MAXD;
    float4 a0 = {0.f, 0.f, 0.f, 0.f}, a1 = {0.f, 0.f, 0.f, 0.f};
    int e = 0;
    for (; e + 2 <= cntn; e += 2) {
        int p0 = ep[e], p1 = ep[e + 1];
        float4 v0 = *(const float4*)(xw + p0 + h4);
        float4 v1 = *(const float4*)(xw + p1 + h4);
        a0.x += v0.x; a0.y += v0.y; a0.z += v0.z; a0.w += v0.w;
        a1.x += v1.x; a1.y += v1.y; a1.z += v1.z; a1.w += v1.w;
    }
    if (e < cntn) {
        float4 v = *(const float4*)(xw + ep[e] + h4);
        a0.x += v.x; a0.y += v.y; a0.z += v.z; a0.w += v.w;
    }
    float inv = 1.f / fmaxf((float)cntn, 1.f);
    float4 r;
    r.x = (a0.x + a1.x) * inv; r.y = (a0.y + a1.y) * inv;
    r.z = (a0.z + a1.z) * inv; r.w = (a0.w + a1.w) * inv;
    *(float4*)&agg[n * NH + h4] = r;
}

__global__ void __launch_bounds__(256)
gc_gather(const int* __restrict__ cur, const int* __restrict__ eidx,
          const u32* __restrict__ h1p, bf16* __restrict__ a2h, bf16* __restrict__ a2l)
{
    const int n = blockIdx.x * 16 + (threadIdx.x >> 4);
    const int h4 = (threadIdx.x & 15) * 4;
    const int cntn = cur[n];
    const int* ep = eidx + n * MAXD;
    float ah0 = 0.f, ah1 = 0.f, ah2 = 0.f, ah3 = 0.f;
    float al0 = 0.f, al1 = 0.f, al2 = 0.f, al3 = 0.f;
    for (int e = 0; e < cntn; e++) {
        int p = ep[e];
        int src64 = (p >> 4) & ~63;           // src*64
        uint4 q = *(const uint4*)(h1p + src64 + h4);
        __nv_bfloat162 t0 = *(__nv_bfloat162*)&q.x;
        __nv_bfloat162 t1 = *(__nv_bfloat162*)&q.y;
        __nv_bfloat162 t2 = *(__nv_bfloat162*)&q.z;
        __nv_bfloat162 t3 = *(__nv_bfloat162*)&q.w;
        ah0 += __bfloat162float(t0.x); al0 += __bfloat162float(t0.y);
        ah1 += __bfloat162float(t1.x); al1 += __bfloat162float(t1.y);
        ah2 += __bfloat162float(t2.x); al2 += __bfloat162float(t2.y);
        ah3 += __bfloat162float(t3.x); al3 += __bfloat162float(t3.y);
    }
    bf16 h0, l0, h1, l1, h2, l2, h3, l3;
    split_pair(ah0 + al0, h0, l0);
    split_pair(ah1 + al1, h1, l1);
    split_pair(ah2 + al2, h2, l2);
    split_pair(ah3 + al3, h3, l3);
    const size_t o = (size_t)n * 128 + 64 + h4;
    *(__nv_bfloat162*)&a2h[o]     = __nv_bfloat162(h0, h1);
    *(__nv_bfloat162*)&a2h[o + 2] = __nv_bfloat162(h2, h3);
    *(__nv_bfloat162*)&a2l[o]     = __nv_bfloat162(l0, l1);
    *(__nv_bfloat162*)&a2l[o + 2] = __nv_bfloat162(l2, l3);
}

// ============================================================
extern "C" void kernel_launch(void* const* d_in, const int* in_sizes, int n_in,
                              void* d_out, int out_size)
{
    const float* x      = (const float*)d_in[0];
    const int*   ei     = (const int*)d_in[1];
    const int*   et     = (const int*)d_in[3];
    const float* umask  = (const float*)d_in[5];
    const float* basis  = (const float*)d_in[8];
    const float* comp   = (const float*)d_in[9];
    const float* root   = (const float*)d_in[10];
    const float* bias1  = (const float*)d_in[11];
    const float* w_nbr  = (const float*)d_in[12];
    const float* w_root = (const float*)d_in[13];
    const float* bias2  = (const float*)d_in[14];
    const float* Wm     = (const float*)d_in[15];
    const float* bm     = (const float*)d_in[16];
    const float* Wl     = (const float*)d_in[17];
    const float* bl     = (const float*)d_in[18];
    const float* Ws     = (const float*)d_in[19];
    const float* bs     = (const float*)d_in[20];
    float* out = (float*)d_out;

#define SYM(T, v, s) T* v; cudaGetSymbolAddress((void**)&v, s)
    SYM(bf16, WtTh, g_WtTh); SYM(bf16, WtTl, g_WtTl);
    SYM(bf16, rootTh, g_rootTh); SYM(bf16, rootTl, g_rootTl);
    SYM(bf16, wcatTh, g_wcatTh); SYM(bf16, wcatTl, g_wcatTl);
    SYM(bf16, WmTh, g_WmTh); SYM(bf16, WmTl, g_WmTl);
    SYM(bf16, WlTh, g_WlTh); SYM(bf16, WlTl, g_WlTl);
    SYM(bf16, emoh, g_emoh); SYM(bf16, emol, g_emol);
    SYM(bf16, a2h, g_a2h); SYM(bf16, a2l, g_a2l);
    SYM(u32, h1p, g_h1p);
    SYM(bf16, Qh, g_Qh); SYM(bf16, Ql, g_Ql);
    SYM(bf16, Sh, g_Sh); SYM(bf16, Sl, g_Sl);
    SYM(bf16, eWTh, g_eWTh); SYM(bf16, eWTl, g_eWTl);
    SYM(float, xw, g_xw); SYM(float, agg, g_agg);
    SYM(int, cur, g_cur); SYM(int, eidx, g_eidx);
#undef SYM

    const int SZ_128_64 = 512 + 2 * 2 * (128 + 64) * 128;   // 98816
    const int SZ_64_128 = 512 + 2 * 2 * (64 + 128) * 128;   // 98816
    const int SZ_64_64  = 512 + 2 * 2 * (64 + 64) * 128;    // 66048

#define SETSM(KERN, SZ) cudaFuncSetAttribute((const void*)(KERN), \
    cudaFuncAttributeMaxDynamicSharedMemorySize, SZ)
    SETSM((mmt<128, 64, 128, false, false, false, false, false, false>), SZ_128_64);
    SETSM((mmt<64, 64, 128, true,  true,  false, true,  false, false>),  SZ_64_64);
    SETSM((mmt<64, 64, 128, false, true,  false, true,  false, false>),  SZ_64_64);
    SETSM((mmt<128, 64, 128, false, true,  false, true,  false, false>), SZ_128_64);
    SETSM((mmt<64, 64, 128, false, false, false, true,  true,  false>),  SZ_64_64);
    SETSM((mmt<128, 64, 128, false, true,  true,  false, false, true>),  SZ_128_64);
    SETSM(scores_softmax, SZ_64_128);
#undef SETSM

    // ---- merged prep (1 launch) ----
    prep_kernel<<<(4194304 + 524288 + 409600) / 256, 256>>>(
        x, emoh, emol, comp, basis, WtTh, WtTl,
        root, rootTh, rootTl, w_root, w_nbr, wcatTh, wcatTl,
        Wm, WmTh, WmTl, Wl, WlTh, WlTl);

    // ---- edge layout: memset + fill ----
    cudaMemsetAsync(cur, 0, NND * sizeof(int));
    fill_kernel<<<NE / 256, 256>>>(ei, et, cur, eidx);

    // xw = x @ Wt  (A = emo cols [0,512), lda=576)
    mmt<128, 64, 128, false, false, false, false, false, false>
        <<<dim3(16, 64, 1), 128, SZ_128_64>>>(
        emoh, emol, NDm, 0, WtTh, WtTl, 512, 0,
        xw, nullptr, nullptr, nullptr, 1024, 0, nullptr, 0, nullptr,
        nullptr, nullptr, 512);

    rgcn_gather<<<NND / 16, 256>>>(cur, eidx, xw, agg);

    // h1 = agg + x@root + bias1 -> a2 cols [0,64) pairs + packed h1p
    mmt<64, 64, 128, true, true, false, true, false, false>
        <<<dim3(1, 128, 1), 128, SZ_64_64>>>(
        emoh, emol, NDm, 0, rootTh, rootTl, 512, 0,
        nullptr, a2h, a2l, h1p, 128, 0, agg, 64, bias1,
        nullptr, nullptr, 512);

    gc_gather<<<NND / 16, 256>>>(cur, eidx, h1p, a2h, a2l);

    // h2 = [h1 | aggH1] @ [w_root; w_nbr] + bias2 -> emo cols [512,576)
    mmt<64, 64, 128, false, true, false, true, false, false>
        <<<dim3(1, 128, 1), 128, SZ_64_64>>>(
        a2h, a2l, 128, 0, wcatTh, wcatTl, 128, 0,
        nullptr, emoh + NF, emol + NF, nullptr, NDm, 0, nullptr, 0, bias2,
        nullptr, nullptr, 128);

    // Q = emo @ Wm + bm -> pairs
    mmt<128, 64, 128, false, true, false, true, false, false>
        <<<dim3(9, 64, 1), 128, SZ_128_64>>>(
        emoh, emol, NDm, 0, WmTh, WmTl, NDm, 0,
        nullptr, Qh, Ql, nullptr, NDm, 0, nullptr, 0, bm,
        nullptr, nullptr, NDm);

    // eW = emo @ Wl -> per-conversation TRANSPOSED pairs eWT[b][n][q]
    mmt<64, 64, 128, false, false, false, true, true, false>
        <<<dim3(1, 128, 1), 128, SZ_64_64>>>(
        emoh, emol, NDm, 0, WlTh, WlTl, NDm, 0,
        nullptr, eWTh, eWTl, nullptr, 0, 0, nullptr, 0, nullptr,
        nullptr, nullptr, NDm);

    // fused scores + softmax -> bf16 pairs
    scores_softmax<<<dim3(1, 2, NBc), 128, SZ_64_128>>>(
        Qh, Ql, emoh, emol, umask, Sh, Sl);

    // hidden = relu(alpha @ eWT + bl) -> FUSED head -> out
    mmt<128, 64, 128, false, true, true, false, false, true>
        <<<dim3(1, 1, NBc), 128, SZ_128_64>>>(
        Sh, Sl, NL, (long long)NL * NL, eWTh, eWTl, NL, (long long)NH * NL,
        out, nullptr, nullptr, nullptr, NH, 0, nullptr, 0, bl,
        Ws, bs, NL);

    (void)in_sizes; (void)n_in; (void)out_size;
}

// round 16
// speedup vs baseline: 1.2577x; 1.0151x over previous
#include <cuda_runtime.h>
#include <cuda_bf16.h>
#include <math.h>
#include <cstdint>

// ---- problem constants ----
#define NND 8192
#define NF  512
#define NH  64
#define NRel 16
#define NBase 30
#define NE  524288
#define NBc 64
#define NL  128
#define NDm 576
#define NC  7
#define KC  64          // K chunk (bf16) per pipeline stage; 128B rows
#define MAXD 192        // padded slots per node (mean deg 64, sigma 8)

typedef __nv_bfloat16 bf16;
typedef unsigned int u32;

// ---- static device scratch ----
__device__ __align__(16) bf16 g_WtTh[1024 * 512];
__device__ __align__(16) bf16 g_WtTl[1024 * 512];
__device__ __align__(16) bf16 g_rootTh[64 * 512];
__device__ __align__(16) bf16 g_rootTl[64 * 512];
__device__ __align__(16) bf16 g_wcatTh[64 * 128];
__device__ __align__(16) bf16 g_wcatTl[64 * 128];
__device__ __align__(16) bf16 g_WmTh[576 * 576];
__device__ __align__(16) bf16 g_WmTl[576 * 576];
__device__ __align__(16) bf16 g_WlTh[64 * 576];
__device__ __align__(16) bf16 g_WlTl[64 * 576];
__device__ __align__(16) bf16 g_emoh[(size_t)NND * NDm];
__device__ __align__(16) bf16 g_emol[(size_t)NND * NDm];
__device__ __align__(16) bf16 g_a2h[NND * 128];
__device__ __align__(16) bf16 g_a2l[NND * 128];
__device__ __align__(16) u32  g_h1p[NND * NH];
__device__ __align__(16) bf16 g_Qh[(size_t)NND * NDm];
__device__ __align__(16) bf16 g_Ql[(size_t)NND * NDm];
__device__ __align__(16) bf16 g_Sh[NND * NL];
__device__ __align__(16) bf16 g_Sl[NND * NL];
__device__ __align__(16) bf16 g_eWTh[NBc * NH * NL];
__device__ __align__(16) bf16 g_eWTl[NBc * NH * NL];

__device__ __align__(16) float g_xw[(size_t)NND * NRel * NH];
__device__ __align__(16) float g_agg[NND * NH];
// padded edge slots
__device__ int g_cur[NND];
__device__ int g_eidx[(size_t)NND * MAXD];

__device__ __forceinline__ void split_pair(float v, bf16& h, bf16& l) {
    h = __float2bfloat16(v);
    l = __float2bfloat16(v - __bfloat162float(h));
}

__device__ __forceinline__ u32 smem_u32(const void* p) {
    u32 a;
    asm("{ .reg .u64 t; cvta.to.shared.u64 t, %1; cvt.u32.u64 %0, t; }"
        : "=r"(a) : "l"(p));
    return a;
}

__device__ __forceinline__ void mma16816(float* d, const u32* a, const u32* b) {
    asm volatile(
        "mma.sync.aligned.m16n8k16.row.col.f32.bf16.bf16.f32 "
        "{%0,%1,%2,%3}, {%4,%5,%6,%7}, {%8,%9}, {%0,%1,%2,%3};"
        : "+f"(d[0]), "+f"(d[1]), "+f"(d[2]), "+f"(d[3])
        : "r"(a[0]), "r"(a[1]), "r"(a[2]), "r"(a[3]), "r"(b[0]), "r"(b[1]));
}

#define LDSM4(r, addr) \
    asm volatile("ldmatrix.sync.aligned.m8n8.x4.shared.b16 {%0,%1,%2,%3}, [%4];" \
        : "=r"((r)[0]), "=r"((r)[1]), "=r"((r)[2]), "=r"((r)[3]) : "r"(addr))

#define CPA(d, s) \
    asm volatile("cp.async.cg.shared.global [%0], [%1], 16;" :: "r"(d), "l"(s) : "memory")
#define CPC() asm volatile("cp.async.commit_group;" ::: "memory")
#define CPW0() asm volatile("cp.async.wait_group 0;" ::: "memory")

// ============================================================
// Pipelined warp-MMA 3xBF16 GEMM: C[M,N] = A @ B^T
// ============================================================
template <int BM, int NT, int THREADS,
          bool ADD_D, bool BIAS, bool RELU, bool OUT_PAIR, bool OUT_T, bool HEAD>
__global__ void __launch_bounds__(THREADS, 2)
mmt(const bf16* __restrict__ Ah, const bf16* __restrict__ Al, int lda, long long sA,
    const bf16* __restrict__ Bh, const bf16* __restrict__ Bl, int ldb, long long sB,
    float* __restrict__ C, bf16* __restrict__ Ch, bf16* __restrict__ Cl,
    u32* __restrict__ Cp,
    int ldc, long long sC,
    const float* __restrict__ D, int ldd,
    const float* __restrict__ bias,
    const float* __restrict__ Ws, const float* __restrict__ bsv,
    int K)
{
    constexpr int WARPS = THREADS / 32;
    constexpr int WN = NT / 64;
    constexpr int WMC = WARPS / WN;
    constexpr int WM = BM / WMC;
    constexpr int MI = WM / 16;
    constexpr int STAGE_ROWS = 2 * (BM + NT);
    constexpr int STAGE_B = STAGE_ROWS * 128;
    constexpr int CHUNKS = STAGE_ROWS * 8 / THREADS;

    extern __shared__ char smem[];
    const u32 sb0 = smem_u32(smem) + 512;

    const int tid = threadIdx.x;
    const int wid = tid >> 5, lane = tid & 31;
    const int warpM = wid % WMC, warpN = wid / WMC;
    const int bz = blockIdx.z;
    const int m0 = blockIdx.y * BM;
    const int n0 = blockIdx.x * NT;

    const char* pAh = (const char*)(Ah + sA * bz + (size_t)m0 * lda);
    const char* pAl = (const char*)(Al + sA * bz + (size_t)m0 * lda);
    const char* pBh = (const char*)(Bh + sB * bz + (size_t)n0 * ldb);
    const char* pBl = (const char*)(Bl + sB * bz + (size_t)n0 * ldb);
    const size_t ldab = (size_t)lda * 2;
    const size_t ldbb = (size_t)ldb * 2;

    float acc[MI][8][4];
#pragma unroll
    for (int i = 0; i < MI; i++)
#pragma unroll
        for (int j = 0; j < 8; j++)
#pragma unroll
            for (int q = 0; q < 4; q++) acc[i][j][q] = 0.f;

    const int S = K / KC;

    auto load_stage = [&](int s) {
        const size_t kcb = (size_t)s * KC * 2;
        const u32 dst0 = sb0 + (u32)(s & 1) * STAGE_B;
#pragma unroll
        for (int f = 0; f < CHUNKS; f++) {
            int idx = tid + f * THREADS;
            int row = idx >> 3;
            u32 cb = (u32)(idx & 7) << 4;
            u32 sw = cb ^ (((u32)(row & 7)) << 4);
            const char* src;
            if (row < BM)               src = pAh + (size_t)row * ldab + kcb + cb;
            else if (row < 2 * BM)      src = pAl + (size_t)(row - BM) * ldab + kcb + cb;
            else if (row < 2 * BM + NT) src = pBh + (size_t)(row - 2 * BM) * ldbb + kcb + cb;
            else                        src = pBl + (size_t)(row - 2 * BM - NT) * ldbb + kcb + cb;
            CPA(dst0 + (u32)row * 128 + sw, src);
        }
    };

    load_stage(0);
    CPC();

    const u32 xorv = ((u32)(lane & 7)) << 4;
    const u32 aRow = (u32)(warpM * WM + (lane & 15));
    const u32 aCol0 = ((u32)(lane >> 4) & 1) * 16;
    const u32 bRow = (u32)(warpN * 64 + ((lane & 7) | ((lane & 16) >> 1)));
    const u32 bCol0 = ((u32)(lane >> 3) & 1) * 16;

    for (int s = 0; s < S; s++) {
        CPW0();
        __syncthreads();
        if (s + 1 < S) { load_stage(s + 1); CPC(); }

        const u32 base = sb0 + (u32)(s & 1) * STAGE_B;
        const u32 aH = base + aRow * 128;
        const u32 aL = aH + (u32)BM * 128;
        const u32 bH = base + (u32)(2 * BM) * 128 + bRow * 128;
        const u32 bL = bH + (u32)NT * 128;

#pragma unroll
        for (int ks = 0; ks < KC / 16; ks++) {
            const u32 kb = (u32)ks * 32;
            const u32 acol = (aCol0 + kb) ^ xorv;
            const u32 bcol = (bCol0 + kb) ^ xorv;
            u32 ah[MI][4], al[MI][4];
#pragma unroll
            for (int mi = 0; mi < MI; mi++) {
                LDSM4(ah[mi], aH + (u32)mi * (16 * 128) + acol);
                LDSM4(al[mi], aL + (u32)mi * (16 * 128) + acol);
            }
#pragma unroll
            for (int nt = 0; nt < 4; nt++) {
                u32 bh[4], bl[4];
                LDSM4(bh, bH + (u32)nt * (16 * 128) + bcol);
                LDSM4(bl, bL + (u32)nt * (16 * 128) + bcol);
#pragma unroll
                for (int mi = 0; mi < MI; mi++)
#pragma unroll
                    for (int half = 0; half < 2; half++) {
                        float* a4 = acc[mi][nt * 2 + half];
                        mma16816(a4, ah[mi], &bh[half * 2]);
                        mma16816(a4, ah[mi], &bl[half * 2]);
                        mma16816(a4, al[mi], &bh[half * 2]);
                    }
            }
        }
    }

    if (HEAD) {
        __syncthreads();
        float* wss = (float*)smem;
        for (int i = tid; i < NH * NC + NC; i += THREADS)
            wss[i] = (i < NH * NC) ? Ws[i] : bsv[i - NH * NC];
        __syncthreads();
        const int tg = lane & 3;
#pragma unroll
        for (int mi = 0; mi < MI; mi++) {
#pragma unroll
            for (int half = 0; half < 2; half++) {
                const int m = m0 + warpM * WM + mi * 16 + (lane >> 2) + half * 8;
                float lg[NC];
#pragma unroll
                for (int c = 0; c < NC; c++) lg[c] = 0.f;
#pragma unroll
                for (int ni = 0; ni < 8; ni++) {
                    const int n = ni * 8 + tg * 2;
                    float v0 = acc[mi][ni][half * 2];
                    float v1 = acc[mi][ni][half * 2 + 1];
                    if (BIAS) { v0 += bias[n]; v1 += bias[n + 1]; }
                    if (RELU) { v0 = fmaxf(v0, 0.f); v1 = fmaxf(v1, 0.f); }
#pragma unroll
                    for (int c = 0; c < NC; c++)
                        lg[c] = fmaf(v0, wss[n * NC + c],
                                     fmaf(v1, wss[(n + 1) * NC + c], lg[c]));
                }
#pragma unroll
                for (int o = 1; o < 4; o <<= 1)
#pragma unroll
                    for (int c = 0; c < NC; c++)
                        lg[c] += __shfl_xor_sync(0xffffffffu, lg[c], o);
                if (tg == 0) {
#pragma unroll
                    for (int c = 0; c < NC; c++) lg[c] += wss[NH * NC + c];
                    float mx = lg[0];
#pragma unroll
                    for (int c = 1; c < NC; c++) mx = fmaxf(mx, lg[c]);
                    float ssum = 0.f;
#pragma unroll
                    for (int c = 0; c < NC; c++) ssum += expf(lg[c] - mx);
                    float lse = mx + logf(ssum);
                    const size_t o0 = (size_t)(bz * NL + m) * NC;
#pragma unroll
                    for (int c = 0; c < NC; c++) C[o0 + c] = lg[c] - lse;
                }
            }
        }
        return;
    }

    // ---- standard epilogue ----
#pragma unroll
    for (int mi = 0; mi < MI; mi++) {
        const int rm = m0 + warpM * WM + mi * 16 + (lane >> 2);
#pragma unroll
        for (int ni = 0; ni < 8; ni++) {
            const int n = n0 + warpN * 64 + ni * 8 + (lane & 3) * 2;
#pragma unroll
            for (int half = 0; half < 2; half++) {
                const int m = rm + half * 8;
                float v0 = acc[mi][ni][half * 2];
                float v1 = acc[mi][ni][half * 2 + 1];
                if (BIAS) { v0 += bias[n]; v1 += bias[n + 1]; }
                if (ADD_D) {
                    v0 += D[(size_t)m * ldd + n];
                    v1 += D[(size_t)m * ldd + n + 1];
                }
                if (RELU) { v0 = fmaxf(v0, 0.f); v1 = fmaxf(v1, 0.f); }
                if (OUT_PAIR) {
                    bf16 h0, l0, h1c, l1c;
                    split_pair(v0, h0, l0);
                    split_pair(v1, h1c, l1c);
                    if (OUT_T) {
                        size_t o = ((size_t)(m >> 7) * 64 + n) * 128 + (m & 127);
                        Ch[o] = h0; Ch[o + 128] = h1c;
                        Cl[o] = l0; Cl[o + 128] = l1c;
                    } else {
                        const size_t o = (size_t)sC * bz + (size_t)m * ldc + n;
                        *(__nv_bfloat162*)&Ch[o] = __nv_bfloat162(h0, h1c);
                        *(__nv_bfloat162*)&Cl[o] = __nv_bfloat162(l0, l1c);
                        if (Cp) {
                            __nv_bfloat162 p0(h0, l0), p1(h1c, l1c);
                            uint2 u; u.x = *(u32*)&p0; u.y = *(u32*)&p1;
                            *(uint2*)&Cp[(size_t)m * 64 + n] = u;
                        }
                    }
                } else {
                    float2 f2; f2.x = v0; f2.y = v1;
                    *(float2*)&C[(size_t)sC * bz + (size_t)m * ldc + n] = f2;
                }
            }
        }
    }
}

// ============================================================
// Fused scores kernel: S = tanh((Q.M)*u^2) -> softmax -> *u -> renorm
// ============================================================
__global__ void __launch_bounds__(128, 2)
scores_softmax(const bf16* __restrict__ Qh, const bf16* __restrict__ Ql,
               const bf16* __restrict__ Mh, const bf16* __restrict__ Ml,
               const float* __restrict__ um,
               bf16* __restrict__ Sh, bf16* __restrict__ Sl)
{
    constexpr int BM = 64, NT = 128, THREADS = 128;
    constexpr int STAGE_ROWS = 2 * (BM + NT);
    constexpr int STAGE_B = STAGE_ROWS * 128;
    constexpr int CHUNKS = STAGE_ROWS * 8 / THREADS;

    extern __shared__ char smem[];
    float* ums = (float*)smem;
    float* sbuf = (float*)(smem + 512);
    const u32 sb0 = smem_u32(smem) + 512;

    const int tid = threadIdx.x;
    const int wid = tid >> 5, lane = tid & 31;
    const int warpM = wid & 1, warpN = wid >> 1;
    const int bz = blockIdx.z;
    const int m0 = blockIdx.y * BM;

    const char* pAh = (const char*)(Qh + (size_t)bz * NL * NDm + (size_t)m0 * NDm);
    const char* pAl = (const char*)(Ql + (size_t)bz * NL * NDm + (size_t)m0 * NDm);
    const char* pBh = (const char*)(Mh + (size_t)bz * NL * NDm);
    const char* pBl = (const char*)(Ml + (size_t)bz * NL * NDm);
    const size_t ldab = (size_t)NDm * 2;

    if (tid < NT) ums[tid] = um[bz * NL + tid];

    float acc[2][8][4];
#pragma unroll
    for (int i = 0; i < 2; i++)
#pragma unroll
        for (int j = 0; j < 8; j++)
#pragma unroll
            for (int q = 0; q < 4; q++) acc[i][j][q] = 0.f;

    const int S = NDm / KC;

    auto load_stage = [&](int s) {
        const size_t kcb = (size_t)s * KC * 2;
        const u32 dst0 = sb0 + (u32)(s & 1) * STAGE_B;
#pragma unroll
        for (int f = 0; f < CHUNKS; f++) {
            int idx = tid + f * THREADS;
            int row = idx >> 3;
            u32 cb = (u32)(idx & 7) << 4;
            u32 sw = cb ^ (((u32)(row & 7)) << 4);
            const char* src;
            if (row < BM)               src = pAh + (size_t)row * ldab + kcb + cb;
            else if (row < 2 * BM)      src = pAl + (size_t)(row - BM) * ldab + kcb + cb;
            else if (row < 2 * BM + NT) src = pBh + (size_t)(row - 2 * BM) * ldab + kcb + cb;
            else                        src = pBl + (size_t)(row - 2 * BM - NT) * ldab + kcb + cb;
            CPA(dst0 + (u32)row * 128 + sw, src);
        }
    };

    load_stage(0);
    CPC();

    const u32 xorv = ((u32)(lane & 7)) << 4;
    const u32 aRow = (u32)(warpM * 32 + (lane & 15));
    const u32 aCol0 = ((u32)(lane >> 4) & 1) * 16;
    const u32 bRow = (u32)(warpN * 64 + ((lane & 7) | ((lane & 16) >> 1)));
    const u32 bCol0 = ((u32)(lane >> 3) & 1) * 16;

    for (int s = 0; s < S; s++) {
        CPW0();
        __syncthreads();
        if (s + 1 < S) { load_stage(s + 1); CPC(); }

        const u32 base = sb0 + (u32)(s & 1) * STAGE_B;
        const u32 aH = base + aRow * 128;
        const u32 aL = aH + (u32)BM * 128;
        const u32 bH = base + (u32)(2 * BM) * 128 + bRow * 128;
        const u32 bL = bH + (u32)NT * 128;

#pragma unroll
        for (int ks = 0; ks < KC / 16; ks++) {
            const u32 kb = (u32)ks * 32;
            const u32 acol = (aCol0 + kb) ^ xorv;
            const u32 bcol = (bCol0 + kb) ^ xorv;
            u32 ah[2][4], al[2][4];
#pragma unroll
            for (int mi = 0; mi < 2; mi++) {
                LDSM4(ah[mi], aH + (u32)mi * (16 * 128) + acol);
                LDSM4(al[mi], aL + (u32)mi * (16 * 128) + acol);
            }
#pragma unroll
            for (int nt = 0; nt < 4; nt++) {
                u32 bh[4], bl[4];
                LDSM4(bh, bH + (u32)nt * (16 * 128) + bcol);
                LDSM4(bl, bL + (u32)nt * (16 * 128) + bcol);
#pragma unroll
                for (int mi = 0; mi < 2; mi++)
#pragma unroll
                    for (int half = 0; half < 2; half++) {
                        float* a4 = acc[mi][nt * 2 + half];
                        mma16816(a4, ah[mi], &bh[half * 2]);
                        mma16816(a4, ah[mi], &bl[half * 2]);
                        mma16816(a4, al[mi], &bh[half * 2]);
                    }
            }
        }
    }
    __syncthreads();

#pragma unroll
    for (int mi = 0; mi < 2; mi++) {
#pragma unroll
        for (int ni = 0; ni < 8; ni++) {
            const int col = warpN * 64 + ni * 8 + (lane & 3) * 2;
            const float u0 = ums[col], u1 = ums[col + 1];
#pragma unroll
            for (int half = 0; half < 2; half++) {
                const int row = warpM * 32 + mi * 16 + (lane >> 2) + half * 8;
                float v0 = tanhf(acc[mi][ni][half * 2] * u0 * u0);
                float v1 = tanhf(acc[mi][ni][half * 2 + 1] * u1 * u1);
                float2 f2; f2.x = v0; f2.y = v1;
                *(float2*)&sbuf[row * 132 + col] = f2;
            }
        }
    }
    __syncthreads();

    for (int r8 = 0; r8 < 16; r8++) {
        const int row = wid * 16 + r8;
        float4 v = *(const float4*)&sbuf[row * 132 + lane * 4];
        float mx = fmaxf(fmaxf(v.x, v.y), fmaxf(v.z, v.w));
#pragma unroll
        for (int o = 16; o > 0; o >>= 1)
            mx = fmaxf(mx, __shfl_xor_sync(0xffffffffu, mx, o));
        float e0 = expf(v.x - mx), e1 = expf(v.y - mx);
        float e2 = expf(v.z - mx), e3 = expf(v.w - mx);
        float sum1 = e0 + e1 + e2 + e3;
#pragma unroll
        for (int o = 16; o > 0; o >>= 1)
            sum1 += __shfl_xor_sync(0xffffffffu, sum1, o);
        const int col = lane * 4;
        float a0 = (e0 / sum1) * ums[col];
        float a1 = (e1 / sum1) * ums[col + 1];
        float a2 = (e2 / sum1) * ums[col + 2];
        float a3 = (e3 / sum1) * ums[col + 3];
        float sum2 = a0 + a1 + a2 + a3;
#pragma unroll
        for (int o = 16; o > 0; o >>= 1)
            sum2 += __shfl_xor_sync(0xffffffffu, sum2, o);
        float inv = 1.f / sum2;
        bf16 h0, l0, h1, l1, h2, l2, h3, l3;
        split_pair(a0 * inv, h0, l0);
        split_pair(a1 * inv, h1, l1);
        split_pair(a2 * inv, h2, l2);
        split_pair(a3 * inv, h3, l3);
        const size_t o0 = (size_t)(bz * NL + m0 + row) * NL + col;
        *(__nv_bfloat162*)&Sh[o0]     = __nv_bfloat162(h0, h1);
        *(__nv_bfloat162*)&Sh[o0 + 2] = __nv_bfloat162(h2, h3);
        *(__nv_bfloat162*)&Sl[o0]     = __nv_bfloat162(l0, l1);
        *(__nv_bfloat162*)&Sl[o0 + 2] = __nv_bfloat162(l2, l3);
    }
}

// ============================================================
// merged prep kernel: cvtx + wt + tcvt in one launch
// ============================================================
__global__ void prep_kernel(
    const float* __restrict__ x, bf16* __restrict__ eh, bf16* __restrict__ el,
    const float* __restrict__ comp, const float* __restrict__ basis,
    bf16* __restrict__ Wh, bf16* __restrict__ Wl,
    const float* __restrict__ root, bf16* __restrict__ rTh, bf16* __restrict__ rTl,
    const float* __restrict__ wr, const float* __restrict__ wn,
    bf16* __restrict__ wcTh, bf16* __restrict__ wcTl,
    const float* __restrict__ Wm, bf16* __restrict__ WmTh, bf16* __restrict__ WmTl,
    const float* __restrict__ Wl2, bf16* __restrict__ WlTh, bf16* __restrict__ WlTl)
{
    int i = blockIdx.x * 256 + threadIdx.x;
    if (i < 4194304) {
        bf16 h, l; split_pair(x[i], h, l);
        int row = i >> 9, c = i & 511;
        size_t eo = (size_t)row * NDm + c;
        eh[eo] = h; el[eo] = l;
    } else if (i < 4718592) {
        int idx = i - 4194304;
        int h = idx & 63, rr = (idx >> 6) & 15, k = idx >> 10;
        float acc = 0.f;
#pragma unroll
        for (int b = 0; b < NBase; b++)
            acc = fmaf(comp[rr * NBase + b], basis[((size_t)b * NF + k) * NH + h], acc);
        bf16 hh, ll; split_pair(acc, hh, ll);
        size_t o = (size_t)(rr * 64 + h) * 512 + k;
        Wh[o] = hh; Wl[o] = ll;
    } else {
        int j = i - 4718592;
        if (j < 32768) {
            int rr = j / 64, cc = j % 64;
            bf16 h, l; split_pair(root[j], h, l);
            rTh[(size_t)cc * 512 + rr] = h; rTl[(size_t)cc * 512 + rr] = l;
        } else if (j < 36864) {
            int q = j - 32768, rr = q / 64, cc = q % 64;
            bf16 h, l; split_pair(wr[q], h, l);
            wcTh[cc * 128 + rr] = h; wcTl[cc * 128 + rr] = l;
        } else if (j < 40960) {
            int q = j - 36864, rr = q / 64, cc = q % 64;
            bf16 h, l; split_pair(wn[q], h, l);
            wcTh[cc * 128 + 64 + rr] = h; wcTl[cc * 128 + 64 + rr] = l;
        } else if (j < 372736) {
            int q = j - 40960, rr = q / 576, cc = q % 576;
            bf16 h, l; split_pair(Wm[q], h, l);
            WmTh[(size_t)cc * 576 + rr] = h; WmTl[(size_t)cc * 576 + rr] = l;
        } else if (j < 409600) {
            int q = j - 372736, rr = q / 64, cc = q % 64;
            bf16 h, l; split_pair(Wl2[q], h, l);
            WlTh[(size_t)cc * 576 + rr] = h; WlTl[(size_t)cc * 576 + rr] = l;
        }
    }
}

// ---- edge fill: store precomputed element offset src*1024 + rel*64 ----
__global__ void fill_kernel(const int* __restrict__ ei, const int* __restrict__ et,
                            int* __restrict__ cur, int* __restrict__ eidx)
{
    int i = blockIdx.x * 256 + threadIdx.x;
    if (i >= NE) return;
    int dst = ei[NE + i];
    int pos = atomicAdd(&cur[dst], 1);
    eidx[(size_t)dst * MAXD + pos] = (ei[i] << 10) + (et[i] << 6);
}

// ---- gathers: 16 threads/node, float4 per thread, 4-way unroll ----
__global__ void __launch_bounds__(256)
rgcn_gather(const int* __restrict__ cur, const int* __restrict__ eidx,
            const float* __restrict__ xw, float* __restrict__ agg)
{
    const int n = blockIdx.x * 16 + (threadIdx.x >> 4);
    const int h4 = (threadIdx.x & 15) * 4;
    const int cntn = cur[n];
    const int* ep = eidx + n * MAXD;
    float4 a0 = {0.f, 0.f, 0.f, 0.f}, a1 = {0.f, 0.f, 0.f, 0.f};
    float4 a2 = {0.f, 0.f, 0.f, 0.f}, a3 = {0.f, 0.f, 0.f, 0.f};
    int e = 0;
    for (; e + 4 <= cntn; e += 4) {
        int p0 = ep[e], p1 = ep[e + 1], p2 = ep[e + 2], p3 = ep[e + 3];
        float4 v0 = *(const float4*)(xw + p0 + h4);
        float4 v1 = *(const float4*)(xw + p1 + h4);
        float4 v2 = *(const float4*)(xw + p2 + h4);
        float4 v3 = *(const float4*)(xw + p3 + h4);
        a0.x += v0.x; a0.y += v0.y; a0.z += v0.z; a0.w += v0.w;
        a1.x += v1.x; a1.y += v1.y; a1.z += v1.z; a1.w += v1.w;
        a2.x += v2.x; a2.y += v2.y; a2.z += v2.z; a2.w += v2.w;
        a3.x += v3.x; a3.y += v3.y; a3.z += v3.z; a3.w += v3.w;
    }
    for (; e < cntn; e++) {
        float4 v = *(const float4*)(xw + ep[e] + h4);
        a0.x += v.x; a0.y += v.y; a0.z += v.z; a0.w += v.w;
    }
    float inv = 1.f / fmaxf((float)cntn, 1.f);
    float4 r;
    r.x = ((a0.x + a1.x) + (a2.x + a3.x)) * inv;
    r.y = ((a0.y + a1.y) + (a2.y + a3.y)) * inv;
    r.z = ((a0.z + a1.z) + (a2.z + a3.z)) * inv;
    r.w = ((a0.w + a1.w) + (a2.w + a3.w)) * inv;
    *(float4*)&agg[n * NH + h4] = r;
}

__global__ void __launch_bounds__(256)
gc_gather(const int* __restrict__ cur, const int* __restrict__ eidx,
          const u32* __restrict__ h1p, bf16* __restrict__ a2h, bf16* __restrict__ a2l)
{
    const int n = blockIdx.x * 16 + (threadIdx.x >> 4);
    const int h4 = (threadIdx.x & 15) * 4;
    const int cntn = cur[n];
    const int* ep = eidx + n * MAXD;
    float sh[4] = {0.f, 0.f, 0.f, 0.f};
    float sl[4] = {0.f, 0.f, 0.f, 0.f};
    int e = 0;
    for (; e + 4 <= cntn; e += 4) {
        uint4 q0 = *(const uint4*)(h1p + ((ep[e]     >> 4) & ~63) + h4);
        uint4 q1 = *(const uint4*)(h1p + ((ep[e + 1] >> 4) & ~63) + h4);
        uint4 q2 = *(const uint4*)(h1p + ((ep[e + 2] >> 4) & ~63) + h4);
        uint4 q3 = *(const uint4*)(h1p + ((ep[e + 3] >> 4) & ~63) + h4);
        const u32* qs[4] = {&q0.x, &q1.x, &q2.x, &q3.x};
#pragma unroll
        for (int u = 0; u < 4; u++)
#pragma unroll
            for (int w = 0; w < 4; w++) {
                __nv_bfloat162 t = *(__nv_bfloat162*)&qs[u][w];
                sh[w] += __bfloat162float(t.x);
                sl[w] += __bfloat162float(t.y);
            }
    }
    for (; e < cntn; e++) {
        uint4 q = *(const uint4*)(h1p + ((ep[e] >> 4) & ~63) + h4);
        const u32* qw = &q.x;
#pragma unroll
        for (int w = 0; w < 4; w++) {
            __nv_bfloat162 t = *(__nv_bfloat162*)&qw[w];
            sh[w] += __bfloat162float(t.x);
            sl[w] += __bfloat162float(t.y);
        }
    }
    bf16 h0, l0, h1, l1, h2, l2, h3, l3;
    split_pair(sh[0] + sl[0], h0, l0);
    split_pair(sh[1] + sl[1], h1, l1);
    split_pair(sh[2] + sl[2], h2, l2);
    split_pair(sh[3] + sl[3], h3, l3);
    const size_t o = (size_t)n * 128 + 64 + h4;
    *(__nv_bfloat162*)&a2h[o]     = __nv_bfloat162(h0, h1);
    *(__nv_bfloat162*)&a2h[o + 2] = __nv_bfloat162(h2, h3);
    *(__nv_bfloat162*)&a2l[o]     = __nv_bfloat162(l0, l1);
    *(__nv_bfloat162*)&a2l[o + 2] = __nv_bfloat162(l2, l3);
}

// ============================================================
extern "C" void kernel_launch(void* const* d_in, const int* in_sizes, int n_in,
                              void* d_out, int out_size)
{
    const float* x      = (const float*)d_in[0];
    const int*   ei     = (const int*)d_in[1];
    const int*   et     = (const int*)d_in[3];
    const float* umask  = (const float*)d_in[5];
    const float* basis  = (const float*)d_in[8];
    const float* comp   = (const float*)d_in[9];
    const float* root   = (const float*)d_in[10];
    const float* bias1  = (const float*)d_in[11];
    const float* w_nbr  = (const float*)d_in[12];
    const float* w_root = (const float*)d_in[13];
    const float* bias2  = (const float*)d_in[14];
    const float* Wm     = (const float*)d_in[15];
    const float* bm     = (const float*)d_in[16];
    const float* Wl     = (const float*)d_in[17];
    const float* bl     = (const float*)d_in[18];
    const float* Ws     = (const float*)d_in[19];
    const float* bs     = (const float*)d_in[20];
    float* out = (float*)d_out;

#define SYM(T, v, s) T* v; cudaGetSymbolAddress((void**)&v, s)
    SYM(bf16, WtTh, g_WtTh); SYM(bf16, WtTl, g_WtTl);
    SYM(bf16, rootTh, g_rootTh); SYM(bf16, rootTl, g_rootTl);
    SYM(bf16, wcatTh, g_wcatTh); SYM(bf16, wcatTl, g_wcatTl);
    SYM(bf16, WmTh, g_WmTh); SYM(bf16, WmTl, g_WmTl);
    SYM(bf16, WlTh, g_WlTh); SYM(bf16, WlTl, g_WlTl);
    SYM(bf16, emoh, g_emoh); SYM(bf16, emol, g_emol);
    SYM(bf16, a2h, g_a2h); SYM(bf16, a2l, g_a2l);
    SYM(u32, h1p, g_h1p);
    SYM(bf16, Qh, g_Qh); SYM(bf16, Ql, g_Ql);
    SYM(bf16, Sh, g_Sh); SYM(bf16, Sl, g_Sl);
    SYM(bf16, eWTh, g_eWTh); SYM(bf16, eWTl, g_eWTl);
    SYM(float, xw, g_xw); SYM(float, agg, g_agg);
    SYM(int, cur, g_cur); SYM(int, eidx, g_eidx);
#undef SYM

    const int SZ_128_64 = 512 + 2 * 2 * (128 + 64) * 128;   // 98816
    const int SZ_64_128 = 512 + 2 * 2 * (64 + 128) * 128;   // 98816
    const int SZ_64_64  = 512 + 2 * 2 * (64 + 64) * 128;    // 66048

#define SETSM(KERN, SZ) cudaFuncSetAttribute((const void*)(KERN), \
    cudaFuncAttributeMaxDynamicSharedMemorySize, SZ)
    SETSM((mmt<128, 64, 128, false, false, false, false, false, false>), SZ_128_64);
    SETSM((mmt<64, 64, 128, true,  true,  false, true,  false, false>),  SZ_64_64);
    SETSM((mmt<64, 64, 128, false, true,  false, true,  false, false>),  SZ_64_64);
    SETSM((mmt<128, 64, 128, false, true,  false, true,  false, false>), SZ_128_64);
    SETSM((mmt<64, 64, 128, false, false, false, true,  true,  false>),  SZ_64_64);
    SETSM((mmt<128, 64, 128, false, true,  true,  false, false, true>),  SZ_128_64);
    SETSM(scores_softmax, SZ_64_128);
#undef SETSM

    // ---- merged prep (1 launch) ----
    prep_kernel<<<(4194304 + 524288 + 409600) / 256, 256>>>(
        x, emoh, emol, comp, basis, WtTh, WtTl,
        root, rootTh, rootTl, w_root, w_nbr, wcatTh, wcatTl,
        Wm, WmTh, WmTl, Wl, WlTh, WlTl);

    // ---- edge layout: memset + fill ----
    cudaMemsetAsync(cur, 0, NND * sizeof(int));
    fill_kernel<<<NE / 256, 256>>>(ei, et, cur, eidx);

    // xw = x @ Wt  (A = emo cols [0,512), lda=576)
    mmt<128, 64, 128, false, false, false, false, false, false>
        <<<dim3(16, 64, 1), 128, SZ_128_64>>>(
        emoh, emol, NDm, 0, WtTh, WtTl, 512, 0,
        xw, nullptr, nullptr, nullptr, 1024, 0, nullptr, 0, nullptr,
        nullptr, nullptr, 512);

    rgcn_gather<<<NND / 16, 256>>>(cur, eidx, xw, agg);

    // h1 = agg + x@root + bias1 -> a2 cols [0,64) pairs + packed h1p
    mmt<64, 64, 128, true, true, false, true, false, false>
        <<<dim3(1, 128, 1), 128, SZ_64_64>>>(
        emoh, emol, NDm, 0, rootTh, rootTl, 512, 0,
        nullptr, a2h, a2l, h1p, 128, 0, agg, 64, bias1,
        nullptr, nullptr, 512);

    gc_gather<<<NND / 16, 256>>>(cur, eidx, h1p, a2h, a2l);

    // h2 = [h1 | aggH1] @ [w_root; w_nbr] + bias2 -> emo cols [512,576)
    mmt<64, 64, 128, false, true, false, true, false, false>
        <<<dim3(1, 128, 1), 128, SZ_64_64>>>(
        a2h, a2l, 128, 0, wcatTh, wcatTl, 128, 0,
        nullptr, emoh + NF, emol + NF, nullptr, NDm, 0, nullptr, 0, bias2,
        nullptr, nullptr, 128);

    // Q = emo @ Wm + bm -> pairs
    mmt<128, 64, 128, false, true, false, true, false, false>
        <<<dim3(9, 64, 1), 128, SZ_128_64>>>(
        emoh, emol, NDm, 0, WmTh, WmTl, NDm, 0,
        nullptr, Qh, Ql, nullptr, NDm, 0, nullptr, 0, bm,
        nullptr, nullptr, NDm);

    // eW = emo @ Wl -> per-conversation TRANSPOSED pairs eWT[b][n][q]
    mmt<64, 64, 128, false, false, false, true, true, false>
        <<<dim3(1, 128, 1), 128, SZ_64_64>>>(
        emoh, emol, NDm, 0, WlTh, WlTl, NDm, 0,
        nullptr, eWTh, eWTl, nullptr, 0, 0, nullptr, 0, nullptr,
        nullptr, nullptr, NDm);

    // fused scores + softmax -> bf16 pairs
    scores_softmax<<<dim3(1, 2, NBc), 128, SZ_64_128>>>(
        Qh, Ql, emoh, emol, umask, Sh, Sl);

    // hidden = relu(alpha @ eWT + bl) -> FUSED head -> out
    mmt<128, 64, 128, false, true, true, false, false, true>
        <<<dim3(1, 1, NBc), 128, SZ_128_64>>>(
        Sh, Sl, NL, (long long)NL * NL, eWTh, eWTl, NL, (long long)NH * NL,
        out, nullptr, nullptr, nullptr, NH, 0, nullptr, 0, bl,
        Ws, bs, NL);

    (void)in_sizes; (void)n_in; (void)out_size;
}

// round 17
// speedup vs baseline: 1.2690x; 1.0090x over previous
#include <cuda_runtime.h>
#include <cuda_bf16.h>
#include <math.h>
#include <cstdint>

// ---- problem constants ----
#define NND 8192
#define NF  512
#define NH  64
#define NRel 16
#define NBase 30
#define NE  524288
#define NBc 64
#define NL  128
#define NDm 576
#define NC  7
#define KC  64          // K chunk (bf16) per pipeline stage; 128B rows
#define MAXD 192        // padded slots per node (mean deg 64, sigma 8)

typedef __nv_bfloat16 bf16;
typedef unsigned int u32;

// ---- side stream + events for graph fork-join (created pre-checkpoint) ----
struct ForkCtx {
    cudaStream_t s2;
    cudaEvent_t evA, evB, evC, evD;
    ForkCtx() {
        cudaStreamCreateWithFlags(&s2, cudaStreamNonBlocking);
        cudaEventCreateWithFlags(&evA, cudaEventDisableTiming);
        cudaEventCreateWithFlags(&evB, cudaEventDisableTiming);
        cudaEventCreateWithFlags(&evC, cudaEventDisableTiming);
        cudaEventCreateWithFlags(&evD, cudaEventDisableTiming);
    }
};
static ForkCtx g_fork;

// ---- static device scratch ----
__device__ __align__(16) bf16 g_WtTh[1024 * 512];
__device__ __align__(16) bf16 g_WtTl[1024 * 512];
__device__ __align__(16) bf16 g_rootTh[64 * 512];
__device__ __align__(16) bf16 g_rootTl[64 * 512];
__device__ __align__(16) bf16 g_wcatTh[64 * 128];
__device__ __align__(16) bf16 g_wcatTl[64 * 128];
__device__ __align__(16) bf16 g_WmTh[576 * 576];
__device__ __align__(16) bf16 g_WmTl[576 * 576];
__device__ __align__(16) bf16 g_WlTh[64 * 576];
__device__ __align__(16) bf16 g_WlTl[64 * 576];
__device__ __align__(16) bf16 g_emoh[(size_t)NND * NDm];
__device__ __align__(16) bf16 g_emol[(size_t)NND * NDm];
__device__ __align__(16) bf16 g_a2h[NND * 128];
__device__ __align__(16) bf16 g_a2l[NND * 128];
__device__ __align__(16) u32  g_h1p[NND * NH];
__device__ __align__(16) bf16 g_Qh[(size_t)NND * NDm];
__device__ __align__(16) bf16 g_Ql[(size_t)NND * NDm];
__device__ __align__(16) bf16 g_Sh[NND * NL];
__device__ __align__(16) bf16 g_Sl[NND * NL];
__device__ __align__(16) bf16 g_eWTh[NBc * NH * NL];
__device__ __align__(16) bf16 g_eWTl[NBc * NH * NL];

__device__ __align__(16) float g_xw[(size_t)NND * NRel * NH];
__device__ __align__(16) float g_agg[NND * NH];
// padded edge slots
__device__ int g_cur[NND];
__device__ int g_eidx[(size_t)NND * MAXD];

__device__ __forceinline__ void split_pair(float v, bf16& h, bf16& l) {
    h = __float2bfloat16(v);
    l = __float2bfloat16(v - __bfloat162float(h));
}

__device__ __forceinline__ u32 smem_u32(const void* p) {
    u32 a;
    asm("{ .reg .u64 t; cvta.to.shared.u64 t, %1; cvt.u32.u64 %0, t; }"
        : "=r"(a) : "l"(p));
    return a;
}

__device__ __forceinline__ void mma16816(float* d, const u32* a, const u32* b) {
    asm volatile(
        "mma.sync.aligned.m16n8k16.row.col.f32.bf16.bf16.f32 "
        "{%0,%1,%2,%3}, {%4,%5,%6,%7}, {%8,%9}, {%0,%1,%2,%3};"
        : "+f"(d[0]), "+f"(d[1]), "+f"(d[2]), "+f"(d[3])
        : "r"(a[0]), "r"(a[1]), "r"(a[2]), "r"(a[3]), "r"(b[0]), "r"(b[1]));
}

#define LDSM4(r, addr) \
    asm volatile("ldmatrix.sync.aligned.m8n8.x4.shared.b16 {%0,%1,%2,%3}, [%4];" \
        : "=r"((r)[0]), "=r"((r)[1]), "=r"((r)[2]), "=r"((r)[3]) : "r"(addr))

#define CPA(d, s) \
    asm volatile("cp.async.cg.shared.global [%0], [%1], 16;" :: "r"(d), "l"(s) : "memory")
#define CPC() asm volatile("cp.async.commit_group;" ::: "memory")
#define CPW0() asm volatile("cp.async.wait_group 0;" ::: "memory")

// ============================================================
// Pipelined warp-MMA 3xBF16 GEMM: C[M,N] = A @ B^T
// ============================================================
template <int BM, int NT, int THREADS,
          bool ADD_D, bool BIAS, bool RELU, bool OUT_PAIR, bool OUT_T, bool HEAD>
__global__ void __launch_bounds__(THREADS, 2)
mmt(const bf16* __restrict__ Ah, const bf16* __restrict__ Al, int lda, long long sA,
    const bf16* __restrict__ Bh, const bf16* __restrict__ Bl, int ldb, long long sB,
    float* __restrict__ C, bf16* __restrict__ Ch, bf16* __restrict__ Cl,
    u32* __restrict__ Cp,
    int ldc, long long sC,
    const float* __restrict__ D, int ldd,
    const float* __restrict__ bias,
    const float* __restrict__ Ws, const float* __restrict__ bsv,
    int K)
{
    constexpr int WARPS = THREADS / 32;
    constexpr int WN = NT / 64;
    constexpr int WMC = WARPS / WN;
    constexpr int WM = BM / WMC;
    constexpr int MI = WM / 16;
    constexpr int STAGE_ROWS = 2 * (BM + NT);
    constexpr int STAGE_B = STAGE_ROWS * 128;
    constexpr int CHUNKS = STAGE_ROWS * 8 / THREADS;

    extern __shared__ char smem[];
    const u32 sb0 = smem_u32(smem) + 512;

    const int tid = threadIdx.x;
    const int wid = tid >> 5, lane = tid & 31;
    const int warpM = wid % WMC, warpN = wid / WMC;
    const int bz = blockIdx.z;
    const int m0 = blockIdx.y * BM;
    const int n0 = blockIdx.x * NT;

    const char* pAh = (const char*)(Ah + sA * bz + (size_t)m0 * lda);
    const char* pAl = (const char*)(Al + sA * bz + (size_t)m0 * lda);
    const char* pBh = (const char*)(Bh + sB * bz + (size_t)n0 * ldb);
    const char* pBl = (const char*)(Bl + sB * bz + (size_t)n0 * ldb);
    const size_t ldab = (size_t)lda * 2;
    const size_t ldbb = (size_t)ldb * 2;

    float acc[MI][8][4];
#pragma unroll
    for (int i = 0; i < MI; i++)
#pragma unroll
        for (int j = 0; j < 8; j++)
#pragma unroll
            for (int q = 0; q < 4; q++) acc[i][j][q] = 0.f;

    const int S = K / KC;

    auto load_stage = [&](int s) {
        const size_t kcb = (size_t)s * KC * 2;
        const u32 dst0 = sb0 + (u32)(s & 1) * STAGE_B;
#pragma unroll
        for (int f = 0; f < CHUNKS; f++) {
            int idx = tid + f * THREADS;
            int row = idx >> 3;
            u32 cb = (u32)(idx & 7) << 4;
            u32 sw = cb ^ (((u32)(row & 7)) << 4);
            const char* src;
            if (row < BM)               src = pAh + (size_t)row * ldab + kcb + cb;
            else if (row < 2 * BM)      src = pAl + (size_t)(row - BM) * ldab + kcb + cb;
            else if (row < 2 * BM + NT) src = pBh + (size_t)(row - 2 * BM) * ldbb + kcb + cb;
            else                        src = pBl + (size_t)(row - 2 * BM - NT) * ldbb + kcb + cb;
            CPA(dst0 + (u32)row * 128 + sw, src);
        }
    };

    load_stage(0);
    CPC();

    const u32 xorv = ((u32)(lane & 7)) << 4;
    const u32 aRow = (u32)(warpM * WM + (lane & 15));
    const u32 aCol0 = ((u32)(lane >> 4) & 1) * 16;
    const u32 bRow = (u32)(warpN * 64 + ((lane & 7) | ((lane & 16) >> 1)));
    const u32 bCol0 = ((u32)(lane >> 3) & 1) * 16;

    for (int s = 0; s < S; s++) {
        CPW0();
        __syncthreads();
        if (s + 1 < S) { load_stage(s + 1); CPC(); }

        const u32 base = sb0 + (u32)(s & 1) * STAGE_B;
        const u32 aH = base + aRow * 128;
        const u32 aL = aH + (u32)BM * 128;
        const u32 bH = base + (u32)(2 * BM) * 128 + bRow * 128;
        const u32 bL = bH + (u32)NT * 128;

#pragma unroll
        for (int ks = 0; ks < KC / 16; ks++) {
            const u32 kb = (u32)ks * 32;
            const u32 acol = (aCol0 + kb) ^ xorv;
            const u32 bcol = (bCol0 + kb) ^ xorv;
            u32 ah[MI][4], al[MI][4];
#pragma unroll
            for (int mi = 0; mi < MI; mi++) {
                LDSM4(ah[mi], aH + (u32)mi * (16 * 128) + acol);
                LDSM4(al[mi], aL + (u32)mi * (16 * 128) + acol);
            }
#pragma unroll
            for (int nt = 0; nt < 4; nt++) {
                u32 bh[4], bl[4];
                LDSM4(bh, bH + (u32)nt * (16 * 128) + bcol);
                LDSM4(bl, bL + (u32)nt * (16 * 128) + bcol);
#pragma unroll
                for (int mi = 0; mi < MI; mi++)
#pragma unroll
                    for (int half = 0; half < 2; half++) {
                        float* a4 = acc[mi][nt * 2 + half];
                        mma16816(a4, ah[mi], &bh[half * 2]);
                        mma16816(a4, ah[mi], &bl[half * 2]);
                        mma16816(a4, al[mi], &bh[half * 2]);
                    }
            }
        }
    }

    if (HEAD) {
        __syncthreads();
        float* wss = (float*)smem;
        for (int i = tid; i < NH * NC + NC; i += THREADS)
            wss[i] = (i < NH * NC) ? Ws[i] : bsv[i - NH * NC];
        __syncthreads();
        const int tg = lane & 3;
#pragma unroll
        for (int mi = 0; mi < MI; mi++) {
#pragma unroll
            for (int half = 0; half < 2; half++) {
                const int m = m0 + warpM * WM + mi * 16 + (lane >> 2) + half * 8;
                float lg[NC];
#pragma unroll
                for (int c = 0; c < NC; c++) lg[c] = 0.f;
#pragma unroll
                for (int ni = 0; ni < 8; ni++) {
                    const int n = ni * 8 + tg * 2;
                    float v0 = acc[mi][ni][half * 2];
                    float v1 = acc[mi][ni][half * 2 + 1];
                    if (BIAS) { v0 += bias[n]; v1 += bias[n + 1]; }
                    if (RELU) { v0 = fmaxf(v0, 0.f); v1 = fmaxf(v1, 0.f); }
#pragma unroll
                    for (int c = 0; c < NC; c++)
                        lg[c] = fmaf(v0, wss[n * NC + c],
                                     fmaf(v1, wss[(n + 1) * NC + c], lg[c]));
                }
#pragma unroll
                for (int o = 1; o < 4; o <<= 1)
#pragma unroll
                    for (int c = 0; c < NC; c++)
                        lg[c] += __shfl_xor_sync(0xffffffffu, lg[c], o);
                if (tg == 0) {
#pragma unroll
                    for (int c = 0; c < NC; c++) lg[c] += wss[NH * NC + c];
                    float mx = lg[0];
#pragma unroll
                    for (int c = 1; c < NC; c++) mx = fmaxf(mx, lg[c]);
                    float ssum = 0.f;
#pragma unroll
                    for (int c = 0; c < NC; c++) ssum += expf(lg[c] - mx);
                    float lse = mx + logf(ssum);
                    const size_t o0 = (size_t)(bz * NL + m) * NC;
#pragma unroll
                    for (int c = 0; c < NC; c++) C[o0 + c] = lg[c] - lse;
                }
            }
        }
        return;
    }

    // ---- standard epilogue ----
#pragma unroll
    for (int mi = 0; mi < MI; mi++) {
        const int rm = m0 + warpM * WM + mi * 16 + (lane >> 2);
#pragma unroll
        for (int ni = 0; ni < 8; ni++) {
            const int n = n0 + warpN * 64 + ni * 8 + (lane & 3) * 2;
#pragma unroll
            for (int half = 0; half < 2; half++) {
                const int m = rm + half * 8;
                float v0 = acc[mi][ni][half * 2];
                float v1 = acc[mi][ni][half * 2 + 1];
                if (BIAS) { v0 += bias[n]; v1 += bias[n + 1]; }
                if (ADD_D) {
                    v0 += D[(size_t)m * ldd + n];
                    v1 += D[(size_t)m * ldd + n + 1];
                }
                if (RELU) { v0 = fmaxf(v0, 0.f); v1 = fmaxf(v1, 0.f); }
                if (OUT_PAIR) {
                    bf16 h0, l0, h1c, l1c;
                    split_pair(v0, h0, l0);
                    split_pair(v1, h1c, l1c);
                    if (OUT_T) {
                        size_t o = ((size_t)(m >> 7) * 64 + n) * 128 + (m & 127);
                        Ch[o] = h0; Ch[o + 128] = h1c;
                        Cl[o] = l0; Cl[o + 128] = l1c;
                    } else {
                        const size_t o = (size_t)sC * bz + (size_t)m * ldc + n;
                        *(__nv_bfloat162*)&Ch[o] = __nv_bfloat162(h0, h1c);
                        *(__nv_bfloat162*)&Cl[o] = __nv_bfloat162(l0, l1c);
                        if (Cp) {
                            __nv_bfloat162 p0(h0, l0), p1(h1c, l1c);
                            uint2 u; u.x = *(u32*)&p0; u.y = *(u32*)&p1;
                            *(uint2*)&Cp[(size_t)m * 64 + n] = u;
                        }
                    }
                } else {
                    float2 f2; f2.x = v0; f2.y = v1;
                    *(float2*)&C[(size_t)sC * bz + (size_t)m * ldc + n] = f2;
                }
            }
        }
    }
}

// ============================================================
// Fused scores kernel: S = tanh((Q.M)*u^2) -> softmax -> *u -> renorm
// ============================================================
__global__ void __launch_bounds__(128, 2)
scores_softmax(const bf16* __restrict__ Qh, const bf16* __restrict__ Ql,
               const bf16* __restrict__ Mh, const bf16* __restrict__ Ml,
               const float* __restrict__ um,
               bf16* __restrict__ Sh, bf16* __restrict__ Sl)
{
    constexpr int BM = 64, NT = 128, THREADS = 128;
    constexpr int STAGE_ROWS = 2 * (BM + NT);
    constexpr int STAGE_B = STAGE_ROWS * 128;
    constexpr int CHUNKS = STAGE_ROWS * 8 / THREADS;

    extern __shared__ char smem[];
    float* ums = (float*)smem;
    float* sbuf = (float*)(smem + 512);
    const u32 sb0 = smem_u32(smem) + 512;

    const int tid = threadIdx.x;
    const int wid = tid >> 5, lane = tid & 31;
    const int warpM = wid & 1, warpN = wid >> 1;
    const int bz = blockIdx.z;
    const int m0 = blockIdx.y * BM;

    const char* pAh = (const char*)(Qh + (size_t)bz * NL * NDm + (size_t)m0 * NDm);
    const char* pAl = (const char*)(Ql + (size_t)bz * NL * NDm + (size_t)m0 * NDm);
    const char* pBh = (const char*)(Mh + (size_t)bz * NL * NDm);
    const char* pBl = (const char*)(Ml + (size_t)bz * NL * NDm);
    const size_t ldab = (size_t)NDm * 2;

    if (tid < NT) ums[tid] = um[bz * NL + tid];

    float acc[2][8][4];
#pragma unroll
    for (int i = 0; i < 2; i++)
#pragma unroll
        for (int j = 0; j < 8; j++)
#pragma unroll
            for (int q = 0; q < 4; q++) acc[i][j][q] = 0.f;

    const int S = NDm / KC;

    auto load_stage = [&](int s) {
        const size_t kcb = (size_t)s * KC * 2;
        const u32 dst0 = sb0 + (u32)(s & 1) * STAGE_B;
#pragma unroll
        for (int f = 0; f < CHUNKS; f++) {
            int idx = tid + f * THREADS;
            int row = idx >> 3;
            u32 cb = (u32)(idx & 7) << 4;
            u32 sw = cb ^ (((u32)(row & 7)) << 4);
            const char* src;
            if (row < BM)               src = pAh + (size_t)row * ldab + kcb + cb;
            else if (row < 2 * BM)      src = pAl + (size_t)(row - BM) * ldab + kcb + cb;
            else if (row < 2 * BM + NT) src = pBh + (size_t)(row - 2 * BM) * ldab + kcb + cb;
            else                        src = pBl + (size_t)(row - 2 * BM - NT) * ldab + kcb + cb;
            CPA(dst0 + (u32)row * 128 + sw, src);
        }
    };

    load_stage(0);
    CPC();

    const u32 xorv = ((u32)(lane & 7)) << 4;
    const u32 aRow = (u32)(warpM * 32 + (lane & 15));
    const u32 aCol0 = ((u32)(lane >> 4) & 1) * 16;
    const u32 bRow = (u32)(warpN * 64 + ((lane & 7) | ((lane & 16) >> 1)));
    const u32 bCol0 = ((u32)(lane >> 3) & 1) * 16;

    for (int s = 0; s < S; s++) {
        CPW0();
        __syncthreads();
        if (s + 1 < S) { load_stage(s + 1); CPC(); }

        const u32 base = sb0 + (u32)(s & 1) * STAGE_B;
        const u32 aH = base + aRow * 128;
        const u32 aL = aH + (u32)BM * 128;
        const u32 bH = base + (u32)(2 * BM) * 128 + bRow * 128;
        const u32 bL = bH + (u32)NT * 128;

#pragma unroll
        for (int ks = 0; ks < KC / 16; ks++) {
            const u32 kb = (u32)ks * 32;
            const u32 acol = (aCol0 + kb) ^ xorv;
            const u32 bcol = (bCol0 + kb) ^ xorv;
            u32 ah[2][4], al[2][4];
#pragma unroll
            for (int mi = 0; mi < 2; mi++) {
                LDSM4(ah[mi], aH + (u32)mi * (16 * 128) + acol);
                LDSM4(al[mi], aL + (u32)mi * (16 * 128) + acol);
            }
#pragma unroll
            for (int nt = 0; nt < 4; nt++) {
                u32 bh[4], bl[4];
                LDSM4(bh, bH + (u32)nt * (16 * 128) + bcol);
                LDSM4(bl, bL + (u32)nt * (16 * 128) + bcol);
#pragma unroll
                for (int mi = 0; mi < 2; mi++)
#pragma unroll
                    for (int half = 0; half < 2; half++) {
                        float* a4 = acc[mi][nt * 2 + half];
                        mma16816(a4, ah[mi], &bh[half * 2]);
                        mma16816(a4, ah[mi], &bl[half * 2]);
                        mma16816(a4, al[mi], &bh[half * 2]);
                    }
            }
        }
    }
    __syncthreads();

#pragma unroll
    for (int mi = 0; mi < 2; mi++) {
#pragma unroll
        for (int ni = 0; ni < 8; ni++) {
            const int col = warpN * 64 + ni * 8 + (lane & 3) * 2;
            const float u0 = ums[col], u1 = ums[col + 1];
#pragma unroll
            for (int half = 0; half < 2; half++) {
                const int row = warpM * 32 + mi * 16 + (lane >> 2) + half * 8;
                float v0 = tanhf(acc[mi][ni][half * 2] * u0 * u0);
                float v1 = tanhf(acc[mi][ni][half * 2 + 1] * u1 * u1);
                float2 f2; f2.x = v0; f2.y = v1;
                *(float2*)&sbuf[row * 132 + col] = f2;
            }
        }
    }
    __syncthreads();

    for (int r8 = 0; r8 < 16; r8++) {
        const int row = wid * 16 + r8;
        float4 v = *(const float4*)&sbuf[row * 132 + lane * 4];
        float mx = fmaxf(fmaxf(v.x, v.y), fmaxf(v.z, v.w));
#pragma unroll
        for (int o = 16; o > 0; o >>= 1)
            mx = fmaxf(mx, __shfl_xor_sync(0xffffffffu, mx, o));
        float e0 = expf(v.x - mx), e1 = expf(v.y - mx);
        float e2 = expf(v.z - mx), e3 = expf(v.w - mx);
        float sum1 = e0 + e1 + e2 + e3;
#pragma unroll
        for (int o = 16; o > 0; o >>= 1)
            sum1 += __shfl_xor_sync(0xffffffffu, sum1, o);
        const int col = lane * 4;
        float a0 = (e0 / sum1) * ums[col];
        float a1 = (e1 / sum1) * ums[col + 1];
        float a2 = (e2 / sum1) * ums[col + 2];
        float a3 = (e3 / sum1) * ums[col + 3];
        float sum2 = a0 + a1 + a2 + a3;
#pragma unroll
        for (int o = 16; o > 0; o >>= 1)
            sum2 += __shfl_xor_sync(0xffffffffu, sum2, o);
        float inv = 1.f / sum2;
        bf16 h0, l0, h1, l1, h2, l2, h3, l3;
        split_pair(a0 * inv, h0, l0);
        split_pair(a1 * inv, h1, l1);
        split_pair(a2 * inv, h2, l2);
        split_pair(a3 * inv, h3, l3);
        const size_t o0 = (size_t)(bz * NL + m0 + row) * NL + col;
        *(__nv_bfloat162*)&Sh[o0]     = __nv_bfloat162(h0, h1);
        *(__nv_bfloat162*)&Sh[o0 + 2] = __nv_bfloat162(h2, h3);
        *(__nv_bfloat162*)&Sl[o0]     = __nv_bfloat162(l0, l1);
        *(__nv_bfloat162*)&Sl[o0 + 2] = __nv_bfloat162(l2, l3);
    }
}

// ============================================================
// merged prep kernel: cvtx + wt + tcvt in one launch
// ============================================================
__global__ void prep_kernel(
    const float* __restrict__ x, bf16* __restrict__ eh, bf16* __restrict__ el,
    const float* __restrict__ comp, const float* __restrict__ basis,
    bf16* __restrict__ Wh, bf16* __restrict__ Wl,
    const float* __restrict__ root, bf16* __restrict__ rTh, bf16* __restrict__ rTl,
    const float* __restrict__ wr, const float* __restrict__ wn,
    bf16* __restrict__ wcTh, bf16* __restrict__ wcTl,
    const float* __restrict__ Wm, bf16* __restrict__ WmTh, bf16* __restrict__ WmTl,
    const float* __restrict__ Wl2, bf16* __restrict__ WlTh, bf16* __restrict__ WlTl)
{
    int i = blockIdx.x * 256 + threadIdx.x;
    if (i < 4194304) {
        bf16 h, l; split_pair(x[i], h, l);
        int row = i >> 9, c = i & 511;
        size_t eo = (size_t)row * NDm + c;
        eh[eo] = h; el[eo] = l;
    } else if (i < 4718592) {
        int idx = i - 4194304;
        int h = idx & 63, rr = (idx >> 6) & 15, k = idx >> 10;
        float acc = 0.f;
#pragma unroll
        for (int b = 0; b < NBase; b++)
            acc = fmaf(comp[rr * NBase + b], basis[((size_t)b * NF + k) * NH + h], acc);
        bf16 hh, ll; split_pair(acc, hh, ll);
        size_t o = (size_t)(rr * 64 + h) * 512 + k;
        Wh[o] = hh; Wl[o] = ll;
    } else {
        int j = i - 4718592;
        if (j < 32768) {
            int rr = j / 64, cc = j % 64;
            bf16 h, l; split_pair(root[j], h, l);
            rTh[(size_t)cc * 512 + rr] = h; rTl[(size_t)cc * 512 + rr] = l;
        } else if (j < 36864) {
            int q = j - 32768, rr = q / 64, cc = q % 64;
            bf16 h, l; split_pair(wr[q], h, l);
            wcTh[cc * 128 + rr] = h; wcTl[cc * 128 + rr] = l;
        } else if (j < 40960) {
            int q = j - 36864, rr = q / 64, cc = q % 64;
            bf16 h, l; split_pair(wn[q], h, l);
            wcTh[cc * 128 + 64 + rr] = h; wcTl[cc * 128 + 64 + rr] = l;
        } else if (j < 372736) {
            int q = j - 40960, rr = q / 576, cc = q % 576;
            bf16 h, l; split_pair(Wm[q], h, l);
            WmTh[(size_t)cc * 576 + rr] = h; WmTl[(size_t)cc * 576 + rr] = l;
        } else if (j < 409600) {
            int q = j - 372736, rr = q / 64, cc = q % 64;
            bf16 h, l; split_pair(Wl2[q], h, l);
            WlTh[(size_t)cc * 576 + rr] = h; WlTl[(size_t)cc * 576 + rr] = l;
        }
    }
}

// ---- edge fill: store precomputed element offset src*1024 + rel*64 ----
__global__ void fill_kernel(const int* __restrict__ ei, const int* __restrict__ et,
                            int* __restrict__ cur, int* __restrict__ eidx)
{
    int i = blockIdx.x * 256 + threadIdx.x;
    if (i >= NE) return;
    int dst = ei[NE + i];
    int pos = atomicAdd(&cur[dst], 1);
    eidx[(size_t)dst * MAXD + pos] = (ei[i] << 10) + (et[i] << 6);
}

// ---- gathers: 16 threads/node, float4 per thread, 4-way unroll ----
__global__ void __launch_bounds__(256)
rgcn_gather(const int* __restrict__ cur, const int* __restrict__ eidx,
            const float* __restrict__ xw, float* __restrict__ agg)
{
    const int n = blockIdx.x * 16 + (threadIdx.x >> 4);
    const int h4 = (threadIdx.x & 15) * 4;
    const int cntn = cur[n];
    const int* ep = eidx + n * MAXD;
    float4 a0 = {0.f, 0.f, 0.f, 0.f}, a1 = {0.f, 0.f, 0.f, 0.f};
    float4 a2 = {0.f, 0.f, 0.f, 0.f}, a3 = {0.f, 0.f, 0.f, 0.f};
    int e = 0;
    for (; e + 4 <= cntn; e += 4) {
        int p0 = ep[e], p1 = ep[e + 1], p2 = ep[e + 2], p3 = ep[e + 3];
        float4 v0 = *(const float4*)(xw + p0 + h4);
        float4 v1 = *(const float4*)(xw + p1 + h4);
        float4 v2 = *(const float4*)(xw + p2 + h4);
        float4 v3 = *(const float4*)(xw + p3 + h4);
        a0.x += v0.x; a0.y += v0.y; a0.z += v0.z; a0.w += v0.w;
        a1.x += v1.x; a1.y += v1.y; a1.z += v1.z; a1.w += v1.w;
        a2.x += v2.x; a2.y += v2.y; a2.z += v2.z; a2.w += v2.w;
        a3.x += v3.x; a3.y += v3.y; a3.z += v3.z; a3.w += v3.w;
    }
    for (; e < cntn; e++) {
        float4 v = *(const float4*)(xw + ep[e] + h4);
        a0.x += v.x; a0.y += v.y; a0.z += v.z; a0.w += v.w;
    }
    float inv = 1.f / fmaxf((float)cntn, 1.f);
    float4 r;
    r.x = ((a0.x + a1.x) + (a2.x + a3.x)) * inv;
    r.y = ((a0.y + a1.y) + (a2.y + a3.y)) * inv;
    r.z = ((a0.z + a1.z) + (a2.z + a3.z)) * inv;
    r.w = ((a0.w + a1.w) + (a2.w + a3.w)) * inv;
    *(float4*)&agg[n * NH + h4] = r;
}

__global__ void __launch_bounds__(256)
gc_gather(const int* __restrict__ cur, const int* __restrict__ eidx,
          const u32* __restrict__ h1p, bf16* __restrict__ a2h, bf16* __restrict__ a2l)
{
    const int n = blockIdx.x * 16 + (threadIdx.x >> 4);
    const int h4 = (threadIdx.x & 15) * 4;
    const int cntn = cur[n];
    const int* ep = eidx + n * MAXD;
    float sh[4] = {0.f, 0.f, 0.f, 0.f};
    float sl[4] = {0.f, 0.f, 0.f, 0.f};
    int e = 0;
    for (; e + 4 <= cntn; e += 4) {
        uint4 q0 = *(const uint4*)(h1p + ((ep[e]     >> 4) & ~63) + h4);
        uint4 q1 = *(const uint4*)(h1p + ((ep[e + 1] >> 4) & ~63) + h4);
        uint4 q2 = *(const uint4*)(h1p + ((ep[e + 2] >> 4) & ~63) + h4);
        uint4 q3 = *(const uint4*)(h1p + ((ep[e + 3] >> 4) & ~63) + h4);
        const u32* qs[4] = {&q0.x, &q1.x, &q2.x, &q3.x};
#pragma unroll
        for (int u = 0; u < 4; u++)
#pragma unroll
            for (int w = 0; w < 4; w++) {
                __nv_bfloat162 t = *(__nv_bfloat162*)&qs[u][w];
                sh[w] += __bfloat162float(t.x);
                sl[w] += __bfloat162float(t.y);
            }
    }
    for (; e < cntn; e++) {
        uint4 q = *(const uint4*)(h1p + ((ep[e] >> 4) & ~63) + h4);
        const u32* qw = &q.x;
#pragma unroll
        for (int w = 0; w < 4; w++) {
            __nv_bfloat162 t = *(__nv_bfloat162*)&qw[w];
            sh[w] += __bfloat162float(t.x);
            sl[w] += __bfloat162float(t.y);
        }
    }
    bf16 h0, l0, h1, l1, h2, l2, h3, l3;
    split_pair(sh[0] + sl[0], h0, l0);
    split_pair(sh[1] + sl[1], h1, l1);
    split_pair(sh[2] + sl[2], h2, l2);
    split_pair(sh[3] + sl[3], h3, l3);
    const size_t o = (size_t)n * 128 + 64 + h4;
    *(__nv_bfloat162*)&a2h[o]     = __nv_bfloat162(h0, h1);
    *(__nv_bfloat162*)&a2h[o + 2] = __nv_bfloat162(h2, h3);
    *(__nv_bfloat162*)&a2l[o]     = __nv_bfloat162(l0, l1);
    *(__nv_bfloat162*)&a2l[o + 2] = __nv_bfloat162(l2, l3);
}

// ============================================================
extern "C" void kernel_launch(void* const* d_in, const int* in_sizes, int n_in,
                              void* d_out, int out_size)
{
    const float* x      = (const float*)d_in[0];
    const int*   ei     = (const int*)d_in[1];
    const int*   et     = (const int*)d_in[3];
    const float* umask  = (const float*)d_in[5];
    const float* basis  = (const float*)d_in[8];
    const float* comp   = (const float*)d_in[9];
    const float* root   = (const float*)d_in[10];
    const float* bias1  = (const float*)d_in[11];
    const float* w_nbr  = (const float*)d_in[12];
    const float* w_root = (const float*)d_in[13];
    const float* bias2  = (const float*)d_in[14];
    const float* Wm     = (const float*)d_in[15];
    const float* bm     = (const float*)d_in[16];
    const float* Wl     = (const float*)d_in[17];
    const float* bl     = (const float*)d_in[18];
    const float* Ws     = (const float*)d_in[19];
    const float* bs     = (const float*)d_in[20];
    float* out = (float*)d_out;

#define SYM(T, v, s) T* v; cudaGetSymbolAddress((void**)&v, s)
    SYM(bf16, WtTh, g_WtTh); SYM(bf16, WtTl, g_WtTl);
    SYM(bf16, rootTh, g_rootTh); SYM(bf16, rootTl, g_rootTl);
    SYM(bf16, wcatTh, g_wcatTh); SYM(bf16, wcatTl, g_wcatTl);
    SYM(bf16, WmTh, g_WmTh); SYM(bf16, WmTl, g_WmTl);
    SYM(bf16, WlTh, g_WlTh); SYM(bf16, WlTl, g_WlTl);
    SYM(bf16, emoh, g_emoh); SYM(bf16, emol, g_emol);
    SYM(bf16, a2h, g_a2h); SYM(bf16, a2l, g_a2l);
    SYM(u32, h1p, g_h1p);
    SYM(bf16, Qh, g_Qh); SYM(bf16, Ql, g_Ql);
    SYM(bf16, Sh, g_Sh); SYM(bf16, Sl, g_Sl);
    SYM(bf16, eWTh, g_eWTh); SYM(bf16, eWTl, g_eWTl);
    SYM(float, xw, g_xw); SYM(float, agg, g_agg);
    SYM(int, cur, g_cur); SYM(int, eidx, g_eidx);
#undef SYM

    const int SZ_128_64 = 512 + 2 * 2 * (128 + 64) * 128;   // 98816
    const int SZ_64_128 = 512 + 2 * 2 * (64 + 128) * 128;   // 98816
    const int SZ_64_64  = 512 + 2 * 2 * (64 + 64) * 128;    // 66048

#define SETSM(KERN, SZ) cudaFuncSetAttribute((const void*)(KERN), \
    cudaFuncAttributeMaxDynamicSharedMemorySize, SZ)
    SETSM((mmt<128, 64, 128, false, false, false, false, false, false>), SZ_128_64);
    SETSM((mmt<64, 64, 128, true,  true,  false, true,  false, false>),  SZ_64_64);
    SETSM((mmt<64, 64, 128, false, true,  false, true,  false, false>),  SZ_64_64);
    SETSM((mmt<128, 64, 128, false, true,  false, true,  false, false>), SZ_128_64);
    SETSM((mmt<64, 64, 128, false, false, false, true,  true,  false>),  SZ_64_64);
    SETSM((mmt<128, 64, 128, false, true,  true,  false, false, true>),  SZ_128_64);
    SETSM(scores_softmax, SZ_64_128);
#undef SETSM

    cudaStream_t s2 = g_fork.s2;

    // ---- fork: edge build on s2 concurrent with prep+xw on main ----
    cudaEventRecord(g_fork.evA, 0);
    cudaStreamWaitEvent(s2, g_fork.evA, 0);
    cudaMemsetAsync(cur, 0, NND * sizeof(int), s2);
    fill_kernel<<<NE / 256, 256, 0, s2>>>(ei, et, cur, eidx);
    cudaEventRecord(g_fork.evB, s2);

    prep_kernel<<<(4194304 + 524288 + 409600) / 256, 256>>>(
        x, emoh, emol, comp, basis, WtTh, WtTl,
        root, rootTh, rootTl, w_root, w_nbr, wcatTh, wcatTl,
        Wm, WmTh, WmTl, Wl, WlTh, WlTl);

    // xw = x @ Wt  (A = emo cols [0,512), lda=576)
    mmt<128, 64, 128, false, false, false, false, false, false>
        <<<dim3(16, 64, 1), 128, SZ_128_64>>>(
        emoh, emol, NDm, 0, WtTh, WtTl, 512, 0,
        xw, nullptr, nullptr, nullptr, 1024, 0, nullptr, 0, nullptr,
        nullptr, nullptr, 512);

    // join: rgcn needs fill
    cudaStreamWaitEvent(0, g_fork.evB, 0);
    rgcn_gather<<<NND / 16, 256>>>(cur, eidx, xw, agg);

    // h1 = agg + x@root + bias1 -> a2 cols [0,64) pairs + packed h1p
    mmt<64, 64, 128, true, true, false, true, false, false>
        <<<dim3(1, 128, 1), 128, SZ_64_64>>>(
        emoh, emol, NDm, 0, rootTh, rootTl, 512, 0,
        nullptr, a2h, a2l, h1p, 128, 0, agg, 64, bias1,
        nullptr, nullptr, 512);

    gc_gather<<<NND / 16, 256>>>(cur, eidx, h1p, a2h, a2l);

    // h2 = [h1 | aggH1] @ [w_root; w_nbr] + bias2 -> emo cols [512,576)
    mmt<64, 64, 128, false, true, false, true, false, false>
        <<<dim3(1, 128, 1), 128, SZ_64_64>>>(
        a2h, a2l, 128, 0, wcatTh, wcatTl, 128, 0,
        nullptr, emoh + NF, emol + NF, nullptr, NDm, 0, nullptr, 0, bias2,
        nullptr, nullptr, 128);

    // ---- fork: eW on s2 concurrent with Q+scores on main ----
    cudaEventRecord(g_fork.evC, 0);
    cudaStreamWaitEvent(s2, g_fork.evC, 0);
    mmt<64, 64, 128, false, false, false, true, true, false>
        <<<dim3(1, 128, 1), 128, SZ_64_64, s2>>>(
        emoh, emol, NDm, 0, WlTh, WlTl, NDm, 0,
        nullptr, eWTh, eWTl, nullptr, 0, 0, nullptr, 0, nullptr,
        nullptr, nullptr, NDm);
    cudaEventRecord(g_fork.evD, s2);

    // Q = emo @ Wm + bm -> pairs
    mmt<128, 64, 128, false, true, false, true, false, false>
        <<<dim3(9, 64, 1), 128, SZ_128_64>>>(
        emoh, emol, NDm, 0, WmTh, WmTl, NDm, 0,
        nullptr, Qh, Ql, nullptr, NDm, 0, nullptr, 0, bm,
        nullptr, nullptr, NDm);

    // fused scores + softmax -> bf16 pairs
    scores_softmax<<<dim3(1, 2, NBc), 128, SZ_64_128>>>(
        Qh, Ql, emoh, emol, umask, Sh, Sl);

    // join: hidden needs eWT
    cudaStreamWaitEvent(0, g_fork.evD, 0);

    // hidden = relu(alpha @ eWT + bl) -> FUSED head -> out
    mmt<128, 64, 128, false, true, true, false, false, true>
        <<<dim3(1, 1, NBc), 128, SZ_128_64>>>(
        Sh, Sl, NL, (long long)NL * NL, eWTh, eWTl, NL, (long long)NH * NL,
        out, nullptr, nullptr, nullptr, NH, 0, nullptr, 0, bl,
        Ws, bs, NL);

    (void)in_sizes; (void)n_in; (void)out_size;
}